// round 3
// baseline (speedup 1.0000x reference)
#include <cuda_runtime.h>

#define NN   50000
#define NE   400000
#define INF  50
#define HID  512
#define OUTF 121
#define EPSF 1e-5f

// ---------------- scratch (device globals; no allocation allowed) ----------------
__device__ float g_deg[NN];
__device__ float g_invdeg[NN];
__device__ float g_agg[(size_t)NN * HID];
__device__ float g_h[(size_t)NN * HID];
__device__ float g_t[(size_t)NN * HID];
__device__ float g_colsum[HID];
__device__ float g_colsq[HID];
__device__ float g_scale[HID];
__device__ float g_shift[HID];
__device__ int   g_src[NE];
__device__ int   g_dst[NE];
__device__ int   g_is64;   // 1 if edge_index is int64, 0 if int32

// buffer selector: 0 -> external pointer, 1 -> g_h, 2 -> g_t
__device__ __forceinline__ float* pick(int sel, float* ext) {
    if (sel == 1) return g_h;
    if (sel == 2) return g_t;
    return ext;
}
__device__ __forceinline__ const float* pickc(int sel, const float* ext) {
    if (sel == 1) return g_h;
    if (sel == 2) return g_t;
    return ext;
}

// ---------------- edge index dtype detection + conversion ----------------
// If the buffer truly holds int64 indices, every int64 value is in [0, NN).
// If it holds int32 indices, reading as int64 packs two indices; the high
// word is a second index which is almost surely nonzero somewhere -> value >= NN.
__global__ void detect_idx_k(const long long* __restrict__ ei) {
    __shared__ int bad;
    if (threadIdx.x == 0) bad = 0;
    __syncthreads();
    int found = 0;
    for (int i = threadIdx.x; i < 2 * NE / 2; i += blockDim.x) {  // NE int64 words cover both rows if int32
        long long v = ei[i];
        if (v < 0 || v >= NN) { found = 1; break; }
    }
    if (found) atomicOr(&bad, 1);
    __syncthreads();
    if (threadIdx.x == 0) g_is64 = bad ? 0 : 1;
}

__global__ void convert_idx_k(const void* __restrict__ ei) {
    int e = blockIdx.x * blockDim.x + threadIdx.x;
    if (e >= NE) return;
    int s, d;
    if (g_is64) {
        const long long* p = (const long long*)ei;
        s = (int)p[e];
        d = (int)p[e + NE];
    } else {
        const int* p = (const int*)ei;
        s = p[e];
        d = p[e + NE];
    }
    s = min(max(s, 0), NN - 1);
    d = min(max(d, 0), NN - 1);
    g_src[e] = s;
    g_dst[e] = d;
}

// ---------------- small utility kernels ----------------
__global__ void zero_agg_k(long long n) {
    long long i = (long long)blockIdx.x * blockDim.x + threadIdx.x;
    if (i < n) g_agg[i] = 0.f;
}

__global__ void zero_deg_k() {
    int i = blockIdx.x * blockDim.x + threadIdx.x;
    if (i < NN) g_deg[i] = 0.f;
}

__global__ void zero_stats_k() {
    int i = threadIdx.x + blockIdx.x * blockDim.x;
    if (i < HID) { g_colsum[i] = 0.f; g_colsq[i] = 0.f; }
}

__global__ void deg_k() {
    int e = blockIdx.x * blockDim.x + threadIdx.x;
    if (e < NE) atomicAdd(&g_deg[g_dst[e]], 1.0f);
}

__global__ void invdeg_k() {
    int n = blockIdx.x * blockDim.x + threadIdx.x;
    if (n < NN) g_invdeg[n] = 1.0f / fmaxf(g_deg[n], 1.0f);
}

// scatter-add in[src] into g_agg[dst]; one thread per (edge, feature) — scalar path
__global__ void scatter_k(int in_sel, const float* __restrict__ ext, int F) {
    const float* x = pickc(in_sel, ext);
    long long idx = (long long)blockIdx.x * blockDim.x + threadIdx.x;
    long long total = (long long)NE * F;
    if (idx >= total) return;
    int e = (int)(idx / F);
    int k = (int)(idx - (long long)e * F);
    int s = g_src[e];
    int d = g_dst[e];
    atomicAdd(&g_agg[(long long)d * F + k], x[(long long)s * F + k]);
}

// vectorized: one thread handles 4 consecutive features of one edge (F % 4 == 0)
__global__ void scatter4_k(int in_sel, const float* __restrict__ ext, int F) {
    const float* x = pickc(in_sel, ext);
    int F4 = F >> 2;
    long long idx = (long long)blockIdx.x * blockDim.x + threadIdx.x;
    long long total = (long long)NE * F4;
    if (idx >= total) return;
    int e = (int)(idx / F4);
    int k4 = (int)(idx - (long long)e * F4);
    int s = g_src[e];
    int d = g_dst[e];
    float4 v = *(const float4*)(x + (long long)s * F + k4 * 4);
    float* dp = g_agg + (long long)d * F + k4 * 4;
    atomicAdd(dp + 0, v.x);
    atomicAdd(dp + 1, v.y);
    atomicAdd(dp + 2, v.z);
    atomicAdd(dp + 3, v.w);
}

// ---------------- dual-GEMM: C = (g_agg * invdeg) @ W1 + A2 @ W2 + bias ----------------
__global__ void gemm2_k(int M, int N, int K,
                        const float* __restrict__ W1,
                        int a2_sel, const float* __restrict__ a2_ext,
                        const float* __restrict__ W2,
                        const float* __restrict__ bias,
                        int c_sel, float* __restrict__ c_ext) {
    const int BM = 64, BN = 64, BK = 16;
    __shared__ float As[BK][BM + 1];
    __shared__ float Ws[BK][BN + 1];

    const float* A2 = pickc(a2_sel, a2_ext);
    float* C = pick(c_sel, c_ext);

    int tid = threadIdx.x;
    int tx = tid & 15;
    int ty = tid >> 4;
    int row0 = blockIdx.y * BM;
    int col0 = blockIdx.x * BN;

    float acc[4][4];
#pragma unroll
    for (int i = 0; i < 4; i++)
#pragma unroll
        for (int j = 0; j < 4; j++) acc[i][j] = 0.f;

    int lm = tid >> 2;
    int lkq = (tid & 3) * 4;

#pragma unroll 1
    for (int pass = 0; pass < 2; ++pass) {
        const float* A = pass ? A2 : g_agg;
        const float* W = pass ? W2 : W1;
        bool useScale = (pass == 0);

        for (int k0 = 0; k0 < K; k0 += BK) {
            {
                int r = row0 + lm;
                float rs = 1.0f;
                if (useScale && r < M) rs = g_invdeg[r];
#pragma unroll
                for (int q = 0; q < 4; q++) {
                    int k = k0 + lkq + q;
                    float v = 0.f;
                    if (r < M && k < K) v = A[(long long)r * K + k];
                    if (useScale) v *= rs;
                    As[lkq + q][lm] = v;
                }
            }
#pragma unroll
            for (int l = tid; l < BK * BN; l += 256) {
                int kk = l >> 6;
                int n = l & 63;
                int c = col0 + n;
                int k = k0 + kk;
                Ws[kk][n] = (c < N && k < K) ? W[(long long)k * N + c] : 0.f;
            }
            __syncthreads();

#pragma unroll
            for (int kk = 0; kk < BK; ++kk) {
                float a[4], w[4];
#pragma unroll
                for (int i = 0; i < 4; i++) a[i] = As[kk][ty * 4 + i];
#pragma unroll
                for (int j = 0; j < 4; j++) w[j] = Ws[kk][tx * 4 + j];
#pragma unroll
                for (int i = 0; i < 4; i++)
#pragma unroll
                    for (int j = 0; j < 4; j++) acc[i][j] += a[i] * w[j];
            }
            __syncthreads();
        }
    }

#pragma unroll
    for (int i = 0; i < 4; i++) {
        int r = row0 + ty * 4 + i;
        if (r >= M) continue;
#pragma unroll
        for (int j = 0; j < 4; j++) {
            int c = col0 + tx * 4 + j;
            if (c < N) C[(long long)r * N + c] = acc[i][j] + bias[c];
        }
    }
}

// ---------------- batch norm ----------------
__global__ void bnstat_k(int sel) {
    const float* h = pickc(sel, nullptr);
    int col = blockIdx.x * 32 + threadIdx.x;
    float s = 0.f, q = 0.f;
    for (int n = blockIdx.y * blockDim.y + threadIdx.y; n < NN; n += gridDim.y * blockDim.y) {
        float v = h[(long long)n * HID + col];
        s += v;
        q += v * v;
    }
    __shared__ float ss[8][33];
    __shared__ float qq[8][33];
    ss[threadIdx.y][threadIdx.x] = s;
    qq[threadIdx.y][threadIdx.x] = q;
    __syncthreads();
    if (threadIdx.y == 0) {
#pragma unroll
        for (int y = 1; y < 8; y++) {
            s += ss[y][threadIdx.x];
            q += qq[y][threadIdx.x];
        }
        atomicAdd(&g_colsum[col], s);
        atomicAdd(&g_colsq[col], q);
    }
}

__global__ void bnfin_k(const float* __restrict__ gamma, const float* __restrict__ beta) {
    int j = blockIdx.x * blockDim.x + threadIdx.x;
    if (j >= HID) return;
    float mean = g_colsum[j] * (1.0f / NN);
    float var = g_colsq[j] * (1.0f / NN) - mean * mean;
    float rstd = rsqrtf(var + EPSF);
    float sc = rstd * gamma[j];
    g_scale[j] = sc;
    g_shift[j] = beta[j] - mean * sc;
}

__global__ void bnapply_k(int sel) {
    float* h = pick(sel, nullptr);
    long long idx = (long long)blockIdx.x * blockDim.x + threadIdx.x;
    if (idx >= (long long)NN * HID) return;
    int c = (int)(idx & (HID - 1));
    float v = h[idx] * g_scale[c] + g_shift[c];
    h[idx] = fmaxf(v, 0.f);
}

// ---------------- host orchestration ----------------
static inline int cdiv(long long a, int b) { return (int)((a + b - 1) / b); }

extern "C" void kernel_launch(void* const* d_in, const int* in_sizes, int n_in,
                              void* d_out, int out_size) {
    const float* x = (const float*)d_in[0];
    const void* ei = d_in[1];

    const float* Wl[4] = {(const float*)d_in[2], (const float*)d_in[5],
                          (const float*)d_in[8], (const float*)d_in[11]};
    const float* bl[4] = {(const float*)d_in[3], (const float*)d_in[6],
                          (const float*)d_in[9], (const float*)d_in[12]};
    const float* Wr[4] = {(const float*)d_in[4], (const float*)d_in[7],
                          (const float*)d_in[10], (const float*)d_in[13]};
    const float* gam[3] = {(const float*)d_in[14], (const float*)d_in[16], (const float*)d_in[18]};
    const float* bet[3] = {(const float*)d_in[15], (const float*)d_in[17], (const float*)d_in[19]};

    float* out = (float*)d_out;

    // edge-index dtype detection + conversion to int32
    detect_idx_k<<<1, 1024>>>((const long long*)ei);
    convert_idx_k<<<cdiv(NE, 256), 256>>>(ei);

    // degrees (shared by all layers)
    zero_deg_k<<<cdiv(NN, 256), 256>>>();
    deg_k<<<cdiv(NE, 256), 256>>>();
    invdeg_k<<<cdiv(NN, 256), 256>>>();

    // ---- layer 1: IN_F=50 -> HID (input = x, output = g_h [sel 1]) ----
    {
        long long aggN = (long long)NN * INF;
        zero_agg_k<<<cdiv(aggN, 256), 256>>>(aggN);
        scatter_k<<<cdiv((long long)NE * INF, 256), 256>>>(0, x, INF);
        dim3 g(cdiv(HID, 64), cdiv(NN, 64));
        gemm2_k<<<g, 256>>>(NN, HID, INF, Wl[0], 0, x, Wr[0], bl[0], 1, nullptr);
        zero_stats_k<<<2, 256>>>();
        bnstat_k<<<dim3(HID / 32, 64), dim3(32, 8)>>>(1);
        bnfin_k<<<2, 256>>>(gam[0], bet[0]);
        bnapply_k<<<cdiv((long long)NN * HID, 256), 256>>>(1);
    }

    // ---- layers 2 & 3: HID -> HID ----
    for (int L = 1; L <= 2; ++L) {
        int in_sel = (L == 1) ? 1 : 2;
        int out_sel = (L == 1) ? 2 : 1;
        long long aggN = (long long)NN * HID;
        zero_agg_k<<<cdiv(aggN, 256), 256>>>(aggN);
        scatter4_k<<<cdiv((long long)NE * (HID / 4), 256), 256>>>(in_sel, nullptr, HID);
        dim3 g(cdiv(HID, 64), cdiv(NN, 64));
        gemm2_k<<<g, 256>>>(NN, HID, HID, Wl[L], in_sel, nullptr, Wr[L], bl[L], out_sel, nullptr);
        zero_stats_k<<<2, 256>>>();
        bnstat_k<<<dim3(HID / 32, 64), dim3(32, 8)>>>(out_sel);
        bnfin_k<<<2, 256>>>(gam[L], bet[L]);
        bnapply_k<<<cdiv((long long)NN * HID, 256), 256>>>(out_sel);
    }

    // ---- layer 4: HID -> OUT_F, straight to d_out (in sel 1 = g_h) ----
    {
        long long aggN = (long long)NN * HID;
        zero_agg_k<<<cdiv(aggN, 256), 256>>>(aggN);
        scatter4_k<<<cdiv((long long)NE * (HID / 4), 256), 256>>>(1, nullptr, HID);
        dim3 g(cdiv(OUTF, 64), cdiv(NN, 64));
        gemm2_k<<<g, 256>>>(NN, OUTF, HID, Wl[3], 1, nullptr, Wr[3], bl[3], 0, out);
    }
}

// round 4
// speedup vs baseline: 2.1283x; 2.1283x over previous
#include <cuda_runtime.h>

#define NN   50000
#define NE   400000
#define INF  50
#define HID  512
#define OUTF 121
#define EPSF 1e-5f

// ---------------- scratch (device globals; no allocation allowed) ----------------
__device__ float g_invdeg[NN];
__device__ float g_agg[(size_t)NN * HID];
__device__ float g_h[(size_t)NN * HID];
__device__ float g_t[(size_t)NN * HID];
__device__ float g_colsum[HID];
__device__ float g_colsq[HID];
__device__ float g_scale[HID];
__device__ float g_shift[HID];
__device__ int   g_src[NE];
__device__ int   g_dst[NE];
__device__ int   g_csrc[NE];       // CSR: source node per slot
__device__ int   g_rowptr[NN + 1];
__device__ int   g_cnt[NN];
__device__ int   g_cursor[NN];
__device__ int   g_is64;

// buffer selector: 0 -> external pointer, 1 -> g_h, 2 -> g_t
__device__ __forceinline__ float* pick(int sel, float* ext) {
    if (sel == 1) return g_h;
    if (sel == 2) return g_t;
    return ext;
}
__device__ __forceinline__ const float* pickc(int sel, const float* ext) {
    if (sel == 1) return g_h;
    if (sel == 2) return g_t;
    return ext;
}

// ---------------- edge index dtype detection + conversion ----------------
__global__ void detect_idx_k(const long long* __restrict__ ei) {
    __shared__ int bad;
    if (threadIdx.x == 0) bad = 0;
    __syncthreads();
    int found = 0;
    for (int i = threadIdx.x; i < NE; i += blockDim.x) {
        long long v = ei[i];
        if (v < 0 || v >= NN) { found = 1; break; }
    }
    if (found) atomicOr(&bad, 1);
    __syncthreads();
    if (threadIdx.x == 0) g_is64 = bad ? 0 : 1;
}

__global__ void convert_idx_k(const void* __restrict__ ei) {
    int e = blockIdx.x * blockDim.x + threadIdx.x;
    if (e >= NE) return;
    int s, d;
    if (g_is64) {
        const long long* p = (const long long*)ei;
        s = (int)p[e];
        d = (int)p[e + NE];
    } else {
        const int* p = (const int*)ei;
        s = p[e];
        d = p[e + NE];
    }
    g_src[e] = min(max(s, 0), NN - 1);
    g_dst[e] = min(max(d, 0), NN - 1);
}

// ---------------- CSR build ----------------
__global__ void zero_cnt_k() {
    int i = blockIdx.x * blockDim.x + threadIdx.x;
    if (i < NN) g_cnt[i] = 0;
}

__global__ void count_k() {
    int e = blockIdx.x * blockDim.x + threadIdx.x;
    if (e < NE) atomicAdd(&g_cnt[g_dst[e]], 1);
}

// single-block exclusive scan over g_cnt -> g_rowptr; also zeroes g_cursor
__global__ void scan_k() {
    __shared__ int sh[1024];
    __shared__ int carry_s;
    int tid = threadIdx.x;
    if (tid == 0) carry_s = 0;
    __syncthreads();
    for (int base = 0; base < NN; base += 1024) {
        int i = base + tid;
        int v = (i < NN) ? g_cnt[i] : 0;
        sh[tid] = v;
        __syncthreads();
        for (int off = 1; off < 1024; off <<= 1) {
            int x = (tid >= off) ? sh[tid - off] : 0;
            __syncthreads();
            sh[tid] += x;
            __syncthreads();
        }
        int carry = carry_s;
        if (i < NN) {
            g_rowptr[i] = carry + sh[tid] - v;
            g_cursor[i] = 0;
        }
        __syncthreads();
        if (tid == 0) carry_s = carry + sh[1023];
        __syncthreads();
    }
    if (tid == 0) g_rowptr[NN] = carry_s;
}

__global__ void invdeg_k() {
    int n = blockIdx.x * blockDim.x + threadIdx.x;
    if (n >= NN) return;
    int d = g_rowptr[n + 1] - g_rowptr[n];
    g_invdeg[n] = 1.0f / (float)max(d, 1);
}

__global__ void fill_k() {
    int e = blockIdx.x * blockDim.x + threadIdx.x;
    if (e >= NE) return;
    int d = g_dst[e];
    int slot = g_rowptr[d] + atomicAdd(&g_cursor[d], 1);
    g_csrc[slot] = g_src[e];
}

// ---------------- mean aggregation via CSR gather (no atomics) ----------------
// 512-feature version: 1 block of 128 threads per node, float4 per thread
__global__ void gather512_k(int in_sel, const float* __restrict__ ext) {
    const float* x = pickc(in_sel, ext);
    int node = blockIdx.x;
    int tid = threadIdx.x;
    int beg = g_rowptr[node], end = g_rowptr[node + 1];
    float4 acc = make_float4(0.f, 0.f, 0.f, 0.f);
    for (int e = beg; e < end; ++e) {
        int s = g_csrc[e];
        float4 v = *(const float4*)(x + (long long)s * HID + tid * 4);
        acc.x += v.x; acc.y += v.y; acc.z += v.z; acc.w += v.w;
    }
    float inv = g_invdeg[node];
    acc.x *= inv; acc.y *= inv; acc.z *= inv; acc.w *= inv;
    *(float4*)(g_agg + (long long)node * HID + tid * 4) = acc;
}

// 50-feature version: 1 block of 64 threads per node (threads >= INF idle)
__global__ void gather50_k(const float* __restrict__ x) {
    int node = blockIdx.x;
    int tid = threadIdx.x;
    if (tid >= INF) return;
    int beg = g_rowptr[node], end = g_rowptr[node + 1];
    float acc = 0.f;
    for (int e = beg; e < end; ++e) {
        int s = g_csrc[e];
        acc += x[(long long)s * INF + tid];
    }
    g_agg[(long long)node * INF + tid] = acc * g_invdeg[node];
}

// ---------------- tf32 tensor-core dual GEMM ----------------
// C = g_agg @ W1 + A2 @ W2 + bias, using 3xTF32 (hi/lo split, drop lo*lo).
// BM=128, BN=64, BK=32; 256 threads = 8 warps (4 along M x 2 along N),
// each warp computes 32x32 via m16n8k8 mma (2 m-tiles x 4 n-tiles).
#define BM 128
#define BN 64
#define BKK 32

__device__ __forceinline__ unsigned f2tf32(float x) {
    unsigned r;
    asm("cvt.rna.tf32.f32 %0, %1;" : "=r"(r) : "f"(x));
    return r;
}

__device__ __forceinline__ void mma_tf32(float& c0, float& c1, float& c2, float& c3,
                                         unsigned a0, unsigned a1, unsigned a2, unsigned a3,
                                         unsigned b0, unsigned b1) {
    asm volatile(
        "mma.sync.aligned.m16n8k8.row.col.f32.tf32.tf32.f32 "
        "{%0,%1,%2,%3},{%4,%5,%6,%7},{%8,%9},{%0,%1,%2,%3};"
        : "+f"(c0), "+f"(c1), "+f"(c2), "+f"(c3)
        : "r"(a0), "r"(a1), "r"(a2), "r"(a3), "r"(b0), "r"(b1));
}

__global__ void __launch_bounds__(256, 2)
gemm_tf32_k(int M, int N, int K,
            const float* __restrict__ W1,
            int a2_sel, const float* __restrict__ a2_ext,
            const float* __restrict__ W2,
            const float* __restrict__ bias,
            int c_sel, float* __restrict__ c_ext) {
    __shared__ float As[BKK][BM + 1];
    __shared__ float Ws[BKK][BN + 4];

    const float* A2 = pickc(a2_sel, a2_ext);
    float* C = pick(c_sel, c_ext);

    int tid = threadIdx.x;
    int warp = tid >> 5, lane = tid & 31;
    int wm = warp & 3;        // warp row slice (32 rows)
    int wn = warp >> 2;       // warp col slice (32 cols)
    int g = lane >> 2, t = lane & 3;
    int row0 = blockIdx.y * BM;
    int col0 = blockIdx.x * BN;

    float acc[2][4][4];
#pragma unroll
    for (int mi = 0; mi < 2; mi++)
#pragma unroll
        for (int ni = 0; ni < 4; ni++)
#pragma unroll
            for (int r = 0; r < 4; r++) acc[mi][ni][r] = 0.f;

#pragma unroll 1
    for (int pass = 0; pass < 2; ++pass) {
        const float* A = pass ? A2 : g_agg;
        const float* W = pass ? W2 : W1;

#pragma unroll 1
        for (int k0 = 0; k0 < K; k0 += BKK) {
            // load A tile: 128x32 floats, coalesced scalar
#pragma unroll
            for (int l = 0; l < 16; l++) {
                int idx = tid + l * 256;
                int r = idx >> 5;
                int k = idx & 31;
                int grow = row0 + r;
                int gk = k0 + k;
                float v = 0.f;
                if (grow < M && gk < K) v = A[(long long)grow * K + gk];
                As[k][r] = v;
            }
            // load W tile: 32x64
#pragma unroll
            for (int l = 0; l < 8; l++) {
                int idx = tid + l * 256;
                int n = idx & 63;
                int k = idx >> 6;
                int gc = col0 + n;
                int gk = k0 + k;
                Ws[k][n] = (gc < N && gk < K) ? W[(long long)gk * N + gc] : 0.f;
            }
            __syncthreads();

#pragma unroll
            for (int ks = 0; ks < 4; ks++) {
                int kb = ks * 8;
                // A fragments (hi/lo)
                unsigned ahi[2][4], alo[2][4];
#pragma unroll
                for (int mi = 0; mi < 2; mi++) {
                    int rb = wm * 32 + mi * 16;
                    float v0 = As[kb + t][rb + g];
                    float v1 = As[kb + t][rb + g + 8];
                    float v2 = As[kb + t + 4][rb + g];
                    float v3 = As[kb + t + 4][rb + g + 8];
                    float f;
                    ahi[mi][0] = f2tf32(v0); f = __uint_as_float(ahi[mi][0]); alo[mi][0] = f2tf32(v0 - f);
                    ahi[mi][1] = f2tf32(v1); f = __uint_as_float(ahi[mi][1]); alo[mi][1] = f2tf32(v1 - f);
                    ahi[mi][2] = f2tf32(v2); f = __uint_as_float(ahi[mi][2]); alo[mi][2] = f2tf32(v2 - f);
                    ahi[mi][3] = f2tf32(v3); f = __uint_as_float(ahi[mi][3]); alo[mi][3] = f2tf32(v3 - f);
                }
                // B fragments (hi/lo)
                unsigned bhi[4][2], blo[4][2];
#pragma unroll
                for (int ni = 0; ni < 4; ni++) {
                    int cb = wn * 32 + ni * 8;
                    float v0 = Ws[kb + t][cb + g];
                    float v1 = Ws[kb + t + 4][cb + g];
                    float f;
                    bhi[ni][0] = f2tf32(v0); f = __uint_as_float(bhi[ni][0]); blo[ni][0] = f2tf32(v0 - f);
                    bhi[ni][1] = f2tf32(v1); f = __uint_as_float(bhi[ni][1]); blo[ni][1] = f2tf32(v1 - f);
                }
#pragma unroll
                for (int mi = 0; mi < 2; mi++)
#pragma unroll
                    for (int ni = 0; ni < 4; ni++) {
                        float* c = acc[mi][ni];
                        mma_tf32(c[0], c[1], c[2], c[3],
                                 ahi[mi][0], ahi[mi][1], ahi[mi][2], ahi[mi][3],
                                 bhi[ni][0], bhi[ni][1]);
                        mma_tf32(c[0], c[1], c[2], c[3],
                                 ahi[mi][0], ahi[mi][1], ahi[mi][2], ahi[mi][3],
                                 blo[ni][0], blo[ni][1]);
                        mma_tf32(c[0], c[1], c[2], c[3],
                                 alo[mi][0], alo[mi][1], alo[mi][2], alo[mi][3],
                                 bhi[ni][0], bhi[ni][1]);
                    }
            }
            __syncthreads();
        }
    }

    // epilogue with bias
#pragma unroll
    for (int mi = 0; mi < 2; mi++) {
        int ra = row0 + wm * 32 + mi * 16 + g;
        int rb = ra + 8;
#pragma unroll
        for (int ni = 0; ni < 4; ni++) {
            int col = col0 + wn * 32 + ni * 8 + t * 2;
            float* c = acc[mi][ni];
            if (col < N) {
                float b0 = bias[col];
                if (ra < M) C[(long long)ra * N + col] = c[0] + b0;
                if (rb < M) C[(long long)rb * N + col] = c[2] + b0;
            }
            if (col + 1 < N) {
                float b1 = bias[col + 1];
                if (ra < M) C[(long long)ra * N + col + 1] = c[1] + b1;
                if (rb < M) C[(long long)rb * N + col + 1] = c[3] + b1;
            }
        }
    }
}

// ---------------- batch norm ----------------
__global__ void zero_stats_k() {
    int i = threadIdx.x + blockIdx.x * blockDim.x;
    if (i < HID) { g_colsum[i] = 0.f; g_colsq[i] = 0.f; }
}

__global__ void bnstat_k(int sel) {
    const float* h = pickc(sel, nullptr);
    int col = blockIdx.x * 32 + threadIdx.x;
    float s = 0.f, q = 0.f;
    for (int n = blockIdx.y * blockDim.y + threadIdx.y; n < NN; n += gridDim.y * blockDim.y) {
        float v = h[(long long)n * HID + col];
        s += v;
        q += v * v;
    }
    __shared__ float ss[8][33];
    __shared__ float qq[8][33];
    ss[threadIdx.y][threadIdx.x] = s;
    qq[threadIdx.y][threadIdx.x] = q;
    __syncthreads();
    if (threadIdx.y == 0) {
#pragma unroll
        for (int y = 1; y < 8; y++) {
            s += ss[y][threadIdx.x];
            q += qq[y][threadIdx.x];
        }
        atomicAdd(&g_colsum[col], s);
        atomicAdd(&g_colsq[col], q);
    }
}

__global__ void bnfin_k(const float* __restrict__ gamma, const float* __restrict__ beta) {
    int j = blockIdx.x * blockDim.x + threadIdx.x;
    if (j >= HID) return;
    float mean = g_colsum[j] * (1.0f / NN);
    float var = g_colsq[j] * (1.0f / NN) - mean * mean;
    float rstd = rsqrtf(var + EPSF);
    float sc = rstd * gamma[j];
    g_scale[j] = sc;
    g_shift[j] = beta[j] - mean * sc;
}

__global__ void bnapply_k(int sel) {
    float* h = pick(sel, nullptr);
    long long idx = (long long)blockIdx.x * blockDim.x + threadIdx.x;
    if (idx >= (long long)NN * HID) return;
    int c = (int)(idx & (HID - 1));
    float v = h[idx] * g_scale[c] + g_shift[c];
    h[idx] = fmaxf(v, 0.f);
}

// ---------------- host orchestration ----------------
static inline int cdiv(long long a, int b) { return (int)((a + b - 1) / b); }

extern "C" void kernel_launch(void* const* d_in, const int* in_sizes, int n_in,
                              void* d_out, int out_size) {
    const float* x = (const float*)d_in[0];
    const void* ei = d_in[1];

    const float* Wl[4] = {(const float*)d_in[2], (const float*)d_in[5],
                          (const float*)d_in[8], (const float*)d_in[11]};
    const float* bl[4] = {(const float*)d_in[3], (const float*)d_in[6],
                          (const float*)d_in[9], (const float*)d_in[12]};
    const float* Wr[4] = {(const float*)d_in[4], (const float*)d_in[7],
                          (const float*)d_in[10], (const float*)d_in[13]};
    const float* gam[3] = {(const float*)d_in[14], (const float*)d_in[16], (const float*)d_in[18]};
    const float* bet[3] = {(const float*)d_in[15], (const float*)d_in[17], (const float*)d_in[19]};

    float* out = (float*)d_out;

    // edge indices -> int32, CSR build
    detect_idx_k<<<1, 1024>>>((const long long*)ei);
    convert_idx_k<<<cdiv(NE, 256), 256>>>(ei);
    zero_cnt_k<<<cdiv(NN, 256), 256>>>();
    count_k<<<cdiv(NE, 256), 256>>>();
    scan_k<<<1, 1024>>>();
    invdeg_k<<<cdiv(NN, 256), 256>>>();
    fill_k<<<cdiv(NE, 256), 256>>>();

    // ---- layer 1: IN_F=50 -> HID (input x -> g_h) ----
    {
        gather50_k<<<NN, 64>>>(x);
        dim3 g(cdiv(HID, BN), cdiv(NN, BM));
        gemm_tf32_k<<<g, 256>>>(NN, HID, INF, Wl[0], 0, x, Wr[0], bl[0], 1, nullptr);
        zero_stats_k<<<2, 256>>>();
        bnstat_k<<<dim3(HID / 32, 64), dim3(32, 8)>>>(1);
        bnfin_k<<<2, 256>>>(gam[0], bet[0]);
        bnapply_k<<<cdiv((long long)NN * HID, 256), 256>>>(1);
    }

    // ---- layers 2 & 3: HID -> HID ----
    for (int L = 1; L <= 2; ++L) {
        int in_sel = (L == 1) ? 1 : 2;
        int out_sel = (L == 1) ? 2 : 1;
        gather512_k<<<NN, 128>>>(in_sel, nullptr);
        dim3 g(cdiv(HID, BN), cdiv(NN, BM));
        gemm_tf32_k<<<g, 256>>>(NN, HID, HID, Wl[L], in_sel, nullptr, Wr[L], bl[L], out_sel, nullptr);
        zero_stats_k<<<2, 256>>>();
        bnstat_k<<<dim3(HID / 32, 64), dim3(32, 8)>>>(out_sel);
        bnfin_k<<<2, 256>>>(gam[L], bet[L]);
        bnapply_k<<<cdiv((long long)NN * HID, 256), 256>>>(out_sel);
    }

    // ---- layer 4: HID -> OUT_F, straight to d_out (input g_h) ----
    {
        gather512_k<<<NN, 128>>>(1, nullptr);
        dim3 g(cdiv(OUTF, BN), cdiv(NN, BM));
        gemm_tf32_k<<<g, 256>>>(NN, OUTF, HID, Wl[3], 1, nullptr, Wr[3], bl[3], 0, out);
    }
}

// round 5
// speedup vs baseline: 2.9568x; 1.3893x over previous
#include <cuda_runtime.h>
#include <cuda_bf16.h>

#define NN   50000
#define NE   400000
#define INF  50
#define HID  512
#define OUTF 121
#define EPSF 1e-5f

// ---------------- scratch (device globals) ----------------
__device__ float g_invdeg[NN];
__device__ float g_agg[(size_t)NN * HID];
__device__ float g_h[(size_t)NN * HID];
__device__ float g_t[(size_t)NN * HID];
__device__ float g_colsum[HID];
__device__ float g_colsq[HID];
__device__ float g_scale[HID];
__device__ float g_shift[HID];
__device__ int   g_src[NE];
__device__ int   g_dst[NE];
__device__ int   g_csrc[NE];
__device__ int   g_rowptr[NN + 1];
__device__ int   g_cnt[NN];
__device__ int   g_cursor[NN];
__device__ int   g_is64;

__device__ __forceinline__ float* pick(int sel, float* ext) {
    if (sel == 1) return g_h;
    if (sel == 2) return g_t;
    return ext;
}
__device__ __forceinline__ const float* pickc(int sel, const float* ext) {
    if (sel == 1) return g_h;
    if (sel == 2) return g_t;
    return ext;
}

// ---------------- edge index dtype detection + conversion ----------------
__global__ void detect_idx_k(const long long* __restrict__ ei) {
    __shared__ int bad;
    if (threadIdx.x == 0) bad = 0;
    __syncthreads();
    int found = 0;
    for (int i = threadIdx.x; i < NE; i += blockDim.x) {
        long long v = ei[i];
        if (v < 0 || v >= NN) { found = 1; break; }
    }
    if (found) atomicOr(&bad, 1);
    __syncthreads();
    if (threadIdx.x == 0) g_is64 = bad ? 0 : 1;
}

__global__ void convert_idx_k(const void* __restrict__ ei) {
    int e = blockIdx.x * blockDim.x + threadIdx.x;
    if (e >= NE) return;
    int s, d;
    if (g_is64) {
        const long long* p = (const long long*)ei;
        s = (int)p[e];
        d = (int)p[e + NE];
    } else {
        const int* p = (const int*)ei;
        s = p[e];
        d = p[e + NE];
    }
    g_src[e] = min(max(s, 0), NN - 1);
    g_dst[e] = min(max(d, 0), NN - 1);
}

// ---------------- CSR build ----------------
__global__ void zero_cnt_k() {
    int i = blockIdx.x * blockDim.x + threadIdx.x;
    if (i < NN) g_cnt[i] = 0;
}

__global__ void count_k() {
    int e = blockIdx.x * blockDim.x + threadIdx.x;
    if (e < NE) atomicAdd(&g_cnt[g_dst[e]], 1);
}

__global__ void scan_k() {
    __shared__ int sh[1024];
    __shared__ int carry_s;
    int tid = threadIdx.x;
    if (tid == 0) carry_s = 0;
    __syncthreads();
    for (int base = 0; base < NN; base += 1024) {
        int i = base + tid;
        int v = (i < NN) ? g_cnt[i] : 0;
        sh[tid] = v;
        __syncthreads();
        for (int off = 1; off < 1024; off <<= 1) {
            int x = (tid >= off) ? sh[tid - off] : 0;
            __syncthreads();
            sh[tid] += x;
            __syncthreads();
        }
        int carry = carry_s;
        if (i < NN) {
            g_rowptr[i] = carry + sh[tid] - v;
            g_cursor[i] = 0;
        }
        __syncthreads();
        if (tid == 0) carry_s = carry + sh[1023];
        __syncthreads();
    }
    if (tid == 0) g_rowptr[NN] = carry_s;
}

__global__ void invdeg_k() {
    int n = blockIdx.x * blockDim.x + threadIdx.x;
    if (n >= NN) return;
    int d = g_rowptr[n + 1] - g_rowptr[n];
    g_invdeg[n] = 1.0f / (float)max(d, 1);
}

__global__ void fill_k() {
    int e = blockIdx.x * blockDim.x + threadIdx.x;
    if (e >= NE) return;
    int d = g_dst[e];
    int slot = g_rowptr[d] + atomicAdd(&g_cursor[d], 1);
    g_csrc[slot] = g_src[e];
}

// ---------------- mean aggregation via CSR gather ----------------
__global__ void gather512_k(int in_sel, const float* __restrict__ ext) {
    const float* x = pickc(in_sel, ext);
    int node = blockIdx.x;
    int tid = threadIdx.x;
    int beg = g_rowptr[node], end = g_rowptr[node + 1];
    float4 acc = make_float4(0.f, 0.f, 0.f, 0.f);
    int e = beg;
    for (; e + 1 < end; e += 2) {
        int s0 = g_csrc[e], s1 = g_csrc[e + 1];
        float4 v0 = *(const float4*)(x + (long long)s0 * HID + tid * 4);
        float4 v1 = *(const float4*)(x + (long long)s1 * HID + tid * 4);
        acc.x += v0.x + v1.x; acc.y += v0.y + v1.y;
        acc.z += v0.z + v1.z; acc.w += v0.w + v1.w;
    }
    if (e < end) {
        int s = g_csrc[e];
        float4 v = *(const float4*)(x + (long long)s * HID + tid * 4);
        acc.x += v.x; acc.y += v.y; acc.z += v.z; acc.w += v.w;
    }
    float inv = g_invdeg[node];
    acc.x *= inv; acc.y *= inv; acc.z *= inv; acc.w *= inv;
    *(float4*)(g_agg + (long long)node * HID + tid * 4) = acc;
}

__global__ void gather50_k(const float* __restrict__ x) {
    int node = blockIdx.x;
    int tid = threadIdx.x;
    if (tid >= INF) return;
    int beg = g_rowptr[node], end = g_rowptr[node + 1];
    float acc = 0.f;
    for (int e = beg; e < end; ++e) {
        int s = g_csrc[e];
        acc += x[(long long)s * INF + tid];
    }
    g_agg[(long long)node * INF + tid] = acc * g_invdeg[node];
}

// ---------------- bf16 3-split tensor-core dual GEMM ----------------
// C = g_agg @ W1 + A2 @ W2 + bias
// BM=128, BN=128, BK=32, 512 threads = 16 warps (4x4), warp tile 32x32.
// smem: packed bf16x2 pairs, hi/lo interleaved as uint2, row stride 20 uint2
// (conflict-free LDS.64). Double-buffered with register-staged prefetch.
#define GBM 128
#define GBN 128
#define GBK 32
#define AROW 20                 // uint2 per row (16 data + 4 pad)
#define STAGE (128 * AROW)      // uint2 per stage per matrix

__device__ __forceinline__ void split2(float v0, float v1, unsigned& hi, unsigned& lo) {
    __nv_bfloat16 h0 = __float2bfloat16(v0);
    __nv_bfloat16 h1 = __float2bfloat16(v1);
    float r0 = v0 - __bfloat162float(h0);
    float r1 = v1 - __bfloat162float(h1);
    __nv_bfloat16 l0 = __float2bfloat16(r0);
    __nv_bfloat16 l1 = __float2bfloat16(r1);
    hi = ((unsigned)__bfloat16_as_ushort(h1) << 16) | (unsigned)__bfloat16_as_ushort(h0);
    lo = ((unsigned)__bfloat16_as_ushort(l1) << 16) | (unsigned)__bfloat16_as_ushort(l0);
}

__device__ __forceinline__ void mma_bf16(float* c,
                                         unsigned a0, unsigned a1, unsigned a2, unsigned a3,
                                         unsigned b0, unsigned b1) {
    asm volatile(
        "mma.sync.aligned.m16n8k16.row.col.f32.bf16.bf16.f32 "
        "{%0,%1,%2,%3},{%4,%5,%6,%7},{%8,%9},{%0,%1,%2,%3};"
        : "+f"(c[0]), "+f"(c[1]), "+f"(c[2]), "+f"(c[3])
        : "r"(a0), "r"(a1), "r"(a2), "r"(a3), "r"(b0), "r"(b1));
}

__global__ void __launch_bounds__(512, 1)
gemm_bf16_k(int M, int N, int K, int SL,
            const float* __restrict__ W1,
            int a2_sel, const float* __restrict__ a2_ext,
            const float* __restrict__ W2,
            const float* __restrict__ bias,
            int c_sel, float* __restrict__ c_ext) {
    extern __shared__ uint2 sm[];
    uint2* sA = sm;              // [2][128][AROW]
    uint2* sB = sm + 2 * STAGE;  // [2][128][AROW]

    const float* A2 = pickc(a2_sel, a2_ext);
    float* C = pick(c_sel, c_ext);

    int tid = threadIdx.x;
    int warp = tid >> 5, lane = tid & 31;
    int wm = warp & 3;         // 4 warp rows x 32
    int wn = warp >> 2;        // 4 warp cols x 32
    int g = lane >> 2, t = lane & 3;
    int row0 = blockIdx.y * GBM;
    int col0 = blockIdx.x * GBN;

    int S = 2 * SL;

    float acc[2][4][4];
#pragma unroll
    for (int mi = 0; mi < 2; mi++)
#pragma unroll
        for (int ni = 0; ni < 4; ni++)
#pragma unroll
            for (int r = 0; r < 4; r++) acc[mi][ni][r] = 0.f;

    float aR[8], bR[8];

    auto LDG = [&](int s) {
        int pass = (s >= SL) ? 1 : 0;
        int kk0 = (s - pass * SL) * GBK;
        const float* A = pass ? A2 : g_agg;
        const float* W = pass ? W2 : W1;
#pragma unroll
        for (int l = 0; l < 4; l++) {
            int idx = tid + l * 512;
            int r = idx >> 4, k2 = idx & 15;
            int row = row0 + r, k = kk0 + 2 * k2;
            bool okr = row < M;
            aR[2 * l]     = (okr && k < K)     ? A[(size_t)row * K + k]     : 0.f;
            aR[2 * l + 1] = (okr && k + 1 < K) ? A[(size_t)row * K + k + 1] : 0.f;
        }
#pragma unroll
        for (int l = 0; l < 4; l++) {
            int idx = tid + l * 512;
            int n = idx & 127, k2 = idx >> 7;
            int col = col0 + n, k = kk0 + 2 * k2;
            bool okc = col < N;
            bR[2 * l]     = (okc && k < K)     ? W[(size_t)k * N + col]       : 0.f;
            bR[2 * l + 1] = (okc && k + 1 < K) ? W[(size_t)(k + 1) * N + col] : 0.f;
        }
    };

    auto STS = [&](int st) {
        uint2* As = sA + st * STAGE;
        uint2* Bs = sB + st * STAGE;
#pragma unroll
        for (int l = 0; l < 4; l++) {
            int idx = tid + l * 512;
            int r = idx >> 4, k2 = idx & 15;
            unsigned hi, lo;
            split2(aR[2 * l], aR[2 * l + 1], hi, lo);
            As[r * AROW + k2] = make_uint2(hi, lo);
        }
#pragma unroll
        for (int l = 0; l < 4; l++) {
            int idx = tid + l * 512;
            int n = idx & 127, k2 = idx >> 7;
            unsigned hi, lo;
            split2(bR[2 * l], bR[2 * l + 1], hi, lo);
            Bs[n * AROW + k2] = make_uint2(hi, lo);
        }
    };

    auto COMPUTE = [&](int st) {
        const uint2* As = sA + st * STAGE;
        const uint2* Bs = sB + st * STAGE;
#pragma unroll
        for (int ks = 0; ks < 2; ks++) {
            int kb = ks * 8;
            uint2 af[2][4];
#pragma unroll
            for (int mi = 0; mi < 2; mi++) {
                int rb = wm * 32 + mi * 16;
                af[mi][0] = As[(rb + g) * AROW + kb + t];
                af[mi][1] = As[(rb + g + 8) * AROW + kb + t];
                af[mi][2] = As[(rb + g) * AROW + kb + t + 4];
                af[mi][3] = As[(rb + g + 8) * AROW + kb + t + 4];
            }
            uint2 bf_[4][2];
#pragma unroll
            for (int ni = 0; ni < 4; ni++) {
                int cb = wn * 32 + ni * 8 + g;
                bf_[ni][0] = Bs[cb * AROW + kb + t];
                bf_[ni][1] = Bs[cb * AROW + kb + t + 4];
            }
#pragma unroll
            for (int mi = 0; mi < 2; mi++)
#pragma unroll
                for (int ni = 0; ni < 4; ni++) {
                    float* c = acc[mi][ni];
                    // hi*hi
                    mma_bf16(c, af[mi][0].x, af[mi][1].x, af[mi][2].x, af[mi][3].x,
                             bf_[ni][0].x, bf_[ni][1].x);
                    // hi*lo
                    mma_bf16(c, af[mi][0].x, af[mi][1].x, af[mi][2].x, af[mi][3].x,
                             bf_[ni][0].y, bf_[ni][1].y);
                    // lo*hi
                    mma_bf16(c, af[mi][0].y, af[mi][1].y, af[mi][2].y, af[mi][3].y,
                             bf_[ni][0].x, bf_[ni][1].x);
                }
        }
    };

    // pipeline
    LDG(0);
    STS(0);
    __syncthreads();
#pragma unroll 1
    for (int s = 0; s < S; s++) {
        int st = s & 1;
        if (s + 1 < S) LDG(s + 1);
        COMPUTE(st);
        if (s + 1 < S) {
            STS(st ^ 1);
            __syncthreads();
        }
    }

    // epilogue with bias
#pragma unroll
    for (int mi = 0; mi < 2; mi++) {
        int ra = row0 + wm * 32 + mi * 16 + g;
        int rb = ra + 8;
#pragma unroll
        for (int ni = 0; ni < 4; ni++) {
            int col = col0 + wn * 32 + ni * 8 + t * 2;
            float* c = acc[mi][ni];
            if (col < N) {
                float b0 = bias[col];
                if (ra < M) C[(size_t)ra * N + col] = c[0] + b0;
                if (rb < M) C[(size_t)rb * N + col] = c[2] + b0;
            }
            if (col + 1 < N) {
                float b1 = bias[col + 1];
                if (ra < M) C[(size_t)ra * N + col + 1] = c[1] + b1;
                if (rb < M) C[(size_t)rb * N + col + 1] = c[3] + b1;
            }
        }
    }
}

// ---------------- batch norm ----------------
__global__ void zero_stats_k() {
    int i = threadIdx.x + blockIdx.x * blockDim.x;
    if (i < HID) { g_colsum[i] = 0.f; g_colsq[i] = 0.f; }
}

__global__ void bnstat_k(int sel) {
    const float* h = pickc(sel, nullptr);
    int col = blockIdx.x * 32 + threadIdx.x;
    float s = 0.f, q = 0.f;
    for (int n = blockIdx.y * blockDim.y + threadIdx.y; n < NN; n += gridDim.y * blockDim.y) {
        float v = h[(long long)n * HID + col];
        s += v;
        q += v * v;
    }
    __shared__ float ss[8][33];
    __shared__ float qq[8][33];
    ss[threadIdx.y][threadIdx.x] = s;
    qq[threadIdx.y][threadIdx.x] = q;
    __syncthreads();
    if (threadIdx.y == 0) {
#pragma unroll
        for (int y = 1; y < 8; y++) {
            s += ss[y][threadIdx.x];
            q += qq[y][threadIdx.x];
        }
        atomicAdd(&g_colsum[col], s);
        atomicAdd(&g_colsq[col], q);
    }
}

__global__ void bnfin_k(const float* __restrict__ gamma, const float* __restrict__ beta) {
    int j = blockIdx.x * blockDim.x + threadIdx.x;
    if (j >= HID) return;
    float mean = g_colsum[j] * (1.0f / NN);
    float var = g_colsq[j] * (1.0f / NN) - mean * mean;
    float rstd = rsqrtf(var + EPSF);
    float sc = rstd * gamma[j];
    g_scale[j] = sc;
    g_shift[j] = beta[j] - mean * sc;
}

__global__ void bnapply_k(int sel) {
    float* h = pick(sel, nullptr);
    long long idx = (long long)blockIdx.x * blockDim.x + threadIdx.x;
    if (idx >= (long long)NN * HID) return;
    int c = (int)(idx & (HID - 1));
    float v = h[idx] * g_scale[c] + g_shift[c];
    h[idx] = fmaxf(v, 0.f);
}

// ---------------- host orchestration ----------------
static inline int cdiv(long long a, int b) { return (int)((a + b - 1) / b); }

#define GEMM_SMEM (4 * STAGE * 8)  // 4 stages-worth of uint2 (A0,A1,B0,B1), 8B each

extern "C" void kernel_launch(void* const* d_in, const int* in_sizes, int n_in,
                              void* d_out, int out_size) {
    const float* x = (const float*)d_in[0];
    const void* ei = d_in[1];

    const float* Wl[4] = {(const float*)d_in[2], (const float*)d_in[5],
                          (const float*)d_in[8], (const float*)d_in[11]};
    const float* bl[4] = {(const float*)d_in[3], (const float*)d_in[6],
                          (const float*)d_in[9], (const float*)d_in[12]};
    const float* Wr[4] = {(const float*)d_in[4], (const float*)d_in[7],
                          (const float*)d_in[10], (const float*)d_in[13]};
    const float* gam[3] = {(const float*)d_in[14], (const float*)d_in[16], (const float*)d_in[18]};
    const float* bet[3] = {(const float*)d_in[15], (const float*)d_in[17], (const float*)d_in[19]};

    float* out = (float*)d_out;

    cudaFuncSetAttribute(gemm_bf16_k, cudaFuncAttributeMaxDynamicSharedMemorySize, GEMM_SMEM);

    // edge indices -> int32, CSR build
    detect_idx_k<<<1, 1024>>>((const long long*)ei);
    convert_idx_k<<<cdiv(NE, 256), 256>>>(ei);
    zero_cnt_k<<<cdiv(NN, 256), 256>>>();
    count_k<<<cdiv(NE, 256), 256>>>();
    scan_k<<<1, 1024>>>();
    invdeg_k<<<cdiv(NN, 256), 256>>>();
    fill_k<<<cdiv(NE, 256), 256>>>();

    // ---- layer 1: IN_F=50 -> HID (input x -> g_h) ----
    {
        gather50_k<<<NN, 64>>>(x);
        dim3 g(cdiv(HID, GBN), cdiv(NN, GBM));
        gemm_bf16_k<<<g, 512, GEMM_SMEM>>>(NN, HID, INF, cdiv(INF, GBK),
                                           Wl[0], 0, x, Wr[0], bl[0], 1, nullptr);
        zero_stats_k<<<2, 256>>>();
        bnstat_k<<<dim3(HID / 32, 64), dim3(32, 8)>>>(1);
        bnfin_k<<<2, 256>>>(gam[0], bet[0]);
        bnapply_k<<<cdiv((long long)NN * HID, 256), 256>>>(1);
    }

    // ---- layers 2 & 3: HID -> HID ----
    for (int L = 1; L <= 2; ++L) {
        int in_sel = (L == 1) ? 1 : 2;
        int out_sel = (L == 1) ? 2 : 1;
        gather512_k<<<NN, 128>>>(in_sel, nullptr);
        dim3 g(cdiv(HID, GBN), cdiv(NN, GBM));
        gemm_bf16_k<<<g, 512, GEMM_SMEM>>>(NN, HID, HID, HID / GBK,
                                           Wl[L], in_sel, nullptr, Wr[L], bl[L], out_sel, nullptr);
        zero_stats_k<<<2, 256>>>();
        bnstat_k<<<dim3(HID / 32, 64), dim3(32, 8)>>>(out_sel);
        bnfin_k<<<2, 256>>>(gam[L], bet[L]);
        bnapply_k<<<cdiv((long long)NN * HID, 256), 256>>>(out_sel);
    }

    // ---- layer 4: HID -> OUT_F -> d_out ----
    {
        gather512_k<<<NN, 128>>>(1, nullptr);
        dim3 g(cdiv(OUTF, GBN), cdiv(NN, GBM));
        gemm_bf16_k<<<g, 512, GEMM_SMEM>>>(NN, OUTF, HID, HID / GBK,
                                           Wl[3], 1, nullptr, Wr[3], bl[3], 0, out);
    }
}

// round 7
// speedup vs baseline: 3.4302x; 1.1601x over previous
#include <cuda_runtime.h>
#include <cuda_bf16.h>

#define NN   50000
#define NNP  50048
#define NE   400000
#define INF  50
#define HID  512
#define OUTF 121
#define EPSF 1e-5f

// ---------------- device scratch ----------------
__device__ float g_invdeg[NN];
__device__ float g_h[(size_t)NNP * HID];
__device__ __nv_bfloat16 g_aggh[(size_t)NNP * HID];
__device__ __nv_bfloat16 g_aggl[(size_t)NNP * HID];
__device__ __nv_bfloat16 g_hbh[(size_t)NNP * HID];
__device__ __nv_bfloat16 g_hbl[(size_t)NNP * HID];
__device__ __nv_bfloat16 g_xh[(size_t)NNP * 64];
__device__ __nv_bfloat16 g_xl[(size_t)NNP * 64];
__device__ __nv_bfloat16 g_a1h[(size_t)NNP * 64];
__device__ __nv_bfloat16 g_a1l[(size_t)NNP * 64];

// weight planes: [Npad][Kpad] (transposed), concatenated
#define OFF_WL1 0
#define OFF_WR1 32768
#define OFF_WL2 65536
#define OFF_WR2 327680
#define OFF_WL3 589824
#define OFF_WR3 851968
#define OFF_WL4 1114112
#define OFF_WR4 1179648
#define WTOT    1245184
__device__ __nv_bfloat16 g_wh[WTOT];
__device__ __nv_bfloat16 g_wl[WTOT];

__device__ float g_colsum[HID], g_colsq[HID], g_scale[HID], g_shift[HID];
__device__ int g_src[NE], g_dst[NE], g_csrc[NE];
__device__ int g_rowptr[NN + 1], g_cnt[NN], g_cursor[NN], g_is64;

// ---------------- helpers ----------------
__device__ __forceinline__ unsigned s2u(const void* p) {
    unsigned a;
    asm("{ .reg .u64 t; cvta.to.shared.u64 t, %1; cvt.u32.u64 %0, t; }" : "=r"(a) : "l"(p));
    return a;
}
__device__ __forceinline__ void cp16(unsigned dst, const void* src) {
    asm volatile("cp.async.cg.shared.global [%0], [%1], 16;" :: "r"(dst), "l"(src));
}
__device__ __forceinline__ void split1(float v, __nv_bfloat16& hi, __nv_bfloat16& lo) {
    hi = __float2bfloat16(v);
    lo = __float2bfloat16(v - __bfloat162float(hi));
}
__device__ __forceinline__ void mma_bf16(float* c,
                                         unsigned a0, unsigned a1, unsigned a2, unsigned a3,
                                         unsigned b0, unsigned b1) {
    asm volatile(
        "mma.sync.aligned.m16n8k16.row.col.f32.bf16.bf16.f32 "
        "{%0,%1,%2,%3},{%4,%5,%6,%7},{%8,%9},{%0,%1,%2,%3};"
        : "+f"(c[0]), "+f"(c[1]), "+f"(c[2]), "+f"(c[3])
        : "r"(a0), "r"(a1), "r"(a2), "r"(a3), "r"(b0), "r"(b1));
}

// ---------------- edge index detection + conversion ----------------
__global__ void detect_idx_k(const long long* __restrict__ ei) {
    __shared__ int bad;
    if (threadIdx.x == 0) bad = 0;
    __syncthreads();
    int found = 0;
    for (int i = threadIdx.x; i < NE; i += blockDim.x) {
        long long v = ei[i];
        if (v < 0 || v >= NN) { found = 1; break; }
    }
    if (found) atomicOr(&bad, 1);
    __syncthreads();
    if (threadIdx.x == 0) g_is64 = bad ? 0 : 1;
}
__global__ void convert_idx_k(const void* __restrict__ ei) {
    int e = blockIdx.x * blockDim.x + threadIdx.x;
    if (e >= NE) return;
    int s, d;
    if (g_is64) {
        const long long* p = (const long long*)ei;
        s = (int)p[e]; d = (int)p[e + NE];
    } else {
        const int* p = (const int*)ei;
        s = p[e]; d = p[e + NE];
    }
    g_src[e] = min(max(s, 0), NN - 1);
    g_dst[e] = min(max(d, 0), NN - 1);
}

// ---------------- CSR build ----------------
__global__ void zero_cnt_k() {
    int i = blockIdx.x * blockDim.x + threadIdx.x;
    if (i < NN) g_cnt[i] = 0;
}
__global__ void count_k() {
    int e = blockIdx.x * blockDim.x + threadIdx.x;
    if (e < NE) atomicAdd(&g_cnt[g_dst[e]], 1);
}
__global__ void scan_k() {
    __shared__ int sh[1024];
    __shared__ int carry_s;
    int tid = threadIdx.x;
    if (tid == 0) carry_s = 0;
    __syncthreads();
    for (int base = 0; base < NN; base += 1024) {
        int i = base + tid;
        int v = (i < NN) ? g_cnt[i] : 0;
        sh[tid] = v;
        __syncthreads();
        for (int off = 1; off < 1024; off <<= 1) {
            int x = (tid >= off) ? sh[tid - off] : 0;
            __syncthreads();
            sh[tid] += x;
            __syncthreads();
        }
        int carry = carry_s;
        if (i < NN) { g_rowptr[i] = carry + sh[tid] - v; g_cursor[i] = 0; }
        __syncthreads();
        if (tid == 0) carry_s = carry + sh[1023];
        __syncthreads();
    }
    if (tid == 0) g_rowptr[NN] = carry_s;
}
__global__ void invdeg_k() {
    int n = blockIdx.x * blockDim.x + threadIdx.x;
    if (n >= NN) return;
    int d = g_rowptr[n + 1] - g_rowptr[n];
    g_invdeg[n] = 1.0f / (float)max(d, 1);
}
__global__ void fill_k() {
    int e = blockIdx.x * blockDim.x + threadIdx.x;
    if (e >= NE) return;
    int d = g_dst[e];
    int slot = g_rowptr[d] + atomicAdd(&g_cursor[d], 1);
    g_csrc[slot] = g_src[e];
}

// ---------------- plane preparation ----------------
__global__ void wsplit_k(const float* __restrict__ W, int K, int N, int Kpad, int Npad, int off) {
    int idx = blockIdx.x * blockDim.x + threadIdx.x;
    if (idx >= Npad * Kpad) return;
    int n = idx / Kpad, k = idx - n * Kpad;
    float v = (n < N && k < K) ? W[(size_t)k * N + n] : 0.f;
    __nv_bfloat16 hi, lo;
    split1(v, hi, lo);
    g_wh[off + idx] = hi;
    g_wl[off + idx] = lo;
}
__global__ void xsplit_k(const float* __restrict__ x) {
    int idx = blockIdx.x * blockDim.x + threadIdx.x;
    if (idx >= NN * 64) return;
    int n = idx >> 6, c = idx & 63;
    float v = (c < INF) ? x[(size_t)n * INF + c] : 0.f;
    __nv_bfloat16 hi, lo;
    split1(v, hi, lo);
    g_xh[idx] = hi;
    g_xl[idx] = lo;
}

// ---------------- gathers (CSR mean) ----------------
__global__ void gather50_k(const float* __restrict__ x) {
    int node = blockIdx.x;
    int t = threadIdx.x;  // 64
    float acc = 0.f;
    if (t < INF) {
        int beg = g_rowptr[node], end = g_rowptr[node + 1];
        for (int e = beg; e < end; ++e) acc += x[(size_t)g_csrc[e] * INF + t];
        acc *= g_invdeg[node];
    }
    __nv_bfloat16 hi, lo;
    split1(acc, hi, lo);
    g_a1h[(size_t)node * 64 + t] = hi;
    g_a1l[(size_t)node * 64 + t] = lo;
}
__global__ void gather512_k() {
    int node = blockIdx.x;
    int tid = threadIdx.x;
    size_t coff = (size_t)tid * 4;
    int beg = g_rowptr[node], end = g_rowptr[node + 1];
    float a0 = 0.f, a1 = 0.f, a2 = 0.f, a3 = 0.f;
    for (int e = beg; e < end; ++e) {
        size_t base = (size_t)g_csrc[e] * HID + coff;
        ushort4 hh = *(const ushort4*)(g_hbh + base);
        ushort4 ll = *(const ushort4*)(g_hbl + base);
        a0 += __bfloat162float(__ushort_as_bfloat16(hh.x)) + __bfloat162float(__ushort_as_bfloat16(ll.x));
        a1 += __bfloat162float(__ushort_as_bfloat16(hh.y)) + __bfloat162float(__ushort_as_bfloat16(ll.y));
        a2 += __bfloat162float(__ushort_as_bfloat16(hh.z)) + __bfloat162float(__ushort_as_bfloat16(ll.z));
        a3 += __bfloat162float(__ushort_as_bfloat16(hh.w)) + __bfloat162float(__ushort_as_bfloat16(ll.w));
    }
    float inv = g_invdeg[node];
    a0 *= inv; a1 *= inv; a2 *= inv; a3 *= inv;
    __nv_bfloat16 h0, l0, h1, l1, h2, l2, h3, l3;
    split1(a0, h0, l0); split1(a1, h1, l1); split1(a2, h2, l2); split1(a3, h3, l3);
    size_t o = (size_t)node * HID + coff;
    *(ushort4*)(g_aggh + o) = make_ushort4(__bfloat16_as_ushort(h0), __bfloat16_as_ushort(h1),
                                           __bfloat16_as_ushort(h2), __bfloat16_as_ushort(h3));
    *(ushort4*)(g_aggl + o) = make_ushort4(__bfloat16_as_ushort(l0), __bfloat16_as_ushort(l1),
                                           __bfloat16_as_ushort(l2), __bfloat16_as_ushort(l3));
}

// ---------------- dual GEMM: mma.sync bf16 3-split, planes pre-split in gmem ----------------
// C[NNP,N] = A1 @ B1^T + A2 @ B2^T + bias. BM=128, BN=128, BK=32, 512 threads.
// smem per stage: 4 plane arrays [128][20] uint (16 data + 4 pad), conflict-free frags.
#define AW 20
#define ASZ (128 * AW)            // uints per plane array
#define STG (4 * ASZ)             // uints per stage
#define GEMM_SMEM (2 * STG * 4)   // bytes

__global__ void __launch_bounds__(512, 1)
gemm_k(int aSel, int K1, int K2, int woff1, int woff2,
       const float* __restrict__ bias, int N, int cSel, float* __restrict__ cExt) {
    extern __shared__ unsigned sm[];
    unsigned sbase = s2u(sm);

    const __nv_bfloat16 *A1h, *A1l, *A2h, *A2l;
    if (aSel == 0) { A1h = g_a1h; A1l = g_a1l; A2h = g_xh; A2l = g_xl; }
    else           { A1h = g_aggh; A1l = g_aggl; A2h = g_hbh; A2l = g_hbl; }
    const __nv_bfloat16* B1h = g_wh + woff1;
    const __nv_bfloat16* B1l = g_wl + woff1;
    const __nv_bfloat16* B2h = g_wh + woff2;
    const __nv_bfloat16* B2l = g_wl + woff2;
    float* C = (cSel == 1) ? g_h : cExt;

    int tid = threadIdx.x;
    int warp = tid >> 5, lane = tid & 31;
    int wm = warp & 3, wn = warp >> 2;
    int g = lane >> 2, t = lane & 3;
    int row0 = blockIdx.y * 128;
    int col0 = blockIdx.x * 128;

    int S1 = K1 >> 5, S2 = K2 >> 5, S = S1 + S2;

    float acc[2][4][4];
#pragma unroll
    for (int mi = 0; mi < 2; mi++)
#pragma unroll
        for (int ni = 0; ni < 4; ni++)
#pragma unroll
            for (int r = 0; r < 4; r++) acc[mi][ni][r] = 0.f;

    int prow = tid >> 2, pch = tid & 3;   // prefetch row/chunk (one 16B chunk per plane)

    auto prefetch = [&](int s, int buf) {
        const __nv_bfloat16 *Ah, *Al, *Bh, *Bl;
        int ka, k0;
        if (s < S1) { Ah = A1h; Al = A1l; Bh = B1h; Bl = B1l; ka = K1; k0 = s * 32; }
        else        { Ah = A2h; Al = A2l; Bh = B2h; Bl = B2l; ka = K2; k0 = (s - S1) * 32; }
        unsigned b = sbase + buf * (STG * 4) + prow * (AW * 4) + pch * 16;
        size_t aoff = (size_t)(row0 + prow) * ka + k0 + pch * 8;
        size_t boff = (size_t)(col0 + prow) * ka + k0 + pch * 8;
        cp16(b,                 Ah + aoff);
        cp16(b + ASZ * 4,       Al + aoff);
        cp16(b + 2 * ASZ * 4,   Bh + boff);
        cp16(b + 3 * ASZ * 4,   Bl + boff);
        asm volatile("cp.async.commit_group;" ::: "memory");
    };

    auto compute = [&](int buf) {
        const unsigned* Ah = sm + buf * STG;
        const unsigned* Al = Ah + ASZ;
        const unsigned* Bh = Ah + 2 * ASZ;
        const unsigned* Bl = Ah + 3 * ASZ;
#pragma unroll
        for (int ks = 0; ks < 2; ks++) {
            int kb = ks * 8;
            unsigned ah[2][4], al[2][4];
#pragma unroll
            for (int mi = 0; mi < 2; mi++) {
                int rb = wm * 32 + mi * 16;
                int i0 = (rb + g) * AW + kb + t;
                int i1 = (rb + g + 8) * AW + kb + t;
                ah[mi][0] = Ah[i0];     al[mi][0] = Al[i0];
                ah[mi][1] = Ah[i1];     al[mi][1] = Al[i1];
                ah[mi][2] = Ah[i0 + 4]; al[mi][2] = Al[i0 + 4];
                ah[mi][3] = Ah[i1 + 4]; al[mi][3] = Al[i1 + 4];
            }
            unsigned bh[4][2], blo[4][2];
#pragma unroll
            for (int ni = 0; ni < 4; ni++) {
                int cb = (wn * 32 + ni * 8 + g) * AW + kb + t;
                bh[ni][0] = Bh[cb];     blo[ni][0] = Bl[cb];
                bh[ni][1] = Bh[cb + 4]; blo[ni][1] = Bl[cb + 4];
            }
#pragma unroll
            for (int mi = 0; mi < 2; mi++)
#pragma unroll
                for (int ni = 0; ni < 4; ni++) {
                    float* c = acc[mi][ni];
                    mma_bf16(c, ah[mi][0], ah[mi][1], ah[mi][2], ah[mi][3], bh[ni][0], bh[ni][1]);
                    mma_bf16(c, ah[mi][0], ah[mi][1], ah[mi][2], ah[mi][3], blo[ni][0], blo[ni][1]);
                    mma_bf16(c, al[mi][0], al[mi][1], al[mi][2], al[mi][3], bh[ni][0], bh[ni][1]);
                }
        }
    };

    prefetch(0, 0);
#pragma unroll 1
    for (int s = 0; s < S; s++) {
        int buf = s & 1;
        asm volatile("cp.async.wait_group 0;" ::: "memory");
        __syncthreads();
        if (s + 1 < S) prefetch(s + 1, buf ^ 1);
        compute(buf);
        __syncthreads();
    }

    // epilogue with bias
#pragma unroll
    for (int mi = 0; mi < 2; mi++) {
        int ra = row0 + wm * 32 + mi * 16 + g;
        int rb = ra + 8;
#pragma unroll
        for (int ni = 0; ni < 4; ni++) {
            int col = col0 + wn * 32 + ni * 8 + t * 2;
            float* c = acc[mi][ni];
            if (col < N) {
                float b0 = __ldg(&bias[col]);
                if (ra < NN) C[(size_t)ra * N + col] = c[0] + b0;
                if (rb < NN) C[(size_t)rb * N + col] = c[2] + b0;
            }
            if (col + 1 < N) {
                float b1 = __ldg(&bias[col + 1]);
                if (ra < NN) C[(size_t)ra * N + col + 1] = c[1] + b1;
                if (rb < NN) C[(size_t)rb * N + col + 1] = c[3] + b1;
            }
        }
    }
}

// ---------------- batch norm ----------------
__global__ void zero_stats_k() {
    int i = threadIdx.x + blockIdx.x * blockDim.x;
    if (i < HID) { g_colsum[i] = 0.f; g_colsq[i] = 0.f; }
}
__global__ void bnstat_k() {
    int col = blockIdx.x * 32 + threadIdx.x;
    float s = 0.f, q = 0.f;
    for (int n = blockIdx.y * blockDim.y + threadIdx.y; n < NN; n += gridDim.y * blockDim.y) {
        float v = g_h[(size_t)n * HID + col];
        s += v; q += v * v;
    }
    __shared__ float ss[8][33];
    __shared__ float qq[8][33];
    ss[threadIdx.y][threadIdx.x] = s;
    qq[threadIdx.y][threadIdx.x] = q;
    __syncthreads();
    if (threadIdx.y == 0) {
#pragma unroll
        for (int y = 1; y < 8; y++) { s += ss[y][threadIdx.x]; q += qq[y][threadIdx.x]; }
        atomicAdd(&g_colsum[col], s);
        atomicAdd(&g_colsq[col], q);
    }
}
__global__ void bnfin_k(const float* __restrict__ gamma, const float* __restrict__ beta) {
    int j = blockIdx.x * blockDim.x + threadIdx.x;
    if (j >= HID) return;
    float mean = g_colsum[j] * (1.0f / NN);
    float var = g_colsq[j] * (1.0f / NN) - mean * mean;
    float rstd = rsqrtf(var + EPSF);
    float sc = rstd * gamma[j];
    g_scale[j] = sc;
    g_shift[j] = beta[j] - mean * sc;
}
__global__ void bnapply_plane_k() {
    size_t idx = (size_t)blockIdx.x * blockDim.x + threadIdx.x;
    if (idx >= (size_t)NN * HID) return;
    int c = (int)(idx & (HID - 1));
    float v = fmaxf(g_h[idx] * g_scale[c] + g_shift[c], 0.f);
    __nv_bfloat16 hi, lo;
    split1(v, hi, lo);
    g_hbh[idx] = hi;
    g_hbl[idx] = lo;
}

// ---------------- host ----------------
static inline int cdiv(long long a, int b) { return (int)((a + b - 1) / b); }

extern "C" void kernel_launch(void* const* d_in, const int* in_sizes, int n_in,
                              void* d_out, int out_size) {
    const float* x = (const float*)d_in[0];
    const void* ei = d_in[1];

    const float* Wl[4] = {(const float*)d_in[2], (const float*)d_in[5],
                          (const float*)d_in[8], (const float*)d_in[11]};
    const float* bl[4] = {(const float*)d_in[3], (const float*)d_in[6],
                          (const float*)d_in[9], (const float*)d_in[12]};
    const float* Wr[4] = {(const float*)d_in[4], (const float*)d_in[7],
                          (const float*)d_in[10], (const float*)d_in[13]};
    const float* gam[3] = {(const float*)d_in[14], (const float*)d_in[16], (const float*)d_in[18]};
    const float* bet[3] = {(const float*)d_in[15], (const float*)d_in[17], (const float*)d_in[19]};
    float* out = (float*)d_out;

    cudaFuncSetAttribute(gemm_k, cudaFuncAttributeMaxDynamicSharedMemorySize, GEMM_SMEM);

    // edge indices + CSR
    detect_idx_k<<<1, 1024>>>((const long long*)ei);
    convert_idx_k<<<cdiv(NE, 256), 256>>>(ei);
    zero_cnt_k<<<cdiv(NN, 256), 256>>>();
    count_k<<<cdiv(NE, 256), 256>>>();
    scan_k<<<1, 1024>>>();
    invdeg_k<<<cdiv(NN, 256), 256>>>();
    fill_k<<<cdiv(NE, 256), 256>>>();

    // weight + x planes
    wsplit_k<<<cdiv(512 * 64, 256), 256>>>(Wl[0], INF, HID, 64, 512, OFF_WL1);
    wsplit_k<<<cdiv(512 * 64, 256), 256>>>(Wr[0], INF, HID, 64, 512, OFF_WR1);
    wsplit_k<<<cdiv(512 * 512, 256), 256>>>(Wl[1], HID, HID, 512, 512, OFF_WL2);
    wsplit_k<<<cdiv(512 * 512, 256), 256>>>(Wr[1], HID, HID, 512, 512, OFF_WR2);
    wsplit_k<<<cdiv(512 * 512, 256), 256>>>(Wl[2], HID, HID, 512, 512, OFF_WL3);
    wsplit_k<<<cdiv(512 * 512, 256), 256>>>(Wr[2], HID, HID, 512, 512, OFF_WR3);
    wsplit_k<<<cdiv(128 * 512, 256), 256>>>(Wl[3], HID, OUTF, 512, 128, OFF_WL4);
    wsplit_k<<<cdiv(128 * 512, 256), 256>>>(Wr[3], HID, OUTF, 512, 128, OFF_WR4);
    xsplit_k<<<cdiv(NN * 64, 256), 256>>>(x);

    dim3 gfull(4, cdiv(NNP, 128));

    // ---- layer 1 ----
    gather50_k<<<NN, 64>>>(x);
    gemm_k<<<gfull, 512, GEMM_SMEM>>>(0, 64, 64, OFF_WL1, OFF_WR1, bl[0], HID, 1, nullptr);
    zero_stats_k<<<2, 256>>>();
    bnstat_k<<<dim3(HID / 32, 64), dim3(32, 8)>>>();
    bnfin_k<<<2, 256>>>(gam[0], bet[0]);
    bnapply_plane_k<<<cdiv((long long)NN * HID, 256), 256>>>();

    // ---- layers 2 & 3 ----
    for (int L = 1; L <= 2; ++L) {
        int wl = (L == 1) ? OFF_WL2 : OFF_WL3;
        int wr = (L == 1) ? OFF_WR2 : OFF_WR3;
        gather512_k<<<NN, 128>>>();
        gemm_k<<<gfull, 512, GEMM_SMEM>>>(1, 512, 512, wl, wr, bl[L], HID, 1, nullptr);
        zero_stats_k<<<2, 256>>>();
        bnstat_k<<<dim3(HID / 32, 64), dim3(32, 8)>>>();
        bnfin_k<<<2, 256>>>(gam[L], bet[L]);
        bnapply_plane_k<<<cdiv((long long)NN * HID, 256), 256>>>();
    }

    // ---- layer 4 -> d_out ----
    gather512_k<<<NN, 128>>>();
    gemm_k<<<dim3(1, cdiv(NNP, 128)), 512, GEMM_SMEM>>>(1, 512, 512, OFF_WL4, OFF_WR4,
                                                        bl[3], OUTF, 0, out);
}

// round 8
// speedup vs baseline: 3.5144x; 1.0245x over previous
#include <cuda_runtime.h>
#include <cuda_bf16.h>

#define NN   50000
#define NNP  50048
#define NE   400000
#define INF  50
#define HID  512
#define OUTF 121
#define EPSF 1e-5f
#define NSB  49          // scan blocks: cdiv(50000, 1024)

// ---------------- device scratch ----------------
__device__ float g_invdeg[NN];
__device__ float g_h[(size_t)NNP * HID];
__device__ __nv_bfloat16 g_aggh[(size_t)NNP * HID];
__device__ __nv_bfloat16 g_aggl[(size_t)NNP * HID];
__device__ __nv_bfloat16 g_hbh[(size_t)NNP * HID];
__device__ __nv_bfloat16 g_hbl[(size_t)NNP * HID];
__device__ __nv_bfloat16 g_xh[(size_t)NNP * 64];
__device__ __nv_bfloat16 g_xl[(size_t)NNP * 64];
__device__ __nv_bfloat16 g_a1h[(size_t)NNP * 64];
__device__ __nv_bfloat16 g_a1l[(size_t)NNP * 64];

#define OFF_WL1 0
#define OFF_WR1 32768
#define OFF_WL2 65536
#define OFF_WR2 327680
#define OFF_WL3 589824
#define OFF_WR3 851968
#define OFF_WL4 1114112
#define OFF_WR4 1179648
#define WTOT    1245184
__device__ __nv_bfloat16 g_wh[WTOT];
__device__ __nv_bfloat16 g_wl[WTOT];

__device__ float g_colsum[HID], g_colsq[HID], g_scale[HID], g_shift[HID];
__device__ int g_src[NE], g_dst[NE], g_csrc[NE];
__device__ int g_rowptr[NN + 1], g_cnt[NN], g_cursor[NN], g_is64;
__device__ int g_blksum[64], g_blkoff[64];

// ---------------- helpers ----------------
__device__ __forceinline__ unsigned s2u(const void* p) {
    unsigned a;
    asm("{ .reg .u64 t; cvta.to.shared.u64 t, %1; cvt.u32.u64 %0, t; }" : "=r"(a) : "l"(p));
    return a;
}
__device__ __forceinline__ void cp16(unsigned dst, const void* src) {
    asm volatile("cp.async.cg.shared.global [%0], [%1], 16;" :: "r"(dst), "l"(src));
}
__device__ __forceinline__ void split1(float v, __nv_bfloat16& hi, __nv_bfloat16& lo) {
    hi = __float2bfloat16(v);
    lo = __float2bfloat16(v - __bfloat162float(hi));
}
__device__ __forceinline__ void mma_bf16(float* c,
                                         unsigned a0, unsigned a1, unsigned a2, unsigned a3,
                                         unsigned b0, unsigned b1) {
    asm volatile(
        "mma.sync.aligned.m16n8k16.row.col.f32.bf16.bf16.f32 "
        "{%0,%1,%2,%3},{%4,%5,%6,%7},{%8,%9},{%0,%1,%2,%3};"
        : "+f"(c[0]), "+f"(c[1]), "+f"(c[2]), "+f"(c[3])
        : "r"(a0), "r"(a1), "r"(a2), "r"(a3), "r"(b0), "r"(b1));
}

// ---------------- edge index detection + conversion ----------------
__global__ void init_flags_k() {
    if (threadIdx.x == 0 && blockIdx.x == 0) g_is64 = 1;
}
__global__ void detect_idx_k(const long long* __restrict__ ei) {
    int stride = gridDim.x * blockDim.x;
    int bad = 0;
    for (int i = blockIdx.x * blockDim.x + threadIdx.x; i < NE; i += stride) {
        long long v = ei[i];
        if (v < 0 || v >= NN) { bad = 1; break; }
    }
    if (__syncthreads_or(bad)) {
        if (threadIdx.x == 0) atomicExch(&g_is64, 0);
    }
}
__global__ void convert_idx_k(const void* __restrict__ ei) {
    int e = blockIdx.x * blockDim.x + threadIdx.x;
    if (e >= NE) return;
    int s, d;
    if (g_is64) {
        const long long* p = (const long long*)ei;
        s = (int)p[e]; d = (int)p[e + NE];
    } else {
        const int* p = (const int*)ei;
        s = p[e]; d = p[e + NE];
    }
    g_src[e] = min(max(s, 0), NN - 1);
    g_dst[e] = min(max(d, 0), NN - 1);
}

// ---------------- CSR build (parallel scan) ----------------
__global__ void zero_cnt_k() {
    int i = blockIdx.x * blockDim.x + threadIdx.x;
    if (i < NN) g_cnt[i] = 0;
}
__global__ void count_k() {
    int e = blockIdx.x * blockDim.x + threadIdx.x;
    if (e < NE) atomicAdd(&g_cnt[g_dst[e]], 1);
}
// pass 1: per-block inclusive scan of 1024 elements; rowptr gets block-local exclusive
__global__ void scan1_k() {
    __shared__ int sh[1024];
    int tid = threadIdx.x;
    int i = blockIdx.x * 1024 + tid;
    int v = (i < NN) ? g_cnt[i] : 0;
    sh[tid] = v;
    __syncthreads();
#pragma unroll
    for (int off = 1; off < 1024; off <<= 1) {
        int x = (tid >= off) ? sh[tid - off] : 0;
        __syncthreads();
        sh[tid] += x;
        __syncthreads();
    }
    if (i < NN) g_rowptr[i] = sh[tid] - v;
    if (tid == 1023) g_blksum[blockIdx.x] = sh[1023];
}
// pass 2: exclusive scan of block sums (single warp-block)
__global__ void scan2_k() {
    __shared__ int sh[64];
    int t = threadIdx.x;
    int v = (t < NSB) ? g_blksum[t] : 0;
    sh[t] = v;
    __syncthreads();
#pragma unroll
    for (int off = 1; off < 64; off <<= 1) {
        int x = (t >= off) ? sh[t - off] : 0;
        __syncthreads();
        sh[t] += x;
        __syncthreads();
    }
    if (t < 64) g_blkoff[t] = sh[t] - v;
}
// pass 3: add offsets; also cursor=0, invdeg, rowptr[NN]
__global__ void scan3_k() {
    int i = blockIdx.x * blockDim.x + threadIdx.x;
    if (i >= NN) return;
    g_rowptr[i] += g_blkoff[i >> 10];
    g_cursor[i] = 0;
    g_invdeg[i] = 1.0f / (float)max(g_cnt[i], 1);
    if (i == 0) g_rowptr[NN] = g_blkoff[NSB - 1] + g_blksum[NSB - 1];
}
__global__ void fill_k() {
    int e = blockIdx.x * blockDim.x + threadIdx.x;
    if (e >= NE) return;
    int d = g_dst[e];
    int slot = g_rowptr[d] + atomicAdd(&g_cursor[d], 1);
    g_csrc[slot] = g_src[e];
}

// ---------------- plane preparation ----------------
__global__ void wsplit_k(const float* __restrict__ W, int K, int N, int Kpad, int Npad, int off) {
    int idx = blockIdx.x * blockDim.x + threadIdx.x;
    if (idx >= Npad * Kpad) return;
    int n = idx / Kpad, k = idx - n * Kpad;
    float v = (n < N && k < K) ? W[(size_t)k * N + n] : 0.f;
    __nv_bfloat16 hi, lo;
    split1(v, hi, lo);
    g_wh[off + idx] = hi;
    g_wl[off + idx] = lo;
}
__global__ void xsplit_k(const float* __restrict__ x) {
    int idx = blockIdx.x * blockDim.x + threadIdx.x;
    if (idx >= NN * 64) return;
    int n = idx >> 6, c = idx & 63;
    float v = (c < INF) ? x[(size_t)n * INF + c] : 0.f;
    __nv_bfloat16 hi, lo;
    split1(v, hi, lo);
    g_xh[idx] = hi;
    g_xl[idx] = lo;
}

// ---------------- gathers (CSR mean) ----------------
__global__ void gather50_k(const float* __restrict__ x) {
    int node = blockIdx.x;
    int t = threadIdx.x;
    float acc = 0.f;
    if (t < INF) {
        int beg = g_rowptr[node], end = g_rowptr[node + 1];
        for (int e = beg; e < end; ++e) acc += x[(size_t)g_csrc[e] * INF + t];
        acc *= g_invdeg[node];
    }
    __nv_bfloat16 hi, lo;
    split1(acc, hi, lo);
    g_a1h[(size_t)node * 64 + t] = hi;
    g_a1l[(size_t)node * 64 + t] = lo;
}
__global__ void gather512_k() {
    int node = blockIdx.x;
    int tid = threadIdx.x;
    size_t coff = (size_t)tid * 4;
    int beg = g_rowptr[node], end = g_rowptr[node + 1];
    float a0 = 0.f, a1 = 0.f, a2 = 0.f, a3 = 0.f;
    for (int e = beg; e < end; ++e) {
        size_t base = (size_t)g_csrc[e] * HID + coff;
        ushort4 hh = *(const ushort4*)(g_hbh + base);
        ushort4 ll = *(const ushort4*)(g_hbl + base);
        a0 += __bfloat162float(__ushort_as_bfloat16(hh.x)) + __bfloat162float(__ushort_as_bfloat16(ll.x));
        a1 += __bfloat162float(__ushort_as_bfloat16(hh.y)) + __bfloat162float(__ushort_as_bfloat16(ll.y));
        a2 += __bfloat162float(__ushort_as_bfloat16(hh.z)) + __bfloat162float(__ushort_as_bfloat16(ll.z));
        a3 += __bfloat162float(__ushort_as_bfloat16(hh.w)) + __bfloat162float(__ushort_as_bfloat16(ll.w));
    }
    float inv = g_invdeg[node];
    a0 *= inv; a1 *= inv; a2 *= inv; a3 *= inv;
    __nv_bfloat16 h0, l0, h1, l1, h2, l2, h3, l3;
    split1(a0, h0, l0); split1(a1, h1, l1); split1(a2, h2, l2); split1(a3, h3, l3);
    size_t o = (size_t)node * HID + coff;
    *(ushort4*)(g_aggh + o) = make_ushort4(__bfloat16_as_ushort(h0), __bfloat16_as_ushort(h1),
                                           __bfloat16_as_ushort(h2), __bfloat16_as_ushort(h3));
    *(ushort4*)(g_aggl + o) = make_ushort4(__bfloat16_as_ushort(l0), __bfloat16_as_ushort(l1),
                                           __bfloat16_as_ushort(l2), __bfloat16_as_ushort(l3));
}

// ---------------- dual GEMM with fused BN-stat epilogue ----------------
#define AW 20
#define ASZ (128 * AW)
#define STG (4 * ASZ)
#define GEMM_SMEM (3 * STG * 4)   // 3-stage ring

__global__ void __launch_bounds__(512, 1)
gemm_k(int aSel, int K1, int K2, int woff1, int woff2,
       const float* __restrict__ bias, int N, int cSel, float* __restrict__ cExt,
       int doStat) {
    extern __shared__ unsigned sm[];
    unsigned sbase = s2u(sm);
    __shared__ float s_sum[128], s_sq[128];

    const __nv_bfloat16 *A1h, *A1l, *A2h, *A2l;
    if (aSel == 0) { A1h = g_a1h; A1l = g_a1l; A2h = g_xh; A2l = g_xl; }
    else           { A1h = g_aggh; A1l = g_aggl; A2h = g_hbh; A2l = g_hbl; }
    const __nv_bfloat16* B1h = g_wh + woff1;
    const __nv_bfloat16* B1l = g_wl + woff1;
    const __nv_bfloat16* B2h = g_wh + woff2;
    const __nv_bfloat16* B2l = g_wl + woff2;
    float* C = (cSel == 1) ? g_h : cExt;

    int tid = threadIdx.x;
    int warp = tid >> 5, lane = tid & 31;
    int wm = warp & 3, wn = warp >> 2;
    int g = lane >> 2, t = lane & 3;
    int row0 = blockIdx.y * 128;
    int col0 = blockIdx.x * 128;

    int S1 = K1 >> 5, S2 = K2 >> 5, S = S1 + S2;

    float acc[2][4][4];
#pragma unroll
    for (int mi = 0; mi < 2; mi++)
#pragma unroll
        for (int ni = 0; ni < 4; ni++)
#pragma unroll
            for (int r = 0; r < 4; r++) acc[mi][ni][r] = 0.f;

    if (doStat && tid < 128) { s_sum[tid] = 0.f; s_sq[tid] = 0.f; }

    int prow = tid >> 2, pch = tid & 3;

    auto prefetch = [&](int s, int buf) {
        const __nv_bfloat16 *Ah, *Al, *Bh, *Bl;
        int ka, k0;
        if (s < S1) { Ah = A1h; Al = A1l; Bh = B1h; Bl = B1l; ka = K1; k0 = s * 32; }
        else        { Ah = A2h; Al = A2l; Bh = B2h; Bl = B2l; ka = K2; k0 = (s - S1) * 32; }
        unsigned b = sbase + buf * (STG * 4) + prow * (AW * 4) + pch * 16;
        size_t aoff = (size_t)(row0 + prow) * ka + k0 + pch * 8;
        size_t boff = (size_t)(col0 + prow) * ka + k0 + pch * 8;
        cp16(b,               Ah + aoff);
        cp16(b + ASZ * 4,     Al + aoff);
        cp16(b + 2 * ASZ * 4, Bh + boff);
        cp16(b + 3 * ASZ * 4, Bl + boff);
        asm volatile("cp.async.commit_group;" ::: "memory");
    };

    auto compute = [&](int buf) {
        const unsigned* Ah = sm + buf * STG;
        const unsigned* Al = Ah + ASZ;
        const unsigned* Bh = Ah + 2 * ASZ;
        const unsigned* Bl = Ah + 3 * ASZ;
#pragma unroll
        for (int ks = 0; ks < 2; ks++) {
            int kb = ks * 8;
            unsigned ah[2][4], al[2][4];
#pragma unroll
            for (int mi = 0; mi < 2; mi++) {
                int rb = wm * 32 + mi * 16;
                int i0 = (rb + g) * AW + kb + t;
                int i1 = (rb + g + 8) * AW + kb + t;
                ah[mi][0] = Ah[i0];     al[mi][0] = Al[i0];
                ah[mi][1] = Ah[i1];     al[mi][1] = Al[i1];
                ah[mi][2] = Ah[i0 + 4]; al[mi][2] = Al[i0 + 4];
                ah[mi][3] = Ah[i1 + 4]; al[mi][3] = Al[i1 + 4];
            }
            unsigned bh[4][2], blo[4][2];
#pragma unroll
            for (int ni = 0; ni < 4; ni++) {
                int cb = (wn * 32 + ni * 8 + g) * AW + kb + t;
                bh[ni][0] = Bh[cb];     blo[ni][0] = Bl[cb];
                bh[ni][1] = Bh[cb + 4]; blo[ni][1] = Bl[cb + 4];
            }
#pragma unroll
            for (int mi = 0; mi < 2; mi++)
#pragma unroll
                for (int ni = 0; ni < 4; ni++) {
                    float* c = acc[mi][ni];
                    mma_bf16(c, ah[mi][0], ah[mi][1], ah[mi][2], ah[mi][3], bh[ni][0], bh[ni][1]);
                    mma_bf16(c, ah[mi][0], ah[mi][1], ah[mi][2], ah[mi][3], blo[ni][0], blo[ni][1]);
                    mma_bf16(c, al[mi][0], al[mi][1], al[mi][2], al[mi][3], bh[ni][0], bh[ni][1]);
                }
        }
    };

    // 3-stage pipeline
    prefetch(0, 0);
    if (S > 1) prefetch(1, 1);
#pragma unroll 1
    for (int s = 0; s < S; s++) {
        if (s + 1 < S) { asm volatile("cp.async.wait_group 1;" ::: "memory"); }
        else           { asm volatile("cp.async.wait_group 0;" ::: "memory"); }
        __syncthreads();
        if (s + 2 < S) prefetch(s + 2, (s + 2) % 3);
        compute(s % 3);
    }

    if (doStat) __syncthreads();  // s_sum/s_sq init visible; compute done

    // epilogue: store + fused BN stats
    float colS[4][2], colQ[4][2];
#pragma unroll
    for (int ni = 0; ni < 4; ni++) {
        colS[ni][0] = colS[ni][1] = 0.f;
        colQ[ni][0] = colQ[ni][1] = 0.f;
    }
#pragma unroll
    for (int mi = 0; mi < 2; mi++) {
        int ra = row0 + wm * 32 + mi * 16 + g;
        int rb = ra + 8;
        bool va = ra < NN, vb = rb < NN;
#pragma unroll
        for (int ni = 0; ni < 4; ni++) {
            int col = col0 + wn * 32 + ni * 8 + t * 2;
            float* c = acc[mi][ni];
            if (col < N) {
                float b0 = __ldg(&bias[col]);
                float v0 = c[0] + b0, v2 = c[2] + b0;
                if (va) { C[(size_t)ra * N + col] = v0; colS[ni][0] += v0; colQ[ni][0] += v0 * v0; }
                if (vb) { C[(size_t)rb * N + col] = v2; colS[ni][0] += v2; colQ[ni][0] += v2 * v2; }
            }
            if (col + 1 < N) {
                float b1 = __ldg(&bias[col + 1]);
                float v1 = c[1] + b1, v3 = c[3] + b1;
                if (va) { C[(size_t)ra * N + col + 1] = v1; colS[ni][1] += v1; colQ[ni][1] += v1 * v1; }
                if (vb) { C[(size_t)rb * N + col + 1] = v3; colS[ni][1] += v3; colQ[ni][1] += v3 * v3; }
            }
        }
    }

    if (doStat) {
        // reduce across g (lanes differing by 4, 8, 16 share columns)
#pragma unroll
        for (int ni = 0; ni < 4; ni++)
#pragma unroll
            for (int p = 0; p < 2; p++) {
#pragma unroll
                for (int off = 4; off < 32; off <<= 1) {
                    colS[ni][p] += __shfl_xor_sync(0xFFFFFFFF, colS[ni][p], off);
                    colQ[ni][p] += __shfl_xor_sync(0xFFFFFFFF, colQ[ni][p], off);
                }
            }
        if (g == 0) {  // lanes 0..3 hold warp sums
#pragma unroll
            for (int ni = 0; ni < 4; ni++) {
                int ci = wn * 32 + ni * 8 + t * 2;
                atomicAdd(&s_sum[ci], colS[ni][0]);
                atomicAdd(&s_sq[ci], colQ[ni][0]);
                atomicAdd(&s_sum[ci + 1], colS[ni][1]);
                atomicAdd(&s_sq[ci + 1], colQ[ni][1]);
            }
        }
        __syncthreads();
        if (tid < 128) {
            atomicAdd(&g_colsum[col0 + tid], s_sum[tid]);
            atomicAdd(&g_colsq[col0 + tid], s_sq[tid]);
        }
    }
}

// ---------------- batch norm finalize / apply ----------------
__global__ void zero_stats_k() {
    int i = threadIdx.x + blockIdx.x * blockDim.x;
    if (i < HID) { g_colsum[i] = 0.f; g_colsq[i] = 0.f; }
}
__global__ void bnfin_k(const float* __restrict__ gamma, const float* __restrict__ beta) {
    int j = blockIdx.x * blockDim.x + threadIdx.x;
    if (j >= HID) return;
    float mean = g_colsum[j] * (1.0f / NN);
    float var = g_colsq[j] * (1.0f / NN) - mean * mean;
    float rstd = rsqrtf(var + EPSF);
    float sc = rstd * gamma[j];
    g_scale[j] = sc;
    g_shift[j] = beta[j] - mean * sc;
}
__global__ void bnapply_plane_k() {
    size_t idx = (size_t)blockIdx.x * blockDim.x + threadIdx.x;
    if (idx >= (size_t)NN * HID) return;
    int c = (int)(idx & (HID - 1));
    float v = fmaxf(g_h[idx] * g_scale[c] + g_shift[c], 0.f);
    __nv_bfloat16 hi, lo;
    split1(v, hi, lo);
    g_hbh[idx] = hi;
    g_hbl[idx] = lo;
}

// ---------------- host ----------------
static inline int cdiv(long long a, int b) { return (int)((a + b - 1) / b); }

extern "C" void kernel_launch(void* const* d_in, const int* in_sizes, int n_in,
                              void* d_out, int out_size) {
    const float* x = (const float*)d_in[0];
    const void* ei = d_in[1];

    const float* Wl[4] = {(const float*)d_in[2], (const float*)d_in[5],
                          (const float*)d_in[8], (const float*)d_in[11]};
    const float* bl[4] = {(const float*)d_in[3], (const float*)d_in[6],
                          (const float*)d_in[9], (const float*)d_in[12]};
    const float* Wr[4] = {(const float*)d_in[4], (const float*)d_in[7],
                          (const float*)d_in[10], (const float*)d_in[13]};
    const float* gam[3] = {(const float*)d_in[14], (const float*)d_in[16], (const float*)d_in[18]};
    const float* bet[3] = {(const float*)d_in[15], (const float*)d_in[17], (const float*)d_in[19]};
    float* out = (float*)d_out;

    cudaFuncSetAttribute(gemm_k, cudaFuncAttributeMaxDynamicSharedMemorySize, GEMM_SMEM);

    // edge indices + CSR
    init_flags_k<<<1, 32>>>();
    detect_idx_k<<<128, 1024>>>((const long long*)ei);
    convert_idx_k<<<cdiv(NE, 256), 256>>>(ei);
    zero_cnt_k<<<cdiv(NN, 256), 256>>>();
    count_k<<<cdiv(NE, 256), 256>>>();
    scan1_k<<<NSB, 1024>>>();
    scan2_k<<<1, 64>>>();
    scan3_k<<<cdiv(NN, 256), 256>>>();
    fill_k<<<cdiv(NE, 256), 256>>>();

    // weight + x planes
    wsplit_k<<<cdiv(512 * 64, 256), 256>>>(Wl[0], INF, HID, 64, 512, OFF_WL1);
    wsplit_k<<<cdiv(512 * 64, 256), 256>>>(Wr[0], INF, HID, 64, 512, OFF_WR1);
    wsplit_k<<<cdiv(512 * 512, 256), 256>>>(Wl[1], HID, HID, 512, 512, OFF_WL2);
    wsplit_k<<<cdiv(512 * 512, 256), 256>>>(Wr[1], HID, HID, 512, 512, OFF_WR2);
    wsplit_k<<<cdiv(512 * 512, 256), 256>>>(Wl[2], HID, HID, 512, 512, OFF_WL3);
    wsplit_k<<<cdiv(512 * 512, 256), 256>>>(Wr[2], HID, HID, 512, 512, OFF_WR3);
    wsplit_k<<<cdiv(128 * 512, 256), 256>>>(Wl[3], HID, OUTF, 512, 128, OFF_WL4);
    wsplit_k<<<cdiv(128 * 512, 256), 256>>>(Wr[3], HID, OUTF, 512, 128, OFF_WR4);
    xsplit_k<<<cdiv(NN * 64, 256), 256>>>(x);

    dim3 gfull(4, cdiv(NNP, 128));

    // ---- layer 1 ----
    gather50_k<<<NN, 64>>>(x);
    zero_stats_k<<<2, 256>>>();
    gemm_k<<<gfull, 512, GEMM_SMEM>>>(0, 64, 64, OFF_WL1, OFF_WR1, bl[0], HID, 1, nullptr, 1);
    bnfin_k<<<2, 256>>>(gam[0], bet[0]);
    bnapply_plane_k<<<cdiv((long long)NN * HID, 256), 256>>>();

    // ---- layers 2 & 3 ----
    for (int L = 1; L <= 2; ++L) {
        int wl = (L == 1) ? OFF_WL2 : OFF_WL3;
        int wr = (L == 1) ? OFF_WR2 : OFF_WR3;
        gather512_k<<<NN, 128>>>();
        zero_stats_k<<<2, 256>>>();
        gemm_k<<<gfull, 512, GEMM_SMEM>>>(1, 512, 512, wl, wr, bl[L], HID, 1, nullptr, 1);
        bnfin_k<<<2, 256>>>(gam[L], bet[L]);
        bnapply_plane_k<<<cdiv((long long)NN * HID, 256), 256>>>();
    }

    // ---- layer 4 -> d_out ----
    gather512_k<<<NN, 128>>>();
    gemm_k<<<dim3(1, cdiv(NNP, 128)), 512, GEMM_SMEM>>>(1, 512, 512, OFF_WL4, OFF_WR4,
                                                        bl[3], OUTF, 0, out, 0);
}

// round 10
// speedup vs baseline: 3.5617x; 1.0135x over previous
#include <cuda_runtime.h>
#include <cuda_bf16.h>

#define NN   50000
#define NNP  50048
#define NE   400000
#define INF  50
#define HID  512
#define OUTF 121
#define EPSF 1e-5f
#define NSB  49

// ---------------- device scratch ----------------
__device__ float g_invdeg[NN];
__device__ float g_h[(size_t)NNP * HID];
__device__ __nv_bfloat16 g_aggh[(size_t)NNP * HID];
__device__ __nv_bfloat16 g_aggl[(size_t)NNP * HID];
__device__ __nv_bfloat16 g_hbh[(size_t)NNP * HID];
__device__ __nv_bfloat16 g_hbl[(size_t)NNP * HID];
__device__ __nv_bfloat16 g_xh[(size_t)NNP * 64];
__device__ __nv_bfloat16 g_xl[(size_t)NNP * 64];
__device__ __nv_bfloat16 g_a1h[(size_t)NNP * 64];
__device__ __nv_bfloat16 g_a1l[(size_t)NNP * 64];

#define OFF_WL1 0
#define OFF_WR1 32768
#define OFF_WL2 65536
#define OFF_WR2 327680
#define OFF_WL3 589824
#define OFF_WR3 851968
#define OFF_WL4 1114112
#define OFF_WR4 1179648
#define WTOT    1245184
__device__ __nv_bfloat16 g_wh[WTOT];
__device__ __nv_bfloat16 g_wl[WTOT];

__device__ float g_colsum[HID], g_colsq[HID], g_scale[HID], g_shift[HID];
__device__ int g_src[NE], g_dst[NE], g_csrc[NE];
__device__ int g_rowptr[NN + 1], g_cnt[NN], g_cursor[NN], g_is64;
__device__ int g_blksum[64], g_blkoff[64];

// ---------------- helpers ----------------
__device__ __forceinline__ unsigned s2u(const void* p) {
    unsigned a;
    asm("{ .reg .u64 t; cvta.to.shared.u64 t, %1; cvt.u32.u64 %0, t; }" : "=r"(a) : "l"(p));
    return a;
}
__device__ __forceinline__ void cp16(unsigned dst, const void* src) {
    asm volatile("cp.async.cg.shared.global [%0], [%1], 16;" :: "r"(dst), "l"(src));
}
__device__ __forceinline__ void split1(float v, __nv_bfloat16& hi, __nv_bfloat16& lo) {
    hi = __float2bfloat16(v);
    lo = __float2bfloat16(v - __bfloat162float(hi));
}
__device__ __forceinline__ void mma_bf16(float* c,
                                         unsigned a0, unsigned a1, unsigned a2, unsigned a3,
                                         unsigned b0, unsigned b1) {
    asm volatile(
        "mma.sync.aligned.m16n8k16.row.col.f32.bf16.bf16.f32 "
        "{%0,%1,%2,%3},{%4,%5,%6,%7},{%8,%9},{%0,%1,%2,%3};"
        : "+f"(c[0]), "+f"(c[1]), "+f"(c[2]), "+f"(c[3])
        : "r"(a0), "r"(a1), "r"(a2), "r"(a3), "r"(b0), "r"(b1));
}

// ---------------- edge index detection + conversion ----------------
__global__ void init_flags_k() {
    if (threadIdx.x == 0 && blockIdx.x == 0) g_is64 = 1;
}
__global__ void detect_idx_k(const long long* __restrict__ ei) {
    int stride = gridDim.x * blockDim.x;
    int bad = 0;
    for (int i = blockIdx.x * blockDim.x + threadIdx.x; i < NE; i += stride) {
        long long v = ei[i];
        if (v < 0 || v >= NN) { bad = 1; break; }
    }
    if (__syncthreads_or(bad)) {
        if (threadIdx.x == 0) atomicExch(&g_is64, 0);
    }
}
__global__ void convert_idx_k(const void* __restrict__ ei) {
    int e = blockIdx.x * blockDim.x + threadIdx.x;
    if (e >= NE) return;
    int s, d;
    if (g_is64) {
        const long long* p = (const long long*)ei;
        s = (int)p[e]; d = (int)p[e + NE];
    } else {
        const int* p = (const int*)ei;
        s = p[e]; d = p[e + NE];
    }
    g_src[e] = min(max(s, 0), NN - 1);
    g_dst[e] = min(max(d, 0), NN - 1);
}

// ---------------- CSR build ----------------
__global__ void zero_cnt_k() {
    int i = blockIdx.x * blockDim.x + threadIdx.x;
    if (i < NN) g_cnt[i] = 0;
}
__global__ void count_k() {
    int e = blockIdx.x * blockDim.x + threadIdx.x;
    if (e < NE) atomicAdd(&g_cnt[g_dst[e]], 1);
}
__global__ void scan1_k() {
    __shared__ int sh[1024];
    int tid = threadIdx.x;
    int i = blockIdx.x * 1024 + tid;
    int v = (i < NN) ? g_cnt[i] : 0;
    sh[tid] = v;
    __syncthreads();
#pragma unroll
    for (int off = 1; off < 1024; off <<= 1) {
        int x = (tid >= off) ? sh[tid - off] : 0;
        __syncthreads();
        sh[tid] += x;
        __syncthreads();
    }
    if (i < NN) g_rowptr[i] = sh[tid] - v;
    if (tid == 1023) g_blksum[blockIdx.x] = sh[1023];
}
__global__ void scan2_k() {
    __shared__ int sh[64];
    int t = threadIdx.x;
    int v = (t < NSB) ? g_blksum[t] : 0;
    sh[t] = v;
    __syncthreads();
#pragma unroll
    for (int off = 1; off < 64; off <<= 1) {
        int x = (t >= off) ? sh[t - off] : 0;
        __syncthreads();
        sh[t] += x;
        __syncthreads();
    }
    if (t < 64) g_blkoff[t] = sh[t] - v;
}
__global__ void scan3_k() {
    int i = blockIdx.x * blockDim.x + threadIdx.x;
    if (i >= NN) return;
    g_rowptr[i] += g_blkoff[i >> 10];
    g_cursor[i] = 0;
    g_invdeg[i] = 1.0f / (float)max(g_cnt[i], 1);
    if (i == 0) g_rowptr[NN] = g_blkoff[NSB - 1] + g_blksum[NSB - 1];
}
__global__ void fill_k() {
    int e = blockIdx.x * blockDim.x + threadIdx.x;
    if (e >= NE) return;
    int d = g_dst[e];
    int slot = g_rowptr[d] + atomicAdd(&g_cursor[d], 1);
    g_csrc[slot] = g_src[e];
}

// ---------------- plane preparation ----------------
__global__ void wsplit_k(const float* __restrict__ W, int K, int N, int Kpad, int Npad, int off) {
    int idx = blockIdx.x * blockDim.x + threadIdx.x;
    if (idx >= Npad * Kpad) return;
    int n = idx / Kpad, k = idx - n * Kpad;
    float v = (n < N && k < K) ? W[(size_t)k * N + n] : 0.f;
    __nv_bfloat16 hi, lo;
    split1(v, hi, lo);
    g_wh[off + idx] = hi;
    g_wl[off + idx] = lo;
}
__global__ void xsplit_k(const float* __restrict__ x) {
    int idx = blockIdx.x * blockDim.x + threadIdx.x;
    if (idx >= NN * 64) return;
    int n = idx >> 6, c = idx & 63;
    float v = (c < INF) ? x[(size_t)n * INF + c] : 0.f;
    __nv_bfloat16 hi, lo;
    split1(v, hi, lo);
    g_xh[idx] = hi;
    g_xl[idx] = lo;
}

// ---------------- gathers (CSR mean) ----------------
__global__ void gather50_k(const float* __restrict__ x) {
    int node = blockIdx.x;
    int t = threadIdx.x;
    float acc = 0.f;
    if (t < INF) {
        int beg = g_rowptr[node], end = g_rowptr[node + 1];
        for (int e = beg; e < end; ++e) acc += x[(size_t)g_csrc[e] * INF + t];
        acc *= g_invdeg[node];
    }
    __nv_bfloat16 hi, lo;
    split1(acc, hi, lo);
    g_a1h[(size_t)node * 64 + t] = hi;
    g_a1l[(size_t)node * 64 + t] = lo;
}

// gather from fp32 g_h with inline BN (scale/shift) + ReLU; full fp32 precision.
__global__ void gather512_k() {
    int node = blockIdx.x;
    int tid = threadIdx.x;
    size_t coff = (size_t)tid * 4;
    float4 sc = *(const float4*)(g_scale + coff);
    float4 sh = *(const float4*)(g_shift + coff);
    int beg = g_rowptr[node], end = g_rowptr[node + 1];
    float a0 = 0.f, a1 = 0.f, a2 = 0.f, a3 = 0.f;
    int e = beg;
    for (; e + 1 < end; e += 2) {
        float4 v0 = *(const float4*)(g_h + (size_t)g_csrc[e] * HID + coff);
        float4 v1 = *(const float4*)(g_h + (size_t)g_csrc[e + 1] * HID + coff);
        a0 += fmaxf(fmaf(v0.x, sc.x, sh.x), 0.f) + fmaxf(fmaf(v1.x, sc.x, sh.x), 0.f);
        a1 += fmaxf(fmaf(v0.y, sc.y, sh.y), 0.f) + fmaxf(fmaf(v1.y, sc.y, sh.y), 0.f);
        a2 += fmaxf(fmaf(v0.z, sc.z, sh.z), 0.f) + fmaxf(fmaf(v1.z, sc.z, sh.z), 0.f);
        a3 += fmaxf(fmaf(v0.w, sc.w, sh.w), 0.f) + fmaxf(fmaf(v1.w, sc.w, sh.w), 0.f);
    }
    if (e < end) {
        float4 v0 = *(const float4*)(g_h + (size_t)g_csrc[e] * HID + coff);
        a0 += fmaxf(fmaf(v0.x, sc.x, sh.x), 0.f);
        a1 += fmaxf(fmaf(v0.y, sc.y, sh.y), 0.f);
        a2 += fmaxf(fmaf(v0.z, sc.z, sh.z), 0.f);
        a3 += fmaxf(fmaf(v0.w, sc.w, sh.w), 0.f);
    }
    float inv = g_invdeg[node];
    a0 *= inv; a1 *= inv; a2 *= inv; a3 *= inv;
    __nv_bfloat16 h0, l0, h1, l1, h2, l2, h3, l3;
    split1(a0, h0, l0); split1(a1, h1, l1); split1(a2, h2, l2); split1(a3, h3, l3);
    size_t o = (size_t)node * HID + coff;
    *(ushort4*)(g_aggh + o) = make_ushort4(__bfloat16_as_ushort(h0), __bfloat16_as_ushort(h1),
                                           __bfloat16_as_ushort(h2), __bfloat16_as_ushort(h3));
    *(ushort4*)(g_aggl + o) = make_ushort4(__bfloat16_as_ushort(l0), __bfloat16_as_ushort(l1),
                                           __bfloat16_as_ushort(l2), __bfloat16_as_ushort(l3));
}

// ---------------- dual GEMM with fused BN-stat epilogue ----------------
#define AW 20
#define ASZ (128 * AW)
#define STG (4 * ASZ)
#define GEMM_SMEM (3 * STG * 4)

__global__ void __launch_bounds__(512, 1)
gemm_k(int aSel, int K1, int K2, int woff1, int woff2,
       const float* __restrict__ bias, int N, int cSel, float* __restrict__ cExt,
       int doStat) {
    extern __shared__ unsigned sm[];
    unsigned sbase = s2u(sm);
    __shared__ float s_sum[128], s_sq[128];

    const __nv_bfloat16 *A1h, *A1l, *A2h, *A2l;
    if (aSel == 0) { A1h = g_a1h; A1l = g_a1l; A2h = g_xh; A2l = g_xl; }
    else           { A1h = g_aggh; A1l = g_aggl; A2h = g_hbh; A2l = g_hbl; }
    const __nv_bfloat16* B1h = g_wh + woff1;
    const __nv_bfloat16* B1l = g_wl + woff1;
    const __nv_bfloat16* B2h = g_wh + woff2;
    const __nv_bfloat16* B2l = g_wl + woff2;
    float* C = (cSel == 1) ? g_h : cExt;

    int tid = threadIdx.x;
    int warp = tid >> 5, lane = tid & 31;
    int wm = warp & 3, wn = warp >> 2;
    int g = lane >> 2, t = lane & 3;
    int row0 = blockIdx.y * 128;
    int col0 = blockIdx.x * 128;

    int S1 = K1 >> 5, S2 = K2 >> 5, S = S1 + S2;

    float acc[2][4][4];
#pragma unroll
    for (int mi = 0; mi < 2; mi++)
#pragma unroll
        for (int ni = 0; ni < 4; ni++)
#pragma unroll
            for (int r = 0; r < 4; r++) acc[mi][ni][r] = 0.f;

    if (doStat && tid < 128) { s_sum[tid] = 0.f; s_sq[tid] = 0.f; }

    int prow = tid >> 2, pch = tid & 3;

    auto prefetch = [&](int s, int buf) {
        const __nv_bfloat16 *Ah, *Al, *Bh, *Bl;
        int ka, k0;
        if (s < S1) { Ah = A1h; Al = A1l; Bh = B1h; Bl = B1l; ka = K1; k0 = s * 32; }
        else        { Ah = A2h; Al = A2l; Bh = B2h; Bl = B2l; ka = K2; k0 = (s - S1) * 32; }
        unsigned b = sbase + buf * (STG * 4) + prow * (AW * 4) + pch * 16;
        size_t aoff = (size_t)(row0 + prow) * ka + k0 + pch * 8;
        size_t boff = (size_t)(col0 + prow) * ka + k0 + pch * 8;
        cp16(b,               Ah + aoff);
        cp16(b + ASZ * 4,     Al + aoff);
        cp16(b + 2 * ASZ * 4, Bh + boff);
        cp16(b + 3 * ASZ * 4, Bl + boff);
        asm volatile("cp.async.commit_group;" ::: "memory");
    };

    auto compute = [&](int buf) {
        const unsigned* Ah = sm + buf * STG;
        const unsigned* Al = Ah + ASZ;
        const unsigned* Bh = Ah + 2 * ASZ;
        const unsigned* Bl = Ah + 3 * ASZ;
#pragma unroll
        for (int ks = 0; ks < 2; ks++) {
            int kb = ks * 8;
            unsigned ah[2][4], al[2][4];
#pragma unroll
            for (int mi = 0; mi < 2; mi++) {
                int rb = wm * 32 + mi * 16;
                int i0 = (rb + g) * AW + kb + t;
                int i1 = (rb + g + 8) * AW + kb + t;
                ah[mi][0] = Ah[i0];     al[mi][0] = Al[i0];
                ah[mi][1] = Ah[i1];     al[mi][1] = Al[i1];
                ah[mi][2] = Ah[i0 + 4]; al[mi][2] = Al[i0 + 4];
                ah[mi][3] = Ah[i1 + 4]; al[mi][3] = Al[i1 + 4];
            }
            unsigned bh[4][2], blo[4][2];
#pragma unroll
            for (int ni = 0; ni < 4; ni++) {
                int cb = (wn * 32 + ni * 8 + g) * AW + kb + t;
                bh[ni][0] = Bh[cb];     blo[ni][0] = Bl[cb];
                bh[ni][1] = Bh[cb + 4]; blo[ni][1] = Bl[cb + 4];
            }
#pragma unroll
            for (int mi = 0; mi < 2; mi++)
#pragma unroll
                for (int ni = 0; ni < 4; ni++) {
                    float* c = acc[mi][ni];
                    mma_bf16(c, ah[mi][0], ah[mi][1], ah[mi][2], ah[mi][3], bh[ni][0], bh[ni][1]);
                    mma_bf16(c, ah[mi][0], ah[mi][1], ah[mi][2], ah[mi][3], blo[ni][0], blo[ni][1]);
                    mma_bf16(c, al[mi][0], al[mi][1], al[mi][2], al[mi][3], bh[ni][0], bh[ni][1]);
                }
        }
    };

    prefetch(0, 0);
    if (S > 1) prefetch(1, 1);
#pragma unroll 1
    for (int s = 0; s < S; s++) {
        if (s + 1 < S) { asm volatile("cp.async.wait_group 1;" ::: "memory"); }
        else           { asm volatile("cp.async.wait_group 0;" ::: "memory"); }
        __syncthreads();
        if (s + 2 < S) prefetch(s + 2, (s + 2) % 3);
        compute(s % 3);
    }

    if (doStat) __syncthreads();

    float colS[4][2], colQ[4][2];
#pragma unroll
    for (int ni = 0; ni < 4; ni++) {
        colS[ni][0] = colS[ni][1] = 0.f;
        colQ[ni][0] = colQ[ni][1] = 0.f;
    }
#pragma unroll
    for (int mi = 0; mi < 2; mi++) {
        int ra = row0 + wm * 32 + mi * 16 + g;
        int rb = ra + 8;
        bool va = ra < NN, vb = rb < NN;
#pragma unroll
        for (int ni = 0; ni < 4; ni++) {
            int col = col0 + wn * 32 + ni * 8 + t * 2;
            float* c = acc[mi][ni];
            if (col < N) {
                float b0 = __ldg(&bias[col]);
                float v0 = c[0] + b0, v2 = c[2] + b0;
                if (va) { C[(size_t)ra * N + col] = v0; colS[ni][0] += v0; colQ[ni][0] += v0 * v0; }
                if (vb) { C[(size_t)rb * N + col] = v2; colS[ni][0] += v2; colQ[ni][0] += v2 * v2; }
            }
            if (col + 1 < N) {
                float b1 = __ldg(&bias[col + 1]);
                float v1 = c[1] + b1, v3 = c[3] + b1;
                if (va) { C[(size_t)ra * N + col + 1] = v1; colS[ni][1] += v1; colQ[ni][1] += v1 * v1; }
                if (vb) { C[(size_t)rb * N + col + 1] = v3; colS[ni][1] += v3; colQ[ni][1] += v3 * v3; }
            }
        }
    }

    if (doStat) {
#pragma unroll
        for (int ni = 0; ni < 4; ni++)
#pragma unroll
            for (int p = 0; p < 2; p++) {
#pragma unroll
                for (int off = 4; off < 32; off <<= 1) {
                    colS[ni][p] += __shfl_xor_sync(0xFFFFFFFF, colS[ni][p], off);
                    colQ[ni][p] += __shfl_xor_sync(0xFFFFFFFF, colQ[ni][p], off);
                }
            }
        if (g == 0) {
#pragma unroll
            for (int ni = 0; ni < 4; ni++) {
                int ci = wn * 32 + ni * 8 + t * 2;
                atomicAdd(&s_sum[ci], colS[ni][0]);
                atomicAdd(&s_sq[ci], colQ[ni][0]);
                atomicAdd(&s_sum[ci + 1], colS[ni][1]);
                atomicAdd(&s_sq[ci + 1], colQ[ni][1]);
            }
        }
        __syncthreads();
        if (tid < 128) {
            atomicAdd(&g_colsum[col0 + tid], s_sum[tid]);
            atomicAdd(&g_colsq[col0 + tid], s_sq[tid]);
        }
    }
}

// ---------------- batch norm finalize / apply ----------------
__global__ void zero_stats_k() {
    int i = threadIdx.x + blockIdx.x * blockDim.x;
    if (i < HID) { g_colsum[i] = 0.f; g_colsq[i] = 0.f; }
}
__global__ void bnfin_k(const float* __restrict__ gamma, const float* __restrict__ beta) {
    int j = blockIdx.x * blockDim.x + threadIdx.x;
    if (j >= HID) return;
    float mean = g_colsum[j] * (1.0f / NN);
    float var = g_colsq[j] * (1.0f / NN) - mean * mean;
    float rstd = rsqrtf(var + EPSF);
    float sc = rstd * gamma[j];
    g_scale[j] = sc;
    g_shift[j] = beta[j] - mean * sc;
    g_colsum[j] = 0.f;
    g_colsq[j] = 0.f;
}
__global__ void bnapply_plane_k() {
    size_t idx = (size_t)blockIdx.x * blockDim.x + threadIdx.x;
    if (idx >= (size_t)NN * HID) return;
    int c = (int)(idx & (HID - 1));
    float v = fmaxf(g_h[idx] * g_scale[c] + g_shift[c], 0.f);
    __nv_bfloat16 hi, lo;
    split1(v, hi, lo);
    g_hbh[idx] = hi;
    g_hbl[idx] = lo;
}

// ---------------- host ----------------
static inline int cdiv(long long a, int b) { return (int)((a + b - 1) / b); }

extern "C" void kernel_launch(void* const* d_in, const int* in_sizes, int n_in,
                              void* d_out, int out_size) {
    const float* x = (const float*)d_in[0];
    const void* ei = d_in[1];

    const float* Wl[4] = {(const float*)d_in[2], (const float*)d_in[5],
                          (const float*)d_in[8], (const float*)d_in[11]};
    const float* bl[4] = {(const float*)d_in[3], (const float*)d_in[6],
                          (const float*)d_in[9], (const float*)d_in[12]};
    const float* Wr[4] = {(const float*)d_in[4], (const float*)d_in[7],
                          (const float*)d_in[10], (const float*)d_in[13]};
    const float* gam[3] = {(const float*)d_in[14], (const float*)d_in[16], (const float*)d_in[18]};
    const float* bet[3] = {(const float*)d_in[15], (const float*)d_in[17], (const float*)d_in[19]};
    float* out = (float*)d_out;

    cudaFuncSetAttribute(gemm_k, cudaFuncAttributeMaxDynamicSharedMemorySize, GEMM_SMEM);

    // edge indices + CSR
    init_flags_k<<<1, 32>>>();
    detect_idx_k<<<128, 1024>>>((const long long*)ei);
    convert_idx_k<<<cdiv(NE, 256), 256>>>(ei);
    zero_cnt_k<<<cdiv(NN, 256), 256>>>();
    count_k<<<cdiv(NE, 256), 256>>>();
    scan1_k<<<NSB, 1024>>>();
    scan2_k<<<1, 64>>>();
    scan3_k<<<cdiv(NN, 256), 256>>>();
    fill_k<<<cdiv(NE, 256), 256>>>();

    // weight + x planes
    wsplit_k<<<cdiv(512 * 64, 256), 256>>>(Wl[0], INF, HID, 64, 512, OFF_WL1);
    wsplit_k<<<cdiv(512 * 64, 256), 256>>>(Wr[0], INF, HID, 64, 512, OFF_WR1);
    wsplit_k<<<cdiv(512 * 512, 256), 256>>>(Wl[1], HID, HID, 512, 512, OFF_WL2);
    wsplit_k<<<cdiv(512 * 512, 256), 256>>>(Wr[1], HID, HID, 512, 512, OFF_WR2);
    wsplit_k<<<cdiv(512 * 512, 256), 256>>>(Wl[2], HID, HID, 512, 512, OFF_WL3);
    wsplit_k<<<cdiv(512 * 512, 256), 256>>>(Wr[2], HID, HID, 512, 512, OFF_WR3);
    wsplit_k<<<cdiv(128 * 512, 256), 256>>>(Wl[3], HID, OUTF, 512, 128, OFF_WL4);
    wsplit_k<<<cdiv(128 * 512, 256), 256>>>(Wr[3], HID, OUTF, 512, 128, OFF_WR4);
    xsplit_k<<<cdiv(NN * 64, 256), 256>>>(x);

    dim3 gfull(4, cdiv(NNP, 128));

    // ---- layer 1 ----
    gather50_k<<<NN, 64>>>(x);
    zero_stats_k<<<2, 256>>>();
    gemm_k<<<gfull, 512, GEMM_SMEM>>>(0, 64, 64, OFF_WL1, OFF_WR1, bl[0], HID, 1, nullptr, 1);
    bnfin_k<<<2, 256>>>(gam[0], bet[0]);
    bnapply_plane_k<<<cdiv((long long)NN * HID, 256), 256>>>();

    // ---- layers 2 & 3 ----
    for (int L = 1; L <= 2; ++L) {
        int wl = (L == 1) ? OFF_WL2 : OFF_WL3;
        int wr = (L == 1) ? OFF_WR2 : OFF_WR3;
        gather512_k<<<NN, 128>>>();
        gemm_k<<<gfull, 512, GEMM_SMEM>>>(1, 512, 512, wl, wr, bl[L], HID, 1, nullptr, 1);
        bnfin_k<<<2, 256>>>(gam[L], bet[L]);
        bnapply_plane_k<<<cdiv((long long)NN * HID, 256), 256>>>();
    }

    // ---- layer 4 -> d_out ----
    gather512_k<<<NN, 128>>>();
    gemm_k<<<dim3(1, cdiv(NNP, 128)), 512, GEMM_SMEM>>>(1, 512, 512, OFF_WL4, OFF_WR4,
                                                        bl[3], OUTF, 0, out, 0);
}

// round 11
// speedup vs baseline: 3.6601x; 1.0276x over previous
#include <cuda_runtime.h>
#include <cuda_bf16.h>

#define NN   50000
#define NNP  50048
#define NE   400000
#define INF  50
#define HID  512
#define OUTF 121
#define EPSF 1e-5f
#define NSB  49

// ---------------- device scratch ----------------
__device__ float g_invdeg[NN];
__device__ float g_h[(size_t)NNP * HID];
__device__ __nv_bfloat16 g_aggh[(size_t)NNP * HID];
__device__ __nv_bfloat16 g_aggl[(size_t)NNP * HID];
__device__ __nv_bfloat16 g_hbh[(size_t)NNP * HID];
__device__ __nv_bfloat16 g_hbl[(size_t)NNP * HID];
__device__ __nv_bfloat16 g_xh[(size_t)NNP * 64];
__device__ __nv_bfloat16 g_xl[(size_t)NNP * 64];
__device__ __nv_bfloat16 g_a1h[(size_t)NNP * 64];
__device__ __nv_bfloat16 g_a1l[(size_t)NNP * 64];

#define OFF_WL1 0
#define OFF_WR1 32768
#define OFF_WL2 65536
#define OFF_WR2 327680
#define OFF_WL3 589824
#define OFF_WR3 851968
#define OFF_WL4 1114112
#define OFF_WR4 1179648
#define WTOT    1245184
__device__ __nv_bfloat16 g_wh[WTOT];
__device__ __nv_bfloat16 g_wl[WTOT];

__device__ float g_colsum[HID], g_colsq[HID], g_scale[HID], g_shift[HID];
__device__ int g_src[NE], g_dst[NE], g_csrc[NE];
__device__ int g_rowptr[NN + 1], g_cnt[NN], g_cursor[NN], g_is64;
__device__ int g_blksum[64], g_blkoff[64];

// ---------------- helpers ----------------
__device__ __forceinline__ unsigned s2u(const void* p) {
    unsigned a;
    asm("{ .reg .u64 t; cvta.to.shared.u64 t, %1; cvt.u32.u64 %0, t; }" : "=r"(a) : "l"(p));
    return a;
}
__device__ __forceinline__ void cp16(unsigned dst, const void* src) {
    asm volatile("cp.async.cg.shared.global [%0], [%1], 16;" :: "r"(dst), "l"(src));
}
__device__ __forceinline__ void split1(float v, __nv_bfloat16& hi, __nv_bfloat16& lo) {
    hi = __float2bfloat16(v);
    lo = __float2bfloat16(v - __bfloat162float(hi));
}
__device__ __forceinline__ void mma_bf16(float* c,
                                         unsigned a0, unsigned a1, unsigned a2, unsigned a3,
                                         unsigned b0, unsigned b1) {
    asm volatile(
        "mma.sync.aligned.m16n8k16.row.col.f32.bf16.bf16.f32 "
        "{%0,%1,%2,%3},{%4,%5,%6,%7},{%8,%9},{%0,%1,%2,%3};"
        : "+f"(c[0]), "+f"(c[1]), "+f"(c[2]), "+f"(c[3])
        : "r"(a0), "r"(a1), "r"(a2), "r"(a3), "r"(b0), "r"(b1));
}

// ---------------- prep: flags + counter zero ----------------
__global__ void prep0_k() {
    int i = blockIdx.x * blockDim.x + threadIdx.x;
    if (i == 0) g_is64 = 1;
    if (i < NN) g_cnt[i] = 0;
}
__global__ void detect_idx_k(const long long* __restrict__ ei) {
    int stride = gridDim.x * blockDim.x;
    int bad = 0;
    for (int i = blockIdx.x * blockDim.x + threadIdx.x; i < NE; i += stride) {
        long long v = ei[i];
        if (v < 0 || v >= NN) { bad = 1; break; }
    }
    if (__syncthreads_or(bad)) {
        if (threadIdx.x == 0) atomicExch(&g_is64, 0);
    }
}
// convert + degree count in one pass
__global__ void convert_count_k(const void* __restrict__ ei) {
    int e = blockIdx.x * blockDim.x + threadIdx.x;
    if (e >= NE) return;
    int s, d;
    if (g_is64) {
        const long long* p = (const long long*)ei;
        s = (int)p[e]; d = (int)p[e + NE];
    } else {
        const int* p = (const int*)ei;
        s = p[e]; d = p[e + NE];
    }
    s = min(max(s, 0), NN - 1);
    d = min(max(d, 0), NN - 1);
    g_src[e] = s;
    g_dst[e] = d;
    atomicAdd(&g_cnt[d], 1);
}

// ---------------- CSR scan ----------------
__global__ void scan1_k() {
    __shared__ int sh[1024];
    int tid = threadIdx.x;
    int i = blockIdx.x * 1024 + tid;
    int v = (i < NN) ? g_cnt[i] : 0;
    sh[tid] = v;
    __syncthreads();
#pragma unroll
    for (int off = 1; off < 1024; off <<= 1) {
        int x = (tid >= off) ? sh[tid - off] : 0;
        __syncthreads();
        sh[tid] += x;
        __syncthreads();
    }
    if (i < NN) g_rowptr[i] = sh[tid] - v;
    if (tid == 1023) g_blksum[blockIdx.x] = sh[1023];
}
__global__ void scan2_k() {
    __shared__ int sh[64];
    int t = threadIdx.x;
    int v = (t < NSB) ? g_blksum[t] : 0;
    sh[t] = v;
    __syncthreads();
#pragma unroll
    for (int off = 1; off < 64; off <<= 1) {
        int x = (t >= off) ? sh[t - off] : 0;
        __syncthreads();
        sh[t] += x;
        __syncthreads();
    }
    if (t < 64) g_blkoff[t] = sh[t] - v;
}
__global__ void scan3_k() {
    int i = blockIdx.x * blockDim.x + threadIdx.x;
    if (i >= NN) return;
    g_rowptr[i] += g_blkoff[i >> 10];
    g_cursor[i] = 0;
    g_invdeg[i] = 1.0f / (float)max(g_cnt[i], 1);
    if (i == 0) g_rowptr[NN] = g_blkoff[NSB - 1] + g_blksum[NSB - 1];
}
__global__ void fill_k() {
    int e = blockIdx.x * blockDim.x + threadIdx.x;
    if (e >= NE) return;
    int d = g_dst[e];
    int slot = g_rowptr[d] + atomicAdd(&g_cursor[d], 1);
    g_csrc[slot] = g_src[e];
}

// ---------------- unified plane split (8 weights + x) ----------------
#define XTOT (NN * 64)
__global__ void split_all_k(const float* __restrict__ Wl1, const float* __restrict__ Wr1,
                            const float* __restrict__ Wl2, const float* __restrict__ Wr2,
                            const float* __restrict__ Wl3, const float* __restrict__ Wr3,
                            const float* __restrict__ Wl4, const float* __restrict__ Wr4,
                            const float* __restrict__ x) {
    int idx = blockIdx.x * blockDim.x + threadIdx.x;
    if (idx >= WTOT + XTOT) return;
    if (idx >= WTOT) {
        int i = idx - WTOT;
        int n = i >> 6, c = i & 63;
        float v = (c < INF) ? x[(size_t)n * INF + c] : 0.f;
        __nv_bfloat16 hi, lo;
        split1(v, hi, lo);
        g_xh[i] = hi;
        g_xl[i] = lo;
        return;
    }
    const float* W;
    int off, Kpad, K, N;
    if (idx < OFF_WL2) {
        Kpad = 64; K = INF; N = HID;
        if (idx < OFF_WR1) { W = Wl1; off = OFF_WL1; }
        else               { W = Wr1; off = OFF_WR1; }
    } else if (idx < OFF_WL4) {
        Kpad = 512; K = HID; N = HID;
        if (idx < OFF_WR2)      { W = Wl2; off = OFF_WL2; }
        else if (idx < OFF_WL3) { W = Wr2; off = OFF_WR2; }
        else if (idx < OFF_WR3) { W = Wl3; off = OFF_WL3; }
        else                    { W = Wr3; off = OFF_WR3; }
    } else {
        Kpad = 512; K = HID; N = OUTF;
        if (idx < OFF_WR4) { W = Wl4; off = OFF_WL4; }
        else               { W = Wr4; off = OFF_WR4; }
    }
    int local = idx - off;
    int n = local / Kpad, k = local - n * Kpad;
    float v = (n < N && k < K) ? W[(size_t)k * N + n] : 0.f;
    __nv_bfloat16 hi, lo;
    split1(v, hi, lo);
    g_wh[idx] = hi;
    g_wl[idx] = lo;
}

// ---------------- layer-1 gather ----------------
__global__ void gather50_k(const float* __restrict__ x) {
    int node = blockIdx.x;
    int t = threadIdx.x;
    float acc = 0.f;
    if (t < INF) {
        int beg = g_rowptr[node], end = g_rowptr[node + 1];
        for (int e = beg; e < end; ++e) acc += x[(size_t)g_csrc[e] * INF + t];
        acc *= g_invdeg[node];
    }
    __nv_bfloat16 hi, lo;
    split1(acc, hi, lo);
    g_a1h[(size_t)node * 64 + t] = hi;
    g_a1l[(size_t)node * 64 + t] = lo;
}

// ---------------- fused gather + BN-apply (2 nodes / 256-thread block) ----------------
// Per node: (a) own row -> relu(bn(h)) -> hb planes; (b) CSR mean of relu(bn(h[src])) -> agg planes.
__global__ void __launch_bounds__(256, 8) gather_bn_k() {
    int half = threadIdx.x >> 7;            // 0 or 1
    int tid = threadIdx.x & 127;
    int node = blockIdx.x * 2 + half;
    if (node >= NN) return;
    size_t coff = (size_t)tid * 4;
    float4 sc = *(const float4*)(g_scale + coff);
    float4 sh = *(const float4*)(g_shift + coff);

    // own row -> hb planes
    {
        float4 v = *(const float4*)(g_h + (size_t)node * HID + coff);
        float r0 = fmaxf(fmaf(v.x, sc.x, sh.x), 0.f);
        float r1 = fmaxf(fmaf(v.y, sc.y, sh.y), 0.f);
        float r2 = fmaxf(fmaf(v.z, sc.z, sh.z), 0.f);
        float r3 = fmaxf(fmaf(v.w, sc.w, sh.w), 0.f);
        __nv_bfloat16 h0, l0, h1, l1, h2, l2, h3, l3;
        split1(r0, h0, l0); split1(r1, h1, l1); split1(r2, h2, l2); split1(r3, h3, l3);
        size_t o = (size_t)node * HID + coff;
        *(ushort4*)(g_hbh + o) = make_ushort4(__bfloat16_as_ushort(h0), __bfloat16_as_ushort(h1),
                                              __bfloat16_as_ushort(h2), __bfloat16_as_ushort(h3));
        *(ushort4*)(g_hbl + o) = make_ushort4(__bfloat16_as_ushort(l0), __bfloat16_as_ushort(l1),
                                              __bfloat16_as_ushort(l2), __bfloat16_as_ushort(l3));
    }

    // gather with 4-edge unroll
    int beg = g_rowptr[node], end = g_rowptr[node + 1];
    float a0 = 0.f, a1 = 0.f, a2 = 0.f, a3 = 0.f;
    int e = beg;
    for (; e + 3 < end; e += 4) {
        int s0 = g_csrc[e], s1 = g_csrc[e + 1], s2 = g_csrc[e + 2], s3 = g_csrc[e + 3];
        float4 v0 = *(const float4*)(g_h + (size_t)s0 * HID + coff);
        float4 v1 = *(const float4*)(g_h + (size_t)s1 * HID + coff);
        float4 v2 = *(const float4*)(g_h + (size_t)s2 * HID + coff);
        float4 v3 = *(const float4*)(g_h + (size_t)s3 * HID + coff);
        a0 += fmaxf(fmaf(v0.x, sc.x, sh.x), 0.f) + fmaxf(fmaf(v1.x, sc.x, sh.x), 0.f)
            + fmaxf(fmaf(v2.x, sc.x, sh.x), 0.f) + fmaxf(fmaf(v3.x, sc.x, sh.x), 0.f);
        a1 += fmaxf(fmaf(v0.y, sc.y, sh.y), 0.f) + fmaxf(fmaf(v1.y, sc.y, sh.y), 0.f)
            + fmaxf(fmaf(v2.y, sc.y, sh.y), 0.f) + fmaxf(fmaf(v3.y, sc.y, sh.y), 0.f);
        a2 += fmaxf(fmaf(v0.z, sc.z, sh.z), 0.f) + fmaxf(fmaf(v1.z, sc.z, sh.z), 0.f)
            + fmaxf(fmaf(v2.z, sc.z, sh.z), 0.f) + fmaxf(fmaf(v3.z, sc.z, sh.z), 0.f);
        a3 += fmaxf(fmaf(v0.w, sc.w, sh.w), 0.f) + fmaxf(fmaf(v1.w, sc.w, sh.w), 0.f)
            + fmaxf(fmaf(v2.w, sc.w, sh.w), 0.f) + fmaxf(fmaf(v3.w, sc.w, sh.w), 0.f);
    }
    for (; e < end; ++e) {
        float4 v0 = *(const float4*)(g_h + (size_t)g_csrc[e] * HID + coff);
        a0 += fmaxf(fmaf(v0.x, sc.x, sh.x), 0.f);
        a1 += fmaxf(fmaf(v0.y, sc.y, sh.y), 0.f);
        a2 += fmaxf(fmaf(v0.z, sc.z, sh.z), 0.f);
        a3 += fmaxf(fmaf(v0.w, sc.w, sh.w), 0.f);
    }
    float inv = g_invdeg[node];
    a0 *= inv; a1 *= inv; a2 *= inv; a3 *= inv;
    __nv_bfloat16 h0, l0, h1, l1, h2, l2, h3, l3;
    split1(a0, h0, l0); split1(a1, h1, l1); split1(a2, h2, l2); split1(a3, h3, l3);
    size_t o = (size_t)node * HID + coff;
    *(ushort4*)(g_aggh + o) = make_ushort4(__bfloat16_as_ushort(h0), __bfloat16_as_ushort(h1),
                                           __bfloat16_as_ushort(h2), __bfloat16_as_ushort(h3));
    *(ushort4*)(g_aggl + o) = make_ushort4(__bfloat16_as_ushort(l0), __bfloat16_as_ushort(l1),
                                           __bfloat16_as_ushort(l2), __bfloat16_as_ushort(l3));
}

// ---------------- dual GEMM with fused BN-stat epilogue ----------------
#define AW 20
#define ASZ (128 * AW)
#define STG (4 * ASZ)
#define GEMM_SMEM (3 * STG * 4)

__global__ void __launch_bounds__(512, 1)
gemm_k(int aSel, int K1, int K2, int woff1, int woff2,
       const float* __restrict__ bias, int N, int cSel, float* __restrict__ cExt,
       int doStat) {
    extern __shared__ unsigned sm[];
    unsigned sbase = s2u(sm);
    __shared__ float s_sum[128], s_sq[128];

    const __nv_bfloat16 *A1h, *A1l, *A2h, *A2l;
    if (aSel == 0) { A1h = g_a1h; A1l = g_a1l; A2h = g_xh; A2l = g_xl; }
    else           { A1h = g_aggh; A1l = g_aggl; A2h = g_hbh; A2l = g_hbl; }
    const __nv_bfloat16* B1h = g_wh + woff1;
    const __nv_bfloat16* B1l = g_wl + woff1;
    const __nv_bfloat16* B2h = g_wh + woff2;
    const __nv_bfloat16* B2l = g_wl + woff2;
    float* C = (cSel == 1) ? g_h : cExt;

    int tid = threadIdx.x;
    int warp = tid >> 5, lane = tid & 31;
    int wm = warp & 3, wn = warp >> 2;
    int g = lane >> 2, t = lane & 3;
    int row0 = blockIdx.y * 128;
    int col0 = blockIdx.x * 128;

    int S1 = K1 >> 5, S2 = K2 >> 5, S = S1 + S2;

    float acc[2][4][4];
#pragma unroll
    for (int mi = 0; mi < 2; mi++)
#pragma unroll
        for (int ni = 0; ni < 4; ni++)
#pragma unroll
            for (int r = 0; r < 4; r++) acc[mi][ni][r] = 0.f;

    if (doStat && tid < 128) { s_sum[tid] = 0.f; s_sq[tid] = 0.f; }

    int prow = tid >> 2, pch = tid & 3;

    auto prefetch = [&](int s, int buf) {
        const __nv_bfloat16 *Ah, *Al, *Bh, *Bl;
        int ka, k0;
        if (s < S1) { Ah = A1h; Al = A1l; Bh = B1h; Bl = B1l; ka = K1; k0 = s * 32; }
        else        { Ah = A2h; Al = A2l; Bh = B2h; Bl = B2l; ka = K2; k0 = (s - S1) * 32; }
        unsigned b = sbase + buf * (STG * 4) + prow * (AW * 4) + pch * 16;
        size_t aoff = (size_t)(row0 + prow) * ka + k0 + pch * 8;
        size_t boff = (size_t)(col0 + prow) * ka + k0 + pch * 8;
        cp16(b,               Ah + aoff);
        cp16(b + ASZ * 4,     Al + aoff);
        cp16(b + 2 * ASZ * 4, Bh + boff);
        cp16(b + 3 * ASZ * 4, Bl + boff);
        asm volatile("cp.async.commit_group;" ::: "memory");
    };

    auto compute = [&](int buf) {
        const unsigned* Ah = sm + buf * STG;
        const unsigned* Al = Ah + ASZ;
        const unsigned* Bh = Ah + 2 * ASZ;
        const unsigned* Bl = Ah + 3 * ASZ;
#pragma unroll
        for (int ks = 0; ks < 2; ks++) {
            int kb = ks * 8;
            unsigned ah[2][4], al[2][4];
#pragma unroll
            for (int mi = 0; mi < 2; mi++) {
                int rb = wm * 32 + mi * 16;
                int i0 = (rb + g) * AW + kb + t;
                int i1 = (rb + g + 8) * AW + kb + t;
                ah[mi][0] = Ah[i0];     al[mi][0] = Al[i0];
                ah[mi][1] = Ah[i1];     al[mi][1] = Al[i1];
                ah[mi][2] = Ah[i0 + 4]; al[mi][2] = Al[i0 + 4];
                ah[mi][3] = Ah[i1 + 4]; al[mi][3] = Al[i1 + 4];
            }
            unsigned bh[4][2], blo[4][2];
#pragma unroll
            for (int ni = 0; ni < 4; ni++) {
                int cb = (wn * 32 + ni * 8 + g) * AW + kb + t;
                bh[ni][0] = Bh[cb];     blo[ni][0] = Bl[cb];
                bh[ni][1] = Bh[cb + 4]; blo[ni][1] = Bl[cb + 4];
            }
#pragma unroll
            for (int mi = 0; mi < 2; mi++)
#pragma unroll
                for (int ni = 0; ni < 4; ni++) {
                    float* c = acc[mi][ni];
                    mma_bf16(c, ah[mi][0], ah[mi][1], ah[mi][2], ah[mi][3], bh[ni][0], bh[ni][1]);
                    mma_bf16(c, ah[mi][0], ah[mi][1], ah[mi][2], ah[mi][3], blo[ni][0], blo[ni][1]);
                    mma_bf16(c, al[mi][0], al[mi][1], al[mi][2], al[mi][3], bh[ni][0], bh[ni][1]);
                }
        }
    };

    prefetch(0, 0);
    if (S > 1) prefetch(1, 1);
#pragma unroll 1
    for (int s = 0; s < S; s++) {
        if (s + 1 < S) { asm volatile("cp.async.wait_group 1;" ::: "memory"); }
        else           { asm volatile("cp.async.wait_group 0;" ::: "memory"); }
        __syncthreads();
        if (s + 2 < S) prefetch(s + 2, (s + 2) % 3);
        compute(s % 3);
    }

    if (doStat) __syncthreads();

    float colS[4][2], colQ[4][2];
#pragma unroll
    for (int ni = 0; ni < 4; ni++) {
        colS[ni][0] = colS[ni][1] = 0.f;
        colQ[ni][0] = colQ[ni][1] = 0.f;
    }
#pragma unroll
    for (int mi = 0; mi < 2; mi++) {
        int ra = row0 + wm * 32 + mi * 16 + g;
        int rb = ra + 8;
        bool va = ra < NN, vb = rb < NN;
#pragma unroll
        for (int ni = 0; ni < 4; ni++) {
            int col = col0 + wn * 32 + ni * 8 + t * 2;
            float* c = acc[mi][ni];
            if (col < N) {
                float b0 = __ldg(&bias[col]);
                float v0 = c[0] + b0, v2 = c[2] + b0;
                if (va) { C[(size_t)ra * N + col] = v0; colS[ni][0] += v0; colQ[ni][0] += v0 * v0; }
                if (vb) { C[(size_t)rb * N + col] = v2; colS[ni][0] += v2; colQ[ni][0] += v2 * v2; }
            }
            if (col + 1 < N) {
                float b1 = __ldg(&bias[col + 1]);
                float v1 = c[1] + b1, v3 = c[3] + b1;
                if (va) { C[(size_t)ra * N + col + 1] = v1; colS[ni][1] += v1; colQ[ni][1] += v1 * v1; }
                if (vb) { C[(size_t)rb * N + col + 1] = v3; colS[ni][1] += v3; colQ[ni][1] += v3 * v3; }
            }
        }
    }

    if (doStat) {
#pragma unroll
        for (int ni = 0; ni < 4; ni++)
#pragma unroll
            for (int p = 0; p < 2; p++) {
#pragma unroll
                for (int off = 4; off < 32; off <<= 1) {
                    colS[ni][p] += __shfl_xor_sync(0xFFFFFFFF, colS[ni][p], off);
                    colQ[ni][p] += __shfl_xor_sync(0xFFFFFFFF, colQ[ni][p], off);
                }
            }
        if (g == 0) {
#pragma unroll
            for (int ni = 0; ni < 4; ni++) {
                int ci = wn * 32 + ni * 8 + t * 2;
                atomicAdd(&s_sum[ci], colS[ni][0]);
                atomicAdd(&s_sq[ci], colQ[ni][0]);
                atomicAdd(&s_sum[ci + 1], colS[ni][1]);
                atomicAdd(&s_sq[ci + 1], colQ[ni][1]);
            }
        }
        __syncthreads();
        if (tid < 128) {
            atomicAdd(&g_colsum[col0 + tid], s_sum[tid]);
            atomicAdd(&g_colsq[col0 + tid], s_sq[tid]);
        }
    }
}

// ---------------- batch norm finalize ----------------
__global__ void zero_stats_k() {
    int i = threadIdx.x + blockIdx.x * blockDim.x;
    if (i < HID) { g_colsum[i] = 0.f; g_colsq[i] = 0.f; }
}
__global__ void bnfin_k(const float* __restrict__ gamma, const float* __restrict__ beta) {
    int j = blockIdx.x * blockDim.x + threadIdx.x;
    if (j >= HID) return;
    float mean = g_colsum[j] * (1.0f / NN);
    float var = g_colsq[j] * (1.0f / NN) - mean * mean;
    float rstd = rsqrtf(var + EPSF);
    float sc = rstd * gamma[j];
    g_scale[j] = sc;
    g_shift[j] = beta[j] - mean * sc;
    g_colsum[j] = 0.f;
    g_colsq[j] = 0.f;
}

// ---------------- host ----------------
static inline int cdiv(long long a, int b) { return (int)((a + b - 1) / b); }

extern "C" void kernel_launch(void* const* d_in, const int* in_sizes, int n_in,
                              void* d_out, int out_size) {
    const float* x = (const float*)d_in[0];
    const void* ei = d_in[1];

    const float* Wl[4] = {(const float*)d_in[2], (const float*)d_in[5],
                          (const float*)d_in[8], (const float*)d_in[11]};
    const float* bl[4] = {(const float*)d_in[3], (const float*)d_in[6],
                          (const float*)d_in[9], (const float*)d_in[12]};
    const float* Wr[4] = {(const float*)d_in[4], (const float*)d_in[7],
                          (const float*)d_in[10], (const float*)d_in[13]};
    const float* gam[3] = {(const float*)d_in[14], (const float*)d_in[16], (const float*)d_in[18]};
    const float* bet[3] = {(const float*)d_in[15], (const float*)d_in[17], (const float*)d_in[19]};
    float* out = (float*)d_out;

    cudaFuncSetAttribute(gemm_k, cudaFuncAttributeMaxDynamicSharedMemorySize, GEMM_SMEM);

    // edge indices + CSR (consolidated)
    prep0_k<<<cdiv(NN, 256), 256>>>();
    detect_idx_k<<<128, 1024>>>((const long long*)ei);
    convert_count_k<<<cdiv(NE, 256), 256>>>(ei);
    scan1_k<<<NSB, 1024>>>();
    scan2_k<<<1, 64>>>();
    scan3_k<<<cdiv(NN, 256), 256>>>();
    fill_k<<<cdiv(NE, 256), 256>>>();
    split_all_k<<<cdiv(WTOT + XTOT, 256), 256>>>(Wl[0], Wr[0], Wl[1], Wr[1],
                                                 Wl[2], Wr[2], Wl[3], Wr[3], x);

    dim3 gfull(4, cdiv(NNP, 128));

    // ---- layer 1 ----
    gather50_k<<<NN, 64>>>(x);
    zero_stats_k<<<2, 256>>>();
    gemm_k<<<gfull, 512, GEMM_SMEM>>>(0, 64, 64, OFF_WL1, OFF_WR1, bl[0], HID, 1, nullptr, 1);
    bnfin_k<<<2, 256>>>(gam[0], bet[0]);

    // ---- layers 2 & 3 ----
    for (int L = 1; L <= 2; ++L) {
        int wl = (L == 1) ? OFF_WL2 : OFF_WL3;
        int wr = (L == 1) ? OFF_WR2 : OFF_WR3;
        gather_bn_k<<<NN / 2, 256>>>();
        gemm_k<<<gfull, 512, GEMM_SMEM>>>(1, 512, 512, wl, wr, bl[L], HID, 1, nullptr, 1);
        bnfin_k<<<2, 256>>>(gam[L], bet[L]);
    }

    // ---- layer 4 -> d_out ----
    gather_bn_k<<<NN / 2, 256>>>();
    gemm_k<<<dim3(1, cdiv(NNP, 128)), 512, GEMM_SMEM>>>(1, 512, 512, OFF_WL4, OFF_WR4,
                                                        bl[3], OUTF, 0, out, 0);
}

// round 12
// speedup vs baseline: 4.2847x; 1.1707x over previous
#include <cuda_runtime.h>
#include <cuda_fp16.h>

#define NN   50000
#define NNP  50048
#define NE   400000
#define INF  50
#define HID  512
#define OUTF 121
#define EPSF 1e-5f
#define NSB  49

// ---------------- device scratch (planes are fp16 now) ----------------
__device__ float g_invdeg[NN];
__device__ float g_h[(size_t)NNP * HID];
__device__ __half g_aggh[(size_t)NNP * HID];
__device__ __half g_aggl[(size_t)NNP * HID];
__device__ __half g_hbh[(size_t)NNP * HID];
__device__ __half g_hbl[(size_t)NNP * HID];
__device__ __half g_xh[(size_t)NNP * 64];
__device__ __half g_xl[(size_t)NNP * 64];
__device__ __half g_a1h[(size_t)NNP * 64];
__device__ __half g_a1l[(size_t)NNP * 64];

#define OFF_WL1 0
#define OFF_WR1 32768
#define OFF_WL2 65536
#define OFF_WR2 327680
#define OFF_WL3 589824
#define OFF_WR3 851968
#define OFF_WL4 1114112
#define OFF_WR4 1179648
#define WTOT    1245184
__device__ __half g_wh[WTOT];
__device__ __half g_wl[WTOT];

__device__ float g_colsum[HID], g_colsq[HID], g_scale[HID], g_shift[HID];
__device__ int g_src[NE], g_dst[NE], g_csrc[NE];
__device__ int g_rowptr[NN + 1], g_cnt[NN], g_cursor[NN], g_is64;
__device__ int g_blksum[64], g_blkoff[64];

// ---------------- helpers ----------------
__device__ __forceinline__ unsigned s2u(const void* p) {
    unsigned a;
    asm("{ .reg .u64 t; cvta.to.shared.u64 t, %1; cvt.u32.u64 %0, t; }" : "=r"(a) : "l"(p));
    return a;
}
__device__ __forceinline__ void cp16(unsigned dst, const void* src) {
    asm volatile("cp.async.cg.shared.global [%0], [%1], 16;" :: "r"(dst), "l"(src));
}
__device__ __forceinline__ void split1(float v, __half& hi, __half& lo) {
    hi = __float2half_rn(v);
    lo = __float2half_rn(v - __half2float(hi));
}
__device__ __forceinline__ void mma_f16(float* c,
                                        unsigned a0, unsigned a1, unsigned a2, unsigned a3,
                                        unsigned b0, unsigned b1) {
    asm volatile(
        "mma.sync.aligned.m16n8k16.row.col.f32.f16.f16.f32 "
        "{%0,%1,%2,%3},{%4,%5,%6,%7},{%8,%9},{%0,%1,%2,%3};"
        : "+f"(c[0]), "+f"(c[1]), "+f"(c[2]), "+f"(c[3])
        : "r"(a0), "r"(a1), "r"(a2), "r"(a3), "r"(b0), "r"(b1));
}

// ---------------- prep ----------------
__global__ void prep0_k() {
    int i = blockIdx.x * blockDim.x + threadIdx.x;
    if (i == 0) g_is64 = 1;
    if (i < NN) g_cnt[i] = 0;
}
__global__ void detect_idx_k(const long long* __restrict__ ei) {
    int stride = gridDim.x * blockDim.x;
    int bad = 0;
    for (int i = blockIdx.x * blockDim.x + threadIdx.x; i < NE; i += stride) {
        long long v = ei[i];
        if (v < 0 || v >= NN) { bad = 1; break; }
    }
    if (__syncthreads_or(bad)) {
        if (threadIdx.x == 0) atomicExch(&g_is64, 0);
    }
}
__global__ void convert_count_k(const void* __restrict__ ei) {
    int e = blockIdx.x * blockDim.x + threadIdx.x;
    if (e >= NE) return;
    int s, d;
    if (g_is64) {
        const long long* p = (const long long*)ei;
        s = (int)p[e]; d = (int)p[e + NE];
    } else {
        const int* p = (const int*)ei;
        s = p[e]; d = p[e + NE];
    }
    s = min(max(s, 0), NN - 1);
    d = min(max(d, 0), NN - 1);
    g_src[e] = s;
    g_dst[e] = d;
    atomicAdd(&g_cnt[d], 1);
}
__global__ void scan1_k() {
    __shared__ int sh[1024];
    int tid = threadIdx.x;
    int i = blockIdx.x * 1024 + tid;
    int v = (i < NN) ? g_cnt[i] : 0;
    sh[tid] = v;
    __syncthreads();
#pragma unroll
    for (int off = 1; off < 1024; off <<= 1) {
        int x = (tid >= off) ? sh[tid - off] : 0;
        __syncthreads();
        sh[tid] += x;
        __syncthreads();
    }
    if (i < NN) g_rowptr[i] = sh[tid] - v;
    if (tid == 1023) g_blksum[blockIdx.x] = sh[1023];
}
__global__ void scan2_k() {
    __shared__ int sh[64];
    int t = threadIdx.x;
    int v = (t < NSB) ? g_blksum[t] : 0;
    sh[t] = v;
    __syncthreads();
#pragma unroll
    for (int off = 1; off < 64; off <<= 1) {
        int x = (t >= off) ? sh[t - off] : 0;
        __syncthreads();
        sh[t] += x;
        __syncthreads();
    }
    if (t < 64) g_blkoff[t] = sh[t] - v;
}
__global__ void scan3_k() {
    int i = blockIdx.x * blockDim.x + threadIdx.x;
    if (i >= NN) return;
    g_rowptr[i] += g_blkoff[i >> 10];
    g_cursor[i] = 0;
    g_invdeg[i] = 1.0f / (float)max(g_cnt[i], 1);
    if (i == 0) g_rowptr[NN] = g_blkoff[NSB - 1] + g_blksum[NSB - 1];
}
__global__ void fill_k() {
    int e = blockIdx.x * blockDim.x + threadIdx.x;
    if (e >= NE) return;
    int d = g_dst[e];
    int slot = g_rowptr[d] + atomicAdd(&g_cursor[d], 1);
    g_csrc[slot] = g_src[e];
}

// ---------------- unified plane split (8 weights + x) ----------------
#define XTOT (NN * 64)
__global__ void split_all_k(const float* __restrict__ Wl1, const float* __restrict__ Wr1,
                            const float* __restrict__ Wl2, const float* __restrict__ Wr2,
                            const float* __restrict__ Wl3, const float* __restrict__ Wr3,
                            const float* __restrict__ Wl4, const float* __restrict__ Wr4,
                            const float* __restrict__ x) {
    int idx = blockIdx.x * blockDim.x + threadIdx.x;
    if (idx >= WTOT + XTOT) return;
    if (idx >= WTOT) {
        int i = idx - WTOT;
        int n = i >> 6, c = i & 63;
        float v = (c < INF) ? x[(size_t)n * INF + c] : 0.f;
        __half hi, lo;
        split1(v, hi, lo);
        g_xh[i] = hi;
        g_xl[i] = lo;
        return;
    }
    const float* W;
    int off, Kpad, K, N;
    if (idx < OFF_WL2) {
        Kpad = 64; K = INF; N = HID;
        if (idx < OFF_WR1) { W = Wl1; off = OFF_WL1; }
        else               { W = Wr1; off = OFF_WR1; }
    } else if (idx < OFF_WL4) {
        Kpad = 512; K = HID; N = HID;
        if (idx < OFF_WR2)      { W = Wl2; off = OFF_WL2; }
        else if (idx < OFF_WL3) { W = Wr2; off = OFF_WR2; }
        else if (idx < OFF_WR3) { W = Wl3; off = OFF_WL3; }
        else                    { W = Wr3; off = OFF_WR3; }
    } else {
        Kpad = 512; K = HID; N = OUTF;
        if (idx < OFF_WR4) { W = Wl4; off = OFF_WL4; }
        else               { W = Wr4; off = OFF_WR4; }
    }
    int local = idx - off;
    int n = local / Kpad, k = local - n * Kpad;
    float v = (n < N && k < K) ? W[(size_t)k * N + n] : 0.f;
    __half hi, lo;
    split1(v, hi, lo);
    g_wh[idx] = hi;
    g_wl[idx] = lo;
}

// ---------------- layer-1 gather ----------------
__global__ void gather50_k(const float* __restrict__ x) {
    int node = blockIdx.x;
    int t = threadIdx.x;
    float acc = 0.f;
    if (t < INF) {
        int beg = g_rowptr[node], end = g_rowptr[node + 1];
        for (int e = beg; e < end; ++e) acc += x[(size_t)g_csrc[e] * INF + t];
        acc *= g_invdeg[node];
    }
    __half hi, lo;
    split1(acc, hi, lo);
    g_a1h[(size_t)node * 64 + t] = hi;
    g_a1l[(size_t)node * 64 + t] = lo;
}

// ---------------- fused gather + BN-apply (2 nodes / 256-thread block) ----------------
__global__ void __launch_bounds__(256, 8) gather_bn_k() {
    int half = threadIdx.x >> 7;
    int tid = threadIdx.x & 127;
    int node = blockIdx.x * 2 + half;
    if (node >= NN) return;
    size_t coff = (size_t)tid * 4;
    float4 sc = *(const float4*)(g_scale + coff);
    float4 sh = *(const float4*)(g_shift + coff);

    {
        float4 v = *(const float4*)(g_h + (size_t)node * HID + coff);
        float r0 = fmaxf(fmaf(v.x, sc.x, sh.x), 0.f);
        float r1 = fmaxf(fmaf(v.y, sc.y, sh.y), 0.f);
        float r2 = fmaxf(fmaf(v.z, sc.z, sh.z), 0.f);
        float r3 = fmaxf(fmaf(v.w, sc.w, sh.w), 0.f);
        __half h0, l0, h1, l1, h2, l2, h3, l3;
        split1(r0, h0, l0); split1(r1, h1, l1); split1(r2, h2, l2); split1(r3, h3, l3);
        size_t o = (size_t)node * HID + coff;
        *(ushort4*)(g_hbh + o) = make_ushort4(__half_as_ushort(h0), __half_as_ushort(h1),
                                              __half_as_ushort(h2), __half_as_ushort(h3));
        *(ushort4*)(g_hbl + o) = make_ushort4(__half_as_ushort(l0), __half_as_ushort(l1),
                                              __half_as_ushort(l2), __half_as_ushort(l3));
    }

    int beg = g_rowptr[node], end = g_rowptr[node + 1];
    float a0 = 0.f, a1 = 0.f, a2 = 0.f, a3 = 0.f;
    int e = beg;
    for (; e + 3 < end; e += 4) {
        int s0 = g_csrc[e], s1 = g_csrc[e + 1], s2 = g_csrc[e + 2], s3 = g_csrc[e + 3];
        float4 v0 = *(const float4*)(g_h + (size_t)s0 * HID + coff);
        float4 v1 = *(const float4*)(g_h + (size_t)s1 * HID + coff);
        float4 v2 = *(const float4*)(g_h + (size_t)s2 * HID + coff);
        float4 v3 = *(const float4*)(g_h + (size_t)s3 * HID + coff);
        a0 += fmaxf(fmaf(v0.x, sc.x, sh.x), 0.f) + fmaxf(fmaf(v1.x, sc.x, sh.x), 0.f)
            + fmaxf(fmaf(v2.x, sc.x, sh.x), 0.f) + fmaxf(fmaf(v3.x, sc.x, sh.x), 0.f);
        a1 += fmaxf(fmaf(v0.y, sc.y, sh.y), 0.f) + fmaxf(fmaf(v1.y, sc.y, sh.y), 0.f)
            + fmaxf(fmaf(v2.y, sc.y, sh.y), 0.f) + fmaxf(fmaf(v3.y, sc.y, sh.y), 0.f);
        a2 += fmaxf(fmaf(v0.z, sc.z, sh.z), 0.f) + fmaxf(fmaf(v1.z, sc.z, sh.z), 0.f)
            + fmaxf(fmaf(v2.z, sc.z, sh.z), 0.f) + fmaxf(fmaf(v3.z, sc.z, sh.z), 0.f);
        a3 += fmaxf(fmaf(v0.w, sc.w, sh.w), 0.f) + fmaxf(fmaf(v1.w, sc.w, sh.w), 0.f)
            + fmaxf(fmaf(v2.w, sc.w, sh.w), 0.f) + fmaxf(fmaf(v3.w, sc.w, sh.w), 0.f);
    }
    for (; e < end; ++e) {
        float4 v0 = *(const float4*)(g_h + (size_t)g_csrc[e] * HID + coff);
        a0 += fmaxf(fmaf(v0.x, sc.x, sh.x), 0.f);
        a1 += fmaxf(fmaf(v0.y, sc.y, sh.y), 0.f);
        a2 += fmaxf(fmaf(v0.z, sc.z, sh.z), 0.f);
        a3 += fmaxf(fmaf(v0.w, sc.w, sh.w), 0.f);
    }
    float inv = g_invdeg[node];
    a0 *= inv; a1 *= inv; a2 *= inv; a3 *= inv;
    __half h0, l0, h1, l1, h2, l2, h3, l3;
    split1(a0, h0, l0); split1(a1, h1, l1); split1(a2, h2, l2); split1(a3, h3, l3);
    size_t o = (size_t)node * HID + coff;
    *(ushort4*)(g_aggh + o) = make_ushort4(__half_as_ushort(h0), __half_as_ushort(h1),
                                           __half_as_ushort(h2), __half_as_ushort(h3));
    *(ushort4*)(g_aggl + o) = make_ushort4(__half_as_ushort(l0), __half_as_ushort(l1),
                                           __half_as_ushort(l2), __half_as_ushort(l3));
}

// ---------------- dual GEMM (fp16 split, 2- or 3-term) + fused BN stats ----------------
#define AW 20
#define ASZ (128 * AW)
#define STG (4 * ASZ)
#define GEMM_SMEM (3 * STG * 4)

__global__ void __launch_bounds__(512, 1)
gemm_k(int aSel, int K1, int K2, int woff1, int woff2,
       const float* __restrict__ bias, int N, int cSel, float* __restrict__ cExt,
       int doStat, int nt) {
    extern __shared__ unsigned sm[];
    unsigned sbase = s2u(sm);
    __shared__ float s_sum[128], s_sq[128];

    const __half *A1h, *A1l, *A2h, *A2l;
    if (aSel == 0) { A1h = g_a1h; A1l = g_a1l; A2h = g_xh; A2l = g_xl; }
    else           { A1h = g_aggh; A1l = g_aggl; A2h = g_hbh; A2l = g_hbl; }
    const __half* B1h = g_wh + woff1;
    const __half* B1l = g_wl + woff1;
    const __half* B2h = g_wh + woff2;
    const __half* B2l = g_wl + woff2;
    float* C = (cSel == 1) ? g_h : cExt;

    int tid = threadIdx.x;
    int warp = tid >> 5, lane = tid & 31;
    int wm = warp & 3, wn = warp >> 2;
    int g = lane >> 2, t = lane & 3;
    int row0 = blockIdx.y * 128;
    int col0 = blockIdx.x * 128;

    int S1 = K1 >> 5, S2 = K2 >> 5, S = S1 + S2;

    float acc[2][4][4];
#pragma unroll
    for (int mi = 0; mi < 2; mi++)
#pragma unroll
        for (int ni = 0; ni < 4; ni++)
#pragma unroll
            for (int r = 0; r < 4; r++) acc[mi][ni][r] = 0.f;

    if (doStat && tid < 128) { s_sum[tid] = 0.f; s_sq[tid] = 0.f; }

    int prow = tid >> 2, pch = tid & 3;

    auto prefetch = [&](int s, int buf) {
        const __half *Ah, *Al, *Bh, *Bl;
        int ka, k0;
        if (s < S1) { Ah = A1h; Al = A1l; Bh = B1h; Bl = B1l; ka = K1; k0 = s * 32; }
        else        { Ah = A2h; Al = A2l; Bh = B2h; Bl = B2l; ka = K2; k0 = (s - S1) * 32; }
        unsigned b = sbase + buf * (STG * 4) + prow * (AW * 4) + pch * 16;
        size_t aoff = (size_t)(row0 + prow) * ka + k0 + pch * 8;
        size_t boff = (size_t)(col0 + prow) * ka + k0 + pch * 8;
        cp16(b,               Ah + aoff);
        cp16(b + ASZ * 4,     Al + aoff);
        cp16(b + 2 * ASZ * 4, Bh + boff);
        if (nt == 3) cp16(b + 3 * ASZ * 4, Bl + boff);
        asm volatile("cp.async.commit_group;" ::: "memory");
    };

    auto compute = [&](int buf) {
        const unsigned* Ah = sm + buf * STG;
        const unsigned* Al = Ah + ASZ;
        const unsigned* Bh = Ah + 2 * ASZ;
        const unsigned* Bl = Ah + 3 * ASZ;
#pragma unroll
        for (int ks = 0; ks < 2; ks++) {
            int kb = ks * 8;
            unsigned ah[2][4], al[2][4];
#pragma unroll
            for (int mi = 0; mi < 2; mi++) {
                int rb = wm * 32 + mi * 16;
                int i0 = (rb + g) * AW + kb + t;
                int i1 = (rb + g + 8) * AW + kb + t;
                ah[mi][0] = Ah[i0];     al[mi][0] = Al[i0];
                ah[mi][1] = Ah[i1];     al[mi][1] = Al[i1];
                ah[mi][2] = Ah[i0 + 4]; al[mi][2] = Al[i0 + 4];
                ah[mi][3] = Ah[i1 + 4]; al[mi][3] = Al[i1 + 4];
            }
            unsigned bh[4][2];
#pragma unroll
            for (int ni = 0; ni < 4; ni++) {
                int cb = (wn * 32 + ni * 8 + g) * AW + kb + t;
                bh[ni][0] = Bh[cb];
                bh[ni][1] = Bh[cb + 4];
            }
#pragma unroll
            for (int mi = 0; mi < 2; mi++)
#pragma unroll
                for (int ni = 0; ni < 4; ni++) {
                    float* c = acc[mi][ni];
                    mma_f16(c, ah[mi][0], ah[mi][1], ah[mi][2], ah[mi][3], bh[ni][0], bh[ni][1]);
                    mma_f16(c, al[mi][0], al[mi][1], al[mi][2], al[mi][3], bh[ni][0], bh[ni][1]);
                }
            if (nt == 3) {
#pragma unroll
                for (int ni = 0; ni < 4; ni++) {
                    int cb = (wn * 32 + ni * 8 + g) * AW + kb + t;
                    unsigned bl0 = Bl[cb];
                    unsigned bl1 = Bl[cb + 4];
#pragma unroll
                    for (int mi = 0; mi < 2; mi++) {
                        float* c = acc[mi][ni];
                        mma_f16(c, ah[mi][0], ah[mi][1], ah[mi][2], ah[mi][3], bl0, bl1);
                    }
                }
            }
        }
    };

    prefetch(0, 0);
    if (S > 1) prefetch(1, 1);
#pragma unroll 1
    for (int s = 0; s < S; s++) {
        if (s + 1 < S) { asm volatile("cp.async.wait_group 1;" ::: "memory"); }
        else           { asm volatile("cp.async.wait_group 0;" ::: "memory"); }
        __syncthreads();
        if (s + 2 < S) prefetch(s + 2, (s + 2) % 3);
        compute(s % 3);
    }

    if (doStat) __syncthreads();

    float colS[4][2], colQ[4][2];
#pragma unroll
    for (int ni = 0; ni < 4; ni++) {
        colS[ni][0] = colS[ni][1] = 0.f;
        colQ[ni][0] = colQ[ni][1] = 0.f;
    }
#pragma unroll
    for (int mi = 0; mi < 2; mi++) {
        int ra = row0 + wm * 32 + mi * 16 + g;
        int rb = ra + 8;
        bool va = ra < NN, vb = rb < NN;
#pragma unroll
        for (int ni = 0; ni < 4; ni++) {
            int col = col0 + wn * 32 + ni * 8 + t * 2;
            float* c = acc[mi][ni];
            if (col < N) {
                float b0 = __ldg(&bias[col]);
                float v0 = c[0] + b0, v2 = c[2] + b0;
                if (va) { C[(size_t)ra * N + col] = v0; colS[ni][0] += v0; colQ[ni][0] += v0 * v0; }
                if (vb) { C[(size_t)rb * N + col] = v2; colS[ni][0] += v2; colQ[ni][0] += v2 * v2; }
            }
            if (col + 1 < N) {
                float b1 = __ldg(&bias[col + 1]);
                float v1 = c[1] + b1, v3 = c[3] + b1;
                if (va) { C[(size_t)ra * N + col + 1] = v1; colS[ni][1] += v1; colQ[ni][1] += v1 * v1; }
                if (vb) { C[(size_t)rb * N + col + 1] = v3; colS[ni][1] += v3; colQ[ni][1] += v3 * v3; }
            }
        }
    }

    if (doStat) {
#pragma unroll
        for (int ni = 0; ni < 4; ni++)
#pragma unroll
            for (int p = 0; p < 2; p++) {
#pragma unroll
                for (int off = 4; off < 32; off <<= 1) {
                    colS[ni][p] += __shfl_xor_sync(0xFFFFFFFF, colS[ni][p], off);
                    colQ[ni][p] += __shfl_xor_sync(0xFFFFFFFF, colQ[ni][p], off);
                }
            }
        if (g == 0) {
#pragma unroll
            for (int ni = 0; ni < 4; ni++) {
                int ci = wn * 32 + ni * 8 + t * 2;
                atomicAdd(&s_sum[ci], colS[ni][0]);
                atomicAdd(&s_sq[ci], colQ[ni][0]);
                atomicAdd(&s_sum[ci + 1], colS[ni][1]);
                atomicAdd(&s_sq[ci + 1], colQ[ni][1]);
            }
        }
        __syncthreads();
        if (tid < 128) {
            atomicAdd(&g_colsum[col0 + tid], s_sum[tid]);
            atomicAdd(&g_colsq[col0 + tid], s_sq[tid]);
        }
    }
}

// ---------------- batch norm finalize ----------------
__global__ void zero_stats_k() {
    int i = threadIdx.x + blockIdx.x * blockDim.x;
    if (i < HID) { g_colsum[i] = 0.f; g_colsq[i] = 0.f; }
}
__global__ void bnfin_k(const float* __restrict__ gamma, const float* __restrict__ beta) {
    int j = blockIdx.x * blockDim.x + threadIdx.x;
    if (j >= HID) return;
    float mean = g_colsum[j] * (1.0f / NN);
    float var = g_colsq[j] * (1.0f / NN) - mean * mean;
    float rstd = rsqrtf(var + EPSF);
    float sc = rstd * gamma[j];
    g_scale[j] = sc;
    g_shift[j] = beta[j] - mean * sc;
    g_colsum[j] = 0.f;
    g_colsq[j] = 0.f;
}

// ---------------- host ----------------
static inline int cdiv(long long a, int b) { return (int)((a + b - 1) / b); }

extern "C" void kernel_launch(void* const* d_in, const int* in_sizes, int n_in,
                              void* d_out, int out_size) {
    const float* x = (const float*)d_in[0];
    const void* ei = d_in[1];

    const float* Wl[4] = {(const float*)d_in[2], (const float*)d_in[5],
                          (const float*)d_in[8], (const float*)d_in[11]};
    const float* bl[4] = {(const float*)d_in[3], (const float*)d_in[6],
                          (const float*)d_in[9], (const float*)d_in[12]};
    const float* Wr[4] = {(const float*)d_in[4], (const float*)d_in[7],
                          (const float*)d_in[10], (const float*)d_in[13]};
    const float* gam[3] = {(const float*)d_in[14], (const float*)d_in[16], (const float*)d_in[18]};
    const float* bet[3] = {(const float*)d_in[15], (const float*)d_in[17], (const float*)d_in[19]};
    float* out = (float*)d_out;

    cudaFuncSetAttribute(gemm_k, cudaFuncAttributeMaxDynamicSharedMemorySize, GEMM_SMEM);

    // edge indices + CSR
    prep0_k<<<cdiv(NN, 256), 256>>>();
    detect_idx_k<<<128, 1024>>>((const long long*)ei);
    convert_count_k<<<cdiv(NE, 256), 256>>>(ei);
    scan1_k<<<NSB, 1024>>>();
    scan2_k<<<1, 64>>>();
    scan3_k<<<cdiv(NN, 256), 256>>>();
    fill_k<<<cdiv(NE, 256), 256>>>();
    split_all_k<<<cdiv(WTOT + XTOT, 256), 256>>>(Wl[0], Wr[0], Wl[1], Wr[1],
                                                 Wl[2], Wr[2], Wl[3], Wr[3], x);

    dim3 gfull(4, cdiv(NNP, 128));

    // ---- layer 1 (2-term) ----
    gather50_k<<<NN, 64>>>(x);
    zero_stats_k<<<2, 256>>>();
    gemm_k<<<gfull, 512, GEMM_SMEM>>>(0, 64, 64, OFF_WL1, OFF_WR1, bl[0], HID, 1, nullptr, 1, 2);
    bnfin_k<<<2, 256>>>(gam[0], bet[0]);

    // ---- layers 2 & 3 (2-term) ----
    for (int L = 1; L <= 2; ++L) {
        int wl = (L == 1) ? OFF_WL2 : OFF_WL3;
        int wr = (L == 1) ? OFF_WR2 : OFF_WR3;
        gather_bn_k<<<NN / 2, 256>>>();
        gemm_k<<<gfull, 512, GEMM_SMEM>>>(1, 512, 512, wl, wr, bl[L], HID, 1, nullptr, 1, 2);
        bnfin_k<<<2, 256>>>(gam[L], bet[L]);
    }

    // ---- layer 4 (3-term, writes checked output) ----
    gather_bn_k<<<NN / 2, 256>>>();
    gemm_k<<<dim3(1, cdiv(NNP, 128)), 512, GEMM_SMEM>>>(1, 512, 512, OFF_WL4, OFF_WR4,
                                                        bl[3], OUTF, 0, out, 0, 3);
}

// round 13
// speedup vs baseline: 4.8138x; 1.1235x over previous
#include <cuda_runtime.h>
#include <cuda_fp16.h>

#define NN   50000
#define NNP  50048
#define NE   400000
#define INF  50
#define HID  512
#define OUTF 121
#define EPSF 1e-5f
#define NSB  49

// ---------------- device scratch (fp16 planes) ----------------
__device__ float g_invdeg[NN];
__device__ float g_h[(size_t)NNP * HID];
__device__ __half g_aggh[(size_t)NNP * HID];
__device__ __half g_aggl[(size_t)NNP * HID];
__device__ __half g_hbh[(size_t)NNP * HID];
__device__ __half g_hbl[(size_t)NNP * HID];
__device__ __half g_xh[(size_t)NNP * 64];
__device__ __half g_xl[(size_t)NNP * 64];
__device__ __half g_a1h[(size_t)NNP * 64];
__device__ __half g_a1l[(size_t)NNP * 64];

#define OFF_WL1 0
#define OFF_WR1 32768
#define OFF_WL2 65536
#define OFF_WR2 327680
#define OFF_WL3 589824
#define OFF_WR3 851968
#define OFF_WL4 1114112
#define OFF_WR4 1179648
#define WTOT    1245184
__device__ __half g_wh[WTOT];
__device__ __half g_wl[WTOT];

__device__ float g_colsum[HID], g_colsq[HID], g_scale[HID], g_shift[HID];
__device__ int g_src[NE], g_dst[NE], g_csrc[NE];
__device__ int g_rowptr[NN + 1], g_cnt[NN], g_cursor[NN], g_is64;
__device__ int g_blksum[64], g_blkoff[64];

// ---------------- helpers ----------------
__device__ __forceinline__ unsigned s2u(const void* p) {
    unsigned a;
    asm("{ .reg .u64 t; cvta.to.shared.u64 t, %1; cvt.u32.u64 %0, t; }" : "=r"(a) : "l"(p));
    return a;
}
__device__ __forceinline__ void cp16(unsigned dst, const void* src) {
    asm volatile("cp.async.cg.shared.global [%0], [%1], 16;" :: "r"(dst), "l"(src));
}
__device__ __forceinline__ void split1(float v, __half& hi, __half& lo) {
    hi = __float2half_rn(v);
    lo = __float2half_rn(v - __half2float(hi));
}
__device__ __forceinline__ void mma_f16(float* c,
                                        unsigned a0, unsigned a1, unsigned a2, unsigned a3,
                                        unsigned b0, unsigned b1) {
    asm volatile(
        "mma.sync.aligned.m16n8k16.row.col.f32.f16.f16.f32 "
        "{%0,%1,%2,%3},{%4,%5,%6,%7},{%8,%9},{%0,%1,%2,%3};"
        : "+f"(c[0]), "+f"(c[1]), "+f"(c[2]), "+f"(c[3])
        : "r"(a0), "r"(a1), "r"(a2), "r"(a3), "r"(b0), "r"(b1));
}

// ---------------- prep ----------------
__global__ void prep0_k() {
    int i = blockIdx.x * blockDim.x + threadIdx.x;
    if (i == 0) g_is64 = 1;
    if (i < NN) g_cnt[i] = 0;
    if (i < HID) { g_colsum[i] = 0.f; g_colsq[i] = 0.f; }
}
__global__ void detect_idx_k(const long long* __restrict__ ei) {
    int stride = gridDim.x * blockDim.x;
    int bad = 0;
    for (int i = blockIdx.x * blockDim.x + threadIdx.x; i < NE; i += stride) {
        long long v = ei[i];
        if (v < 0 || v >= NN) { bad = 1; break; }
    }
    if (__syncthreads_or(bad)) {
        if (threadIdx.x == 0) atomicExch(&g_is64, 0);
    }
}
__global__ void convert_count_k(const void* __restrict__ ei) {
    int e = blockIdx.x * blockDim.x + threadIdx.x;
    if (e >= NE) return;
    int s, d;
    if (g_is64) {
        const long long* p = (const long long*)ei;
        s = (int)p[e]; d = (int)p[e + NE];
    } else {
        const int* p = (const int*)ei;
        s = p[e]; d = p[e + NE];
    }
    s = min(max(s, 0), NN - 1);
    d = min(max(d, 0), NN - 1);
    g_src[e] = s;
    g_dst[e] = d;
    atomicAdd(&g_cnt[d], 1);
}
__global__ void scan1_k() {
    __shared__ int sh[1024];
    int tid = threadIdx.x;
    int i = blockIdx.x * 1024 + tid;
    int v = (i < NN) ? g_cnt[i] : 0;
    sh[tid] = v;
    __syncthreads();
#pragma unroll
    for (int off = 1; off < 1024; off <<= 1) {
        int x = (tid >= off) ? sh[tid - off] : 0;
        __syncthreads();
        sh[tid] += x;
        __syncthreads();
    }
    if (i < NN) g_rowptr[i] = sh[tid] - v;
    if (tid == 1023) g_blksum[blockIdx.x] = sh[1023];
}
__global__ void scan2_k() {
    __shared__ int sh[64];
    int t = threadIdx.x;
    int v = (t < NSB) ? g_blksum[t] : 0;
    sh[t] = v;
    __syncthreads();
#pragma unroll
    for (int off = 1; off < 64; off <<= 1) {
        int x = (t >= off) ? sh[t - off] : 0;
        __syncthreads();
        sh[t] += x;
        __syncthreads();
    }
    if (t < 64) g_blkoff[t] = sh[t] - v;
}
__global__ void scan3_k() {
    int i = blockIdx.x * blockDim.x + threadIdx.x;
    if (i >= NN) return;
    g_rowptr[i] += g_blkoff[i >> 10];
    g_cursor[i] = 0;
    g_invdeg[i] = 1.0f / (float)max(g_cnt[i], 1);
    if (i == 0) g_rowptr[NN] = g_blkoff[NSB - 1] + g_blksum[NSB - 1];
}
__global__ void fill_k() {
    int e = blockIdx.x * blockDim.x + threadIdx.x;
    if (e >= NE) return;
    int d = g_dst[e];
    int slot = g_rowptr[d] + atomicAdd(&g_cursor[d], 1);
    g_csrc[slot] = g_src[e];
}

// ---------------- unified plane split ----------------
#define XTOT (NN * 64)
__global__ void split_all_k(const float* __restrict__ Wl1, const float* __restrict__ Wr1,
                            const float* __restrict__ Wl2, const float* __restrict__ Wr2,
                            const float* __restrict__ Wl3, const float* __restrict__ Wr3,
                            const float* __restrict__ Wl4, const float* __restrict__ Wr4,
                            const float* __restrict__ x) {
    int idx = blockIdx.x * blockDim.x + threadIdx.x;
    if (idx >= WTOT + XTOT) return;
    if (idx >= WTOT) {
        int i = idx - WTOT;
        int n = i >> 6, c = i & 63;
        float v = (c < INF) ? x[(size_t)n * INF + c] : 0.f;
        __half hi, lo;
        split1(v, hi, lo);
        g_xh[i] = hi;
        g_xl[i] = lo;
        return;
    }
    const float* W;
    int off, Kpad, K, N;
    if (idx < OFF_WL2) {
        Kpad = 64; K = INF; N = HID;
        if (idx < OFF_WR1) { W = Wl1; off = OFF_WL1; }
        else               { W = Wr1; off = OFF_WR1; }
    } else if (idx < OFF_WL4) {
        Kpad = 512; K = HID; N = HID;
        if (idx < OFF_WR2)      { W = Wl2; off = OFF_WL2; }
        else if (idx < OFF_WL3) { W = Wr2; off = OFF_WR2; }
        else if (idx < OFF_WR3) { W = Wl3; off = OFF_WL3; }
        else                    { W = Wr3; off = OFF_WR3; }
    } else {
        Kpad = 512; K = HID; N = OUTF;
        if (idx < OFF_WR4) { W = Wl4; off = OFF_WL4; }
        else               { W = Wr4; off = OFF_WR4; }
    }
    int local = idx - off;
    int n = local / Kpad, k = local - n * Kpad;
    float v = (n < N && k < K) ? W[(size_t)k * N + n] : 0.f;
    __half hi, lo;
    split1(v, hi, lo);
    g_wh[idx] = hi;
    g_wl[idx] = lo;
}

// ---------------- layer-1 gather ----------------
__global__ void gather50_k(const float* __restrict__ x) {
    int node = blockIdx.x;
    int t = threadIdx.x;
    float acc = 0.f;
    if (t < INF) {
        int beg = g_rowptr[node], end = g_rowptr[node + 1];
        for (int e = beg; e < end; ++e) acc += x[(size_t)g_csrc[e] * INF + t];
        acc *= g_invdeg[node];
    }
    __half hi, lo;
    split1(acc, hi, lo);
    g_a1h[(size_t)node * 64 + t] = hi;
    g_a1l[(size_t)node * 64 + t] = lo;
}

// ---------------- fused gather + BN-apply ----------------
__global__ void __launch_bounds__(256, 8) gather_bn_k() {
    int half = threadIdx.x >> 7;
    int tid = threadIdx.x & 127;
    int node = blockIdx.x * 2 + half;
    if (node >= NN) return;
    size_t coff = (size_t)tid * 4;
    float4 sc = *(const float4*)(g_scale + coff);
    float4 sh = *(const float4*)(g_shift + coff);

    {
        float4 v = *(const float4*)(g_h + (size_t)node * HID + coff);
        float r0 = fmaxf(fmaf(v.x, sc.x, sh.x), 0.f);
        float r1 = fmaxf(fmaf(v.y, sc.y, sh.y), 0.f);
        float r2 = fmaxf(fmaf(v.z, sc.z, sh.z), 0.f);
        float r3 = fmaxf(fmaf(v.w, sc.w, sh.w), 0.f);
        __half h0, l0, h1, l1, h2, l2, h3, l3;
        split1(r0, h0, l0); split1(r1, h1, l1); split1(r2, h2, l2); split1(r3, h3, l3);
        size_t o = (size_t)node * HID + coff;
        *(ushort4*)(g_hbh + o) = make_ushort4(__half_as_ushort(h0), __half_as_ushort(h1),
                                              __half_as_ushort(h2), __half_as_ushort(h3));
        *(ushort4*)(g_hbl + o) = make_ushort4(__half_as_ushort(l0), __half_as_ushort(l1),
                                              __half_as_ushort(l2), __half_as_ushort(l3));
    }

    int beg = g_rowptr[node], end = g_rowptr[node + 1];
    float a0 = 0.f, a1 = 0.f, a2 = 0.f, a3 = 0.f;
    int e = beg;
    for (; e + 3 < end; e += 4) {
        int s0 = g_csrc[e], s1 = g_csrc[e + 1], s2 = g_csrc[e + 2], s3 = g_csrc[e + 3];
        float4 v0 = *(const float4*)(g_h + (size_t)s0 * HID + coff);
        float4 v1 = *(const float4*)(g_h + (size_t)s1 * HID + coff);
        float4 v2 = *(const float4*)(g_h + (size_t)s2 * HID + coff);
        float4 v3 = *(const float4*)(g_h + (size_t)s3 * HID + coff);
        a0 += fmaxf(fmaf(v0.x, sc.x, sh.x), 0.f) + fmaxf(fmaf(v1.x, sc.x, sh.x), 0.f)
            + fmaxf(fmaf(v2.x, sc.x, sh.x), 0.f) + fmaxf(fmaf(v3.x, sc.x, sh.x), 0.f);
        a1 += fmaxf(fmaf(v0.y, sc.y, sh.y), 0.f) + fmaxf(fmaf(v1.y, sc.y, sh.y), 0.f)
            + fmaxf(fmaf(v2.y, sc.y, sh.y), 0.f) + fmaxf(fmaf(v3.y, sc.y, sh.y), 0.f);
        a2 += fmaxf(fmaf(v0.z, sc.z, sh.z), 0.f) + fmaxf(fmaf(v1.z, sc.z, sh.z), 0.f)
            + fmaxf(fmaf(v2.z, sc.z, sh.z), 0.f) + fmaxf(fmaf(v3.z, sc.z, sh.z), 0.f);
        a3 += fmaxf(fmaf(v0.w, sc.w, sh.w), 0.f) + fmaxf(fmaf(v1.w, sc.w, sh.w), 0.f)
            + fmaxf(fmaf(v2.w, sc.w, sh.w), 0.f) + fmaxf(fmaf(v3.w, sc.w, sh.w), 0.f);
    }
    for (; e < end; ++e) {
        float4 v0 = *(const float4*)(g_h + (size_t)g_csrc[e] * HID + coff);
        a0 += fmaxf(fmaf(v0.x, sc.x, sh.x), 0.f);
        a1 += fmaxf(fmaf(v0.y, sc.y, sh.y), 0.f);
        a2 += fmaxf(fmaf(v0.z, sc.z, sh.z), 0.f);
        a3 += fmaxf(fmaf(v0.w, sc.w, sh.w), 0.f);
    }
    float inv = g_invdeg[node];
    a0 *= inv; a1 *= inv; a2 *= inv; a3 *= inv;
    __half h0, l0, h1, l1, h2, l2, h3, l3;
    split1(a0, h0, l0); split1(a1, h1, l1); split1(a2, h2, l2); split1(a3, h3, l3);
    size_t o = (size_t)node * HID + coff;
    *(ushort4*)(g_aggh + o) = make_ushort4(__half_as_ushort(h0), __half_as_ushort(h1),
                                           __half_as_ushort(h2), __half_as_ushort(h3));
    *(ushort4*)(g_aggl + o) = make_ushort4(__half_as_ushort(l0), __half_as_ushort(l1),
                                           __half_as_ushort(l2), __half_as_ushort(l3));
}

// ---------------- templated dual GEMM: NI = col-groups per warp (4 -> BN=128, 8 -> BN=256) ----------------
#define AW 20
#define ASZ (128 * AW)

template <int NI, int NT>
__global__ void __launch_bounds__(512, 1)
gemm_k(int aSel, int K1, int K2, int woff1, int woff2,
       const float* __restrict__ bias, int N, int cSel, float* __restrict__ cExt,
       int doStat) {
    constexpr int BN = NI * 32;                       // 128 or 256
    constexpr int BSZ = BN * AW;                      // uints per B plane
    constexpr int NB = (NT == 3) ? 2 : 1;             // B planes in smem
    constexpr int STGU = 2 * ASZ + NB * BSZ;          // uints per stage

    extern __shared__ unsigned sm[];
    unsigned sbase = s2u(sm);
    __shared__ float s_sum[BN], s_sq[BN];

    const __half *A1h, *A1l, *A2h, *A2l;
    if (aSel == 0) { A1h = g_a1h; A1l = g_a1l; A2h = g_xh; A2l = g_xl; }
    else           { A1h = g_aggh; A1l = g_aggl; A2h = g_hbh; A2l = g_hbl; }
    const __half* B1h = g_wh + woff1;
    const __half* B1l = g_wl + woff1;
    const __half* B2h = g_wh + woff2;
    const __half* B2l = g_wl + woff2;
    float* C = (cSel == 1) ? g_h : cExt;

    int tid = threadIdx.x;
    int warp = tid >> 5, lane = tid & 31;
    int wm = warp & 3, wn = warp >> 2;
    int g = lane >> 2, t = lane & 3;
    int row0 = blockIdx.y * 128;
    int col0 = blockIdx.x * BN;

    int S1 = K1 >> 5, S2 = K2 >> 5, S = S1 + S2;

    float acc[2][NI][4];
#pragma unroll
    for (int mi = 0; mi < 2; mi++)
#pragma unroll
        for (int ni = 0; ni < NI; ni++)
#pragma unroll
            for (int r = 0; r < 4; r++) acc[mi][ni][r] = 0.f;

    if (doStat && tid < BN) { s_sum[tid] = 0.f; s_sq[tid] = 0.f; }

    int prow = tid >> 2, pch = tid & 3;

    auto prefetch = [&](int s, int buf) {
        const __half *Ah, *Al, *Bh, *Bl;
        int ka, k0;
        if (s < S1) { Ah = A1h; Al = A1l; Bh = B1h; Bl = B1l; ka = K1; k0 = s * 32; }
        else        { Ah = A2h; Al = A2l; Bh = B2h; Bl = B2l; ka = K2; k0 = (s - S1) * 32; }
        unsigned base = sbase + buf * (STGU * 4);
        // A planes: 128 rows x 4 chunks, one cp16 per (thread, plane)
        {
            unsigned d = base + prow * (AW * 4) + pch * 16;
            size_t aoff = (size_t)(row0 + prow) * ka + k0 + pch * 8;
            cp16(d,           Ah + aoff);
            cp16(d + ASZ * 4, Al + aoff);
        }
        // B planes: BN rows x 4 chunks
#pragma unroll
        for (int l = 0; l < NI / 4; l++) {
            int idx = tid + l * 512;
            int brow = idx >> 2, bch = idx & 3;
            unsigned d = base + 2 * ASZ * 4 + brow * (AW * 4) + bch * 16;
            size_t boff = (size_t)(col0 + brow) * ka + k0 + bch * 8;
            cp16(d, Bh + boff);
            if (NT == 3) cp16(d + BSZ * 4, Bl + boff);
        }
        asm volatile("cp.async.commit_group;" ::: "memory");
    };

    auto compute = [&](int buf) {
        const unsigned* Ah = sm + buf * STGU;
        const unsigned* Al = Ah + ASZ;
        const unsigned* Bh = Ah + 2 * ASZ;
        const unsigned* Bl = Bh + BSZ;
#pragma unroll
        for (int ks = 0; ks < 2; ks++) {
            int kb = ks * 8;
            unsigned ah[2][4], al[2][4];
#pragma unroll
            for (int mi = 0; mi < 2; mi++) {
                int rb = wm * 32 + mi * 16;
                int i0 = (rb + g) * AW + kb + t;
                int i1 = (rb + g + 8) * AW + kb + t;
                ah[mi][0] = Ah[i0];     al[mi][0] = Al[i0];
                ah[mi][1] = Ah[i1];     al[mi][1] = Al[i1];
                ah[mi][2] = Ah[i0 + 4]; al[mi][2] = Al[i0 + 4];
                ah[mi][3] = Ah[i1 + 4]; al[mi][3] = Al[i1 + 4];
            }
#pragma unroll
            for (int ni = 0; ni < NI; ni++) {
                int cb = (wn * (NI * 8) + ni * 8 + g) * AW + kb + t;
                unsigned b0 = Bh[cb];
                unsigned b1 = Bh[cb + 4];
#pragma unroll
                for (int mi = 0; mi < 2; mi++) {
                    float* c = acc[mi][ni];
                    mma_f16(c, ah[mi][0], ah[mi][1], ah[mi][2], ah[mi][3], b0, b1);
                    mma_f16(c, al[mi][0], al[mi][1], al[mi][2], al[mi][3], b0, b1);
                }
                if (NT == 3) {
                    unsigned bl0 = Bl[cb];
                    unsigned bl1 = Bl[cb + 4];
#pragma unroll
                    for (int mi = 0; mi < 2; mi++) {
                        float* c = acc[mi][ni];
                        mma_f16(c, ah[mi][0], ah[mi][1], ah[mi][2], ah[mi][3], bl0, bl1);
                    }
                }
            }
        }
    };

    prefetch(0, 0);
    if (S > 1) prefetch(1, 1);
#pragma unroll 1
    for (int s = 0; s < S; s++) {
        if (s + 1 < S) { asm volatile("cp.async.wait_group 1;" ::: "memory"); }
        else           { asm volatile("cp.async.wait_group 0;" ::: "memory"); }
        __syncthreads();
        if (s + 2 < S) prefetch(s + 2, (s + 2) % 3);
        compute(s % 3);
    }

    if (doStat) __syncthreads();

    float colS[NI][2], colQ[NI][2];
#pragma unroll
    for (int ni = 0; ni < NI; ni++) {
        colS[ni][0] = colS[ni][1] = 0.f;
        colQ[ni][0] = colQ[ni][1] = 0.f;
    }
#pragma unroll
    for (int mi = 0; mi < 2; mi++) {
        int ra = row0 + wm * 32 + mi * 16 + g;
        int rb = ra + 8;
        bool va = ra < NN, vb = rb < NN;
#pragma unroll
        for (int ni = 0; ni < NI; ni++) {
            int col = col0 + wn * (NI * 8) + ni * 8 + t * 2;
            float* c = acc[mi][ni];
            if (col < N) {
                float b0 = __ldg(&bias[col]);
                float v0 = c[0] + b0, v2 = c[2] + b0;
                if (va) { C[(size_t)ra * N + col] = v0; colS[ni][0] += v0; colQ[ni][0] += v0 * v0; }
                if (vb) { C[(size_t)rb * N + col] = v2; colS[ni][0] += v2; colQ[ni][0] += v2 * v2; }
            }
            if (col + 1 < N) {
                float b1 = __ldg(&bias[col + 1]);
                float v1 = c[1] + b1, v3 = c[3] + b1;
                if (va) { C[(size_t)ra * N + col + 1] = v1; colS[ni][1] += v1; colQ[ni][1] += v1 * v1; }
                if (vb) { C[(size_t)rb * N + col + 1] = v3; colS[ni][1] += v3; colQ[ni][1] += v3 * v3; }
            }
        }
    }

    if (doStat) {
#pragma unroll
        for (int ni = 0; ni < NI; ni++)
#pragma unroll
            for (int p = 0; p < 2; p++) {
#pragma unroll
                for (int off = 4; off < 32; off <<= 1) {
                    colS[ni][p] += __shfl_xor_sync(0xFFFFFFFF, colS[ni][p], off);
                    colQ[ni][p] += __shfl_xor_sync(0xFFFFFFFF, colQ[ni][p], off);
                }
            }
        if (g == 0) {
#pragma unroll
            for (int ni = 0; ni < NI; ni++) {
                int ci = wn * (NI * 8) + ni * 8 + t * 2;
                atomicAdd(&s_sum[ci], colS[ni][0]);
                atomicAdd(&s_sq[ci], colQ[ni][0]);
                atomicAdd(&s_sum[ci + 1], colS[ni][1]);
                atomicAdd(&s_sq[ci + 1], colQ[ni][1]);
            }
        }
        __syncthreads();
        if (tid < BN) {
            atomicAdd(&g_colsum[col0 + tid], s_sum[tid]);
            atomicAdd(&g_colsq[col0 + tid], s_sq[tid]);
        }
    }
}

// smem sizes: NI=8/NT=2: (2*2560 + 5120)*3*4 = 122880; NI=4/NT=3: same 122880
#define GEMM_SMEM 122880

// ---------------- batch norm finalize (self-zeroing) ----------------
__global__ void bnfin_k(const float* __restrict__ gamma, const float* __restrict__ beta) {
    int j = blockIdx.x * blockDim.x + threadIdx.x;
    if (j >= HID) return;
    float mean = g_colsum[j] * (1.0f / NN);
    float var = g_colsq[j] * (1.0f / NN) - mean * mean;
    float rstd = rsqrtf(var + EPSF);
    float sc = rstd * gamma[j];
    g_scale[j] = sc;
    g_shift[j] = beta[j] - mean * sc;
    g_colsum[j] = 0.f;
    g_colsq[j] = 0.f;
}

// ---------------- host ----------------
static inline int cdiv(long long a, int b) { return (int)((a + b - 1) / b); }

extern "C" void kernel_launch(void* const* d_in, const int* in_sizes, int n_in,
                              void* d_out, int out_size) {
    const float* x = (const float*)d_in[0];
    const void* ei = d_in[1];

    const float* Wl[4] = {(const float*)d_in[2], (const float*)d_in[5],
                          (const float*)d_in[8], (const float*)d_in[11]};
    const float* bl[4] = {(const float*)d_in[3], (const float*)d_in[6],
                          (const float*)d_in[9], (const float*)d_in[12]};
    const float* Wr[4] = {(const float*)d_in[4], (const float*)d_in[7],
                          (const float*)d_in[10], (const float*)d_in[13]};
    const float* gam[3] = {(const float*)d_in[14], (const float*)d_in[16], (const float*)d_in[18]};
    const float* bet[3] = {(const float*)d_in[15], (const float*)d_in[17], (const float*)d_in[19]};
    float* out = (float*)d_out;

    cudaFuncSetAttribute(gemm_k<8, 2>, cudaFuncAttributeMaxDynamicSharedMemorySize, GEMM_SMEM);
    cudaFuncSetAttribute(gemm_k<4, 3>, cudaFuncAttributeMaxDynamicSharedMemorySize, GEMM_SMEM);

    // edge indices + CSR
    prep0_k<<<cdiv(NN, 256), 256>>>();
    detect_idx_k<<<128, 1024>>>((const long long*)ei);
    convert_count_k<<<cdiv(NE, 256), 256>>>(ei);
    scan1_k<<<NSB, 1024>>>();
    scan2_k<<<1, 64>>>();
    scan3_k<<<cdiv(NN, 256), 256>>>();
    fill_k<<<cdiv(NE, 256), 256>>>();
    split_all_k<<<cdiv(WTOT + XTOT, 256), 256>>>(Wl[0], Wr[0], Wl[1], Wr[1],
                                                 Wl[2], Wr[2], Wl[3], Wr[3], x);

    dim3 gwide(2, cdiv(NNP, 128));   // BN=256 tiles

    // ---- layer 1 (2-term, BN=256) ----
    gather50_k<<<NN, 64>>>(x);
    gemm_k<8, 2><<<gwide, 512, GEMM_SMEM>>>(0, 64, 64, OFF_WL1, OFF_WR1, bl[0], HID, 1, nullptr, 1);
    bnfin_k<<<2, 256>>>(gam[0], bet[0]);

    // ---- layers 2 & 3 (2-term, BN=256) ----
    for (int L = 1; L <= 2; ++L) {
        int wl = (L == 1) ? OFF_WL2 : OFF_WL3;
        int wr = (L == 1) ? OFF_WR2 : OFF_WR3;
        gather_bn_k<<<NN / 2, 256>>>();
        gemm_k<8, 2><<<gwide, 512, GEMM_SMEM>>>(1, 512, 512, wl, wr, bl[L], HID, 1, nullptr, 1);
        bnfin_k<<<2, 256>>>(gam[L], bet[L]);
    }

    // ---- layer 4 (3-term, BN=128, writes checked output) ----
    gather_bn_k<<<NN / 2, 256>>>();
    gemm_k<4, 3><<<dim3(1, cdiv(NNP, 128)), 512, GEMM_SMEM>>>(1, 512, 512, OFF_WL4, OFF_WR4,
                                                              bl[3], OUTF, 0, out, 0);
}

// round 14
// speedup vs baseline: 5.0638x; 1.0519x over previous
#include <cuda_runtime.h>
#include <cuda_fp16.h>

#define NN   50000
#define NNP  50048
#define NE   400000
#define INF  50
#define HID  512
#define OUTF 121
#define EPSF 1e-5f
#define NSB  49

// ---------------- device scratch (fp16 planes) ----------------
__device__ float g_invdeg[NN];
__device__ float g_h[(size_t)NNP * HID];
__device__ __half g_aggh[(size_t)NNP * HID];
__device__ __half g_aggl[(size_t)NNP * HID];
__device__ __half g_hbh[(size_t)NNP * HID];
__device__ __half g_hbl[(size_t)NNP * HID];
__device__ __half g_xh[(size_t)NNP * 64];
__device__ __half g_xl[(size_t)NNP * 64];
__device__ __half g_a1h[(size_t)NNP * 64];
__device__ __half g_a1l[(size_t)NNP * 64];

#define OFF_WL1 0
#define OFF_WR1 32768
#define OFF_WL2 65536
#define OFF_WR2 327680
#define OFF_WL3 589824
#define OFF_WR3 851968
#define OFF_WL4 1114112
#define OFF_WR4 1179648
#define WTOT    1245184
__device__ __half g_wh[WTOT];
__device__ __half g_wl[WTOT];

// per-layer BN stat buffers (3 BN layers)
__device__ float g_colsum[3 * HID], g_colsq[3 * HID];
__device__ int g_src[NE], g_dst[NE], g_csrc[NE];
__device__ int g_rowptr[NN + 1], g_cnt[NN], g_cursor[NN], g_is64;
__device__ int g_blksum[64], g_blkoff[64];

// ---------------- helpers ----------------
__device__ __forceinline__ unsigned s2u(const void* p) {
    unsigned a;
    asm("{ .reg .u64 t; cvta.to.shared.u64 t, %1; cvt.u32.u64 %0, t; }" : "=r"(a) : "l"(p));
    return a;
}
__device__ __forceinline__ void cp16(unsigned dst, const void* src) {
    asm volatile("cp.async.cg.shared.global [%0], [%1], 16;" :: "r"(dst), "l"(src));
}
__device__ __forceinline__ void split1(float v, __half& hi, __half& lo) {
    hi = __float2half_rn(v);
    lo = __float2half_rn(v - __half2float(hi));
}
__device__ __forceinline__ void mma_f16(float* c,
                                        unsigned a0, unsigned a1, unsigned a2, unsigned a3,
                                        unsigned b0, unsigned b1) {
    asm volatile(
        "mma.sync.aligned.m16n8k16.row.col.f32.f16.f16.f32 "
        "{%0,%1,%2,%3},{%4,%5,%6,%7},{%8,%9},{%0,%1,%2,%3};"
        : "+f"(c[0]), "+f"(c[1]), "+f"(c[2]), "+f"(c[3])
        : "r"(a0), "r"(a1), "r"(a2), "r"(a3), "r"(b0), "r"(b1));
}

// ---------------- prep ----------------
__global__ void prep0_k() {
    int i = blockIdx.x * blockDim.x + threadIdx.x;
    if (i == 0) g_is64 = 1;
    if (i < NN) g_cnt[i] = 0;
    if (i < 3 * HID) { g_colsum[i] = 0.f; g_colsq[i] = 0.f; }
}
__global__ void detect_idx_k(const long long* __restrict__ ei) {
    int stride = gridDim.x * blockDim.x;
    int bad = 0;
    for (int i = blockIdx.x * blockDim.x + threadIdx.x; i < NE; i += stride) {
        long long v = ei[i];
        if (v < 0 || v >= NN) { bad = 1; break; }
    }
    if (__syncthreads_or(bad)) {
        if (threadIdx.x == 0) atomicExch(&g_is64, 0);
    }
}
__global__ void convert_count_k(const void* __restrict__ ei) {
    int e = blockIdx.x * blockDim.x + threadIdx.x;
    if (e >= NE) return;
    int s, d;
    if (g_is64) {
        const long long* p = (const long long*)ei;
        s = (int)p[e]; d = (int)p[e + NE];
    } else {
        const int* p = (const int*)ei;
        s = p[e]; d = p[e + NE];
    }
    s = min(max(s, 0), NN - 1);
    d = min(max(d, 0), NN - 1);
    g_src[e] = s;
    g_dst[e] = d;
    atomicAdd(&g_cnt[d], 1);
}
__global__ void scan1_k() {
    __shared__ int sh[1024];
    int tid = threadIdx.x;
    int i = blockIdx.x * 1024 + tid;
    int v = (i < NN) ? g_cnt[i] : 0;
    sh[tid] = v;
    __syncthreads();
#pragma unroll
    for (int off = 1; off < 1024; off <<= 1) {
        int x = (tid >= off) ? sh[tid - off] : 0;
        __syncthreads();
        sh[tid] += x;
        __syncthreads();
    }
    if (i < NN) g_rowptr[i] = sh[tid] - v;
    if (tid == 1023) g_blksum[blockIdx.x] = sh[1023];
}
__global__ void scan2_k() {
    __shared__ int sh[64];
    int t = threadIdx.x;
    int v = (t < NSB) ? g_blksum[t] : 0;
    sh[t] = v;
    __syncthreads();
#pragma unroll
    for (int off = 1; off < 64; off <<= 1) {
        int x = (t >= off) ? sh[t - off] : 0;
        __syncthreads();
        sh[t] += x;
        __syncthreads();
    }
    if (t < 64) g_blkoff[t] = sh[t] - v;
}
__global__ void scan3_k() {
    int i = blockIdx.x * blockDim.x + threadIdx.x;
    if (i >= NN) return;
    g_rowptr[i] += g_blkoff[i >> 10];
    g_cursor[i] = 0;
    g_invdeg[i] = 1.0f / (float)max(g_cnt[i], 1);
    if (i == 0) g_rowptr[NN] = g_blkoff[NSB - 1] + g_blksum[NSB - 1];
}
__global__ void fill_k() {
    int e = blockIdx.x * blockDim.x + threadIdx.x;
    if (e >= NE) return;
    int d = g_dst[e];
    int slot = g_rowptr[d] + atomicAdd(&g_cursor[d], 1);
    g_csrc[slot] = g_src[e];
}

// ---------------- unified plane split ----------------
#define XTOT (NN * 64)
__global__ void split_all_k(const float* __restrict__ Wl1, const float* __restrict__ Wr1,
                            const float* __restrict__ Wl2, const float* __restrict__ Wr2,
                            const float* __restrict__ Wl3, const float* __restrict__ Wr3,
                            const float* __restrict__ Wl4, const float* __restrict__ Wr4,
                            const float* __restrict__ x) {
    int idx = blockIdx.x * blockDim.x + threadIdx.x;
    if (idx >= WTOT + XTOT) return;
    if (idx >= WTOT) {
        int i = idx - WTOT;
        int n = i >> 6, c = i & 63;
        float v = (c < INF) ? x[(size_t)n * INF + c] : 0.f;
        __half hi, lo;
        split1(v, hi, lo);
        g_xh[i] = hi;
        g_xl[i] = lo;
        return;
    }
    const float* W;
    int off, Kpad, K, N;
    if (idx < OFF_WL2) {
        Kpad = 64; K = INF; N = HID;
        if (idx < OFF_WR1) { W = Wl1; off = OFF_WL1; }
        else               { W = Wr1; off = OFF_WR1; }
    } else if (idx < OFF_WL4) {
        Kpad = 512; K = HID; N = HID;
        if (idx < OFF_WR2)      { W = Wl2; off = OFF_WL2; }
        else if (idx < OFF_WL3) { W = Wr2; off = OFF_WR2; }
        else if (idx < OFF_WR3) { W = Wl3; off = OFF_WL3; }
        else                    { W = Wr3; off = OFF_WR3; }
    } else {
        Kpad = 512; K = HID; N = OUTF;
        if (idx < OFF_WR4) { W = Wl4; off = OFF_WL4; }
        else               { W = Wr4; off = OFF_WR4; }
    }
    int local = idx - off;
    int n = local / Kpad, k = local - n * Kpad;
    float v = (n < N && k < K) ? W[(size_t)k * N + n] : 0.f;
    __half hi, lo;
    split1(v, hi, lo);
    g_wh[idx] = hi;
    g_wl[idx] = lo;
}

// ---------------- layer-1 gather ----------------
__global__ void gather50_k(const float* __restrict__ x) {
    int node = blockIdx.x;
    int t = threadIdx.x;
    float acc = 0.f;
    if (t < INF) {
        int beg = g_rowptr[node], end = g_rowptr[node + 1];
        for (int e = beg; e < end; ++e) acc += x[(size_t)g_csrc[e] * INF + t];
        acc *= g_invdeg[node];
    }
    __half hi, lo;
    split1(acc, hi, lo);
    g_a1h[(size_t)node * 64 + t] = hi;
    g_a1l[(size_t)node * 64 + t] = lo;
}

// ---------------- fused gather + inline-BN apply (2 nodes / 256-thread block) ----------------
// BN coefficients derived inline from per-layer stat buffers (no bnfin kernel).
__global__ void __launch_bounds__(256, 8)
gather_bn_k(const float* __restrict__ gamma, const float* __restrict__ beta, int si) {
    int half = threadIdx.x >> 7;
    int tid = threadIdx.x & 127;
    int node = blockIdx.x * 2 + half;
    if (node >= NN) return;
    size_t coff = (size_t)tid * 4;

    // inline BN coefficient computation
    float4 cs = *(const float4*)(g_colsum + si * HID + coff);
    float4 cq = *(const float4*)(g_colsq + si * HID + coff);
    float4 ga = *(const float4*)(gamma + coff);
    float4 be = *(const float4*)(beta + coff);
    const float invn = 1.0f / NN;
    float4 sc, sh;
    {
        float m, r;
        m = cs.x * invn; r = rsqrtf(cq.x * invn - m * m + EPSF); sc.x = r * ga.x; sh.x = be.x - m * sc.x;
        m = cs.y * invn; r = rsqrtf(cq.y * invn - m * m + EPSF); sc.y = r * ga.y; sh.y = be.y - m * sc.y;
        m = cs.z * invn; r = rsqrtf(cq.z * invn - m * m + EPSF); sc.z = r * ga.z; sh.z = be.z - m * sc.z;
        m = cs.w * invn; r = rsqrtf(cq.w * invn - m * m + EPSF); sc.w = r * ga.w; sh.w = be.w - m * sc.w;
    }

    // own row -> hb planes
    {
        float4 v = *(const float4*)(g_h + (size_t)node * HID + coff);
        float r0 = fmaxf(fmaf(v.x, sc.x, sh.x), 0.f);
        float r1 = fmaxf(fmaf(v.y, sc.y, sh.y), 0.f);
        float r2 = fmaxf(fmaf(v.z, sc.z, sh.z), 0.f);
        float r3 = fmaxf(fmaf(v.w, sc.w, sh.w), 0.f);
        __half h0, l0, h1, l1, h2, l2, h3, l3;
        split1(r0, h0, l0); split1(r1, h1, l1); split1(r2, h2, l2); split1(r3, h3, l3);
        size_t o = (size_t)node * HID + coff;
        *(ushort4*)(g_hbh + o) = make_ushort4(__half_as_ushort(h0), __half_as_ushort(h1),
                                              __half_as_ushort(h2), __half_as_ushort(h3));
        *(ushort4*)(g_hbl + o) = make_ushort4(__half_as_ushort(l0), __half_as_ushort(l1),
                                              __half_as_ushort(l2), __half_as_ushort(l3));
    }

    int beg = g_rowptr[node], end = g_rowptr[node + 1];
    float a0 = 0.f, a1 = 0.f, a2 = 0.f, a3 = 0.f;
    int e = beg;
#define GB_ACC(v) \
    a0 += fmaxf(fmaf((v).x, sc.x, sh.x), 0.f); \
    a1 += fmaxf(fmaf((v).y, sc.y, sh.y), 0.f); \
    a2 += fmaxf(fmaf((v).z, sc.z, sh.z), 0.f); \
    a3 += fmaxf(fmaf((v).w, sc.w, sh.w), 0.f)
    for (; e + 7 < end; e += 8) {
        float4 v0 = __ldcg((const float4*)(g_h + (size_t)g_csrc[e]     * HID + coff));
        float4 v1 = __ldcg((const float4*)(g_h + (size_t)g_csrc[e + 1] * HID + coff));
        float4 v2 = __ldcg((const float4*)(g_h + (size_t)g_csrc[e + 2] * HID + coff));
        float4 v3 = __ldcg((const float4*)(g_h + (size_t)g_csrc[e + 3] * HID + coff));
        float4 v4 = __ldcg((const float4*)(g_h + (size_t)g_csrc[e + 4] * HID + coff));
        float4 v5 = __ldcg((const float4*)(g_h + (size_t)g_csrc[e + 5] * HID + coff));
        float4 v6 = __ldcg((const float4*)(g_h + (size_t)g_csrc[e + 6] * HID + coff));
        float4 v7 = __ldcg((const float4*)(g_h + (size_t)g_csrc[e + 7] * HID + coff));
        GB_ACC(v0); GB_ACC(v1); GB_ACC(v2); GB_ACC(v3);
        GB_ACC(v4); GB_ACC(v5); GB_ACC(v6); GB_ACC(v7);
    }
    for (; e + 3 < end; e += 4) {
        float4 v0 = __ldcg((const float4*)(g_h + (size_t)g_csrc[e]     * HID + coff));
        float4 v1 = __ldcg((const float4*)(g_h + (size_t)g_csrc[e + 1] * HID + coff));
        float4 v2 = __ldcg((const float4*)(g_h + (size_t)g_csrc[e + 2] * HID + coff));
        float4 v3 = __ldcg((const float4*)(g_h + (size_t)g_csrc[e + 3] * HID + coff));
        GB_ACC(v0); GB_ACC(v1); GB_ACC(v2); GB_ACC(v3);
    }
    for (; e < end; ++e) {
        float4 v0 = __ldcg((const float4*)(g_h + (size_t)g_csrc[e] * HID + coff));
        GB_ACC(v0);
    }
#undef GB_ACC
    float inv = g_invdeg[node];
    a0 *= inv; a1 *= inv; a2 *= inv; a3 *= inv;
    __half h0, l0, h1, l1, h2, l2, h3, l3;
    split1(a0, h0, l0); split1(a1, h1, l1); split1(a2, h2, l2); split1(a3, h3, l3);
    size_t o = (size_t)node * HID + coff;
    *(ushort4*)(g_aggh + o) = make_ushort4(__half_as_ushort(h0), __half_as_ushort(h1),
                                           __half_as_ushort(h2), __half_as_ushort(h3));
    *(ushort4*)(g_aggl + o) = make_ushort4(__half_as_ushort(l0), __half_as_ushort(l1),
                                           __half_as_ushort(l2), __half_as_ushort(l3));
}

// ---------------- templated dual GEMM (NI col-groups/warp; NT split terms) ----------------
#define AW 20
#define ASZ (128 * AW)

template <int NI, int NT>
__global__ void __launch_bounds__(512, 1)
gemm_k(int aSel, int K1, int K2, int woff1, int woff2,
       const float* __restrict__ bias, int N, int cSel, float* __restrict__ cExt,
       int si) {
    constexpr int BN = NI * 32;
    constexpr int BSZ = BN * AW;
    constexpr int NB = (NT == 3) ? 2 : 1;
    constexpr int STGU = 2 * ASZ + NB * BSZ;

    extern __shared__ unsigned sm[];
    unsigned sbase = s2u(sm);
    __shared__ float s_sum[BN], s_sq[BN];

    const __half *A1h, *A1l, *A2h, *A2l;
    if (aSel == 0) { A1h = g_a1h; A1l = g_a1l; A2h = g_xh; A2l = g_xl; }
    else           { A1h = g_aggh; A1l = g_aggl; A2h = g_hbh; A2l = g_hbl; }
    const __half* B1h = g_wh + woff1;
    const __half* B1l = g_wl + woff1;
    const __half* B2h = g_wh + woff2;
    const __half* B2l = g_wl + woff2;
    float* C = (cSel == 1) ? g_h : cExt;
    bool doStat = (si >= 0);

    int tid = threadIdx.x;
    int warp = tid >> 5, lane = tid & 31;
    int wm = warp & 3, wn = warp >> 2;
    int g = lane >> 2, t = lane & 3;
    int row0 = blockIdx.y * 128;
    int col0 = blockIdx.x * BN;

    int S1 = K1 >> 5, S2 = K2 >> 5, S = S1 + S2;

    float acc[2][NI][4];
#pragma unroll
    for (int mi = 0; mi < 2; mi++)
#pragma unroll
        for (int ni = 0; ni < NI; ni++)
#pragma unroll
            for (int r = 0; r < 4; r++) acc[mi][ni][r] = 0.f;

    if (doStat && tid < BN) { s_sum[tid] = 0.f; s_sq[tid] = 0.f; }

    int prow = tid >> 2, pch = tid & 3;

    auto prefetch = [&](int s, int buf) {
        const __half *Ah, *Al, *Bh, *Bl;
        int ka, k0;
        if (s < S1) { Ah = A1h; Al = A1l; Bh = B1h; Bl = B1l; ka = K1; k0 = s * 32; }
        else        { Ah = A2h; Al = A2l; Bh = B2h; Bl = B2l; ka = K2; k0 = (s - S1) * 32; }
        unsigned base = sbase + buf * (STGU * 4);
        {
            unsigned d = base + prow * (AW * 4) + pch * 16;
            size_t aoff = (size_t)(row0 + prow) * ka + k0 + pch * 8;
            cp16(d,           Ah + aoff);
            cp16(d + ASZ * 4, Al + aoff);
        }
#pragma unroll
        for (int l = 0; l < NI / 4; l++) {
            int idx = tid + l * 512;
            int brow = idx >> 2, bch = idx & 3;
            unsigned d = base + 2 * ASZ * 4 + brow * (AW * 4) + bch * 16;
            size_t boff = (size_t)(col0 + brow) * ka + k0 + bch * 8;
            cp16(d, Bh + boff);
            if (NT == 3) cp16(d + BSZ * 4, Bl + boff);
        }
        asm volatile("cp.async.commit_group;" ::: "memory");
    };

    auto compute = [&](int buf) {
        const unsigned* Ah = sm + buf * STGU;
        const unsigned* Al = Ah + ASZ;
        const unsigned* Bh = Ah + 2 * ASZ;
        const unsigned* Bl = Bh + BSZ;
#pragma unroll
        for (int ks = 0; ks < 2; ks++) {
            int kb = ks * 8;
            unsigned ah[2][4], al[2][4];
#pragma unroll
            for (int mi = 0; mi < 2; mi++) {
                int rb = wm * 32 + mi * 16;
                int i0 = (rb + g) * AW + kb + t;
                int i1 = (rb + g + 8) * AW + kb + t;
                ah[mi][0] = Ah[i0];     al[mi][0] = Al[i0];
                ah[mi][1] = Ah[i1];     al[mi][1] = Al[i1];
                ah[mi][2] = Ah[i0 + 4]; al[mi][2] = Al[i0 + 4];
                ah[mi][3] = Ah[i1 + 4]; al[mi][3] = Al[i1 + 4];
            }
#pragma unroll
            for (int ni = 0; ni < NI; ni++) {
                int cb = (wn * (NI * 8) + ni * 8 + g) * AW + kb + t;
                unsigned b0 = Bh[cb];
                unsigned b1 = Bh[cb + 4];
#pragma unroll
                for (int mi = 0; mi < 2; mi++) {
                    float* c = acc[mi][ni];
                    mma_f16(c, ah[mi][0], ah[mi][1], ah[mi][2], ah[mi][3], b0, b1);
                    mma_f16(c, al[mi][0], al[mi][1], al[mi][2], al[mi][3], b0, b1);
                }
                if (NT == 3) {
                    unsigned bl0 = Bl[cb];
                    unsigned bl1 = Bl[cb + 4];
#pragma unroll
                    for (int mi = 0; mi < 2; mi++) {
                        float* c = acc[mi][ni];
                        mma_f16(c, ah[mi][0], ah[mi][1], ah[mi][2], ah[mi][3], bl0, bl1);
                    }
                }
            }
        }
    };

    prefetch(0, 0);
    if (S > 1) prefetch(1, 1);
#pragma unroll 1
    for (int s = 0; s < S; s++) {
        if (s + 1 < S) { asm volatile("cp.async.wait_group 1;" ::: "memory"); }
        else           { asm volatile("cp.async.wait_group 0;" ::: "memory"); }
        __syncthreads();
        if (s + 2 < S) prefetch(s + 2, (s + 2) % 3);
        compute(s % 3);
    }

    if (doStat) __syncthreads();

    float colS[NI][2], colQ[NI][2];
#pragma unroll
    for (int ni = 0; ni < NI; ni++) {
        colS[ni][0] = colS[ni][1] = 0.f;
        colQ[ni][0] = colQ[ni][1] = 0.f;
    }
#pragma unroll
    for (int mi = 0; mi < 2; mi++) {
        int ra = row0 + wm * 32 + mi * 16 + g;
        int rb = ra + 8;
        bool va = ra < NN, vb = rb < NN;
#pragma unroll
        for (int ni = 0; ni < NI; ni++) {
            int col = col0 + wn * (NI * 8) + ni * 8 + t * 2;
            float* c = acc[mi][ni];
            if (col < N) {
                float b0 = __ldg(&bias[col]);
                float v0 = c[0] + b0, v2 = c[2] + b0;
                if (va) { C[(size_t)ra * N + col] = v0; colS[ni][0] += v0; colQ[ni][0] += v0 * v0; }
                if (vb) { C[(size_t)rb * N + col] = v2; colS[ni][0] += v2; colQ[ni][0] += v2 * v2; }
            }
            if (col + 1 < N) {
                float b1 = __ldg(&bias[col + 1]);
                float v1 = c[1] + b1, v3 = c[3] + b1;
                if (va) { C[(size_t)ra * N + col + 1] = v1; colS[ni][1] += v1; colQ[ni][1] += v1 * v1; }
                if (vb) { C[(size_t)rb * N + col + 1] = v3; colS[ni][1] += v3; colQ[ni][1] += v3 * v3; }
            }
        }
    }

    if (doStat) {
#pragma unroll
        for (int ni = 0; ni < NI; ni++)
#pragma unroll
            for (int p = 0; p < 2; p++) {
#pragma unroll
                for (int off = 4; off < 32; off <<= 1) {
                    colS[ni][p] += __shfl_xor_sync(0xFFFFFFFF, colS[ni][p], off);
                    colQ[ni][p] += __shfl_xor_sync(0xFFFFFFFF, colQ[ni][p], off);
                }
            }
        if (g == 0) {
#pragma unroll
            for (int ni = 0; ni < NI; ni++) {
                int ci = wn * (NI * 8) + ni * 8 + t * 2;
                atomicAdd(&s_sum[ci], colS[ni][0]);
                atomicAdd(&s_sq[ci], colQ[ni][0]);
                atomicAdd(&s_sum[ci + 1], colS[ni][1]);
                atomicAdd(&s_sq[ci + 1], colQ[ni][1]);
            }
        }
        __syncthreads();
        if (tid < BN) {
            atomicAdd(&g_colsum[si * HID + col0 + tid], s_sum[tid]);
            atomicAdd(&g_colsq[si * HID + col0 + tid], s_sq[tid]);
        }
    }
}

#define GEMM_SMEM 122880

// ---------------- host ----------------
static inline int cdiv(long long a, int b) { return (int)((a + b - 1) / b); }

extern "C" void kernel_launch(void* const* d_in, const int* in_sizes, int n_in,
                              void* d_out, int out_size) {
    const float* x = (const float*)d_in[0];
    const void* ei = d_in[1];

    const float* Wl[4] = {(const float*)d_in[2], (const float*)d_in[5],
                          (const float*)d_in[8], (const float*)d_in[11]};
    const float* bl[4] = {(const float*)d_in[3], (const float*)d_in[6],
                          (const float*)d_in[9], (const float*)d_in[12]};
    const float* Wr[4] = {(const float*)d_in[4], (const float*)d_in[7],
                          (const float*)d_in[10], (const float*)d_in[13]};
    const float* gam[3] = {(const float*)d_in[14], (const float*)d_in[16], (const float*)d_in[18]};
    const float* bet[3] = {(const float*)d_in[15], (const float*)d_in[17], (const float*)d_in[19]};
    float* out = (float*)d_out;

    cudaFuncSetAttribute(gemm_k<8, 2>, cudaFuncAttributeMaxDynamicSharedMemorySize, GEMM_SMEM);
    cudaFuncSetAttribute(gemm_k<4, 3>, cudaFuncAttributeMaxDynamicSharedMemorySize, GEMM_SMEM);

    // edge indices + CSR
    prep0_k<<<cdiv(NN, 256), 256>>>();
    detect_idx_k<<<128, 1024>>>((const long long*)ei);
    convert_count_k<<<cdiv(NE, 256), 256>>>(ei);
    scan1_k<<<NSB, 1024>>>();
    scan2_k<<<1, 64>>>();
    scan3_k<<<cdiv(NN, 256), 256>>>();
    fill_k<<<cdiv(NE, 256), 256>>>();
    split_all_k<<<cdiv(WTOT + XTOT, 256), 256>>>(Wl[0], Wr[0], Wl[1], Wr[1],
                                                 Wl[2], Wr[2], Wl[3], Wr[3], x);

    dim3 gwide(2, cdiv(NNP, 128));

    // ---- layer 1 (2-term, BN=256; stats -> buf 0) ----
    gather50_k<<<NN, 64>>>(x);
    gemm_k<8, 2><<<gwide, 512, GEMM_SMEM>>>(0, 64, 64, OFF_WL1, OFF_WR1, bl[0], HID, 1, nullptr, 0);

    // ---- layers 2 & 3 (2-term, BN=256) ----
    for (int L = 1; L <= 2; ++L) {
        int wl = (L == 1) ? OFF_WL2 : OFF_WL3;
        int wr = (L == 1) ? OFF_WR2 : OFF_WR3;
        gather_bn_k<<<NN / 2, 256>>>(gam[L - 1], bet[L - 1], L - 1);
        gemm_k<8, 2><<<gwide, 512, GEMM_SMEM>>>(1, 512, 512, wl, wr, bl[L], HID, 1, nullptr, L);
    }

    // ---- layer 4 (3-term, BN=128, writes checked output) ----
    gather_bn_k<<<NN / 2, 256>>>(gam[2], bet[2], 2);
    gemm_k<4, 3><<<dim3(1, cdiv(NNP, 128)), 512, GEMM_SMEM>>>(1, 512, 512, OFF_WL4, OFF_WR4,
                                                              bl[3], OUTF, 0, out, -1);
}

// round 15
// speedup vs baseline: 5.5828x; 1.1025x over previous
#include <cuda_runtime.h>
#include <cuda_fp16.h>

#define NN   50000
#define NNP  50048
#define NE   400000
#define INF  50
#define HID  512
#define OUTF 121
#define EPSF 1e-5f
#define NSB  49

// ---------------- device scratch (fp16 planes) ----------------
__device__ float g_invdeg[NN];
__device__ __half g_hh[(size_t)NNP * HID];   // inter-layer h, fp16 hi only
__device__ __half g_aggh[(size_t)NNP * HID];
__device__ __half g_aggl[(size_t)NNP * HID];
__device__ __half g_hbh[(size_t)NNP * HID];
__device__ __half g_hbl[(size_t)NNP * HID];
__device__ __half g_xh[(size_t)NNP * 64];
__device__ __half g_xl[(size_t)NNP * 64];
__device__ __half g_a1h[(size_t)NNP * 64];
__device__ __half g_a1l[(size_t)NNP * 64];

#define OFF_WL1 0
#define OFF_WR1 32768
#define OFF_WL2 65536
#define OFF_WR2 327680
#define OFF_WL3 589824
#define OFF_WR3 851968
#define OFF_WL4 1114112
#define OFF_WR4 1179648
#define WTOT    1245184
__device__ __half g_wh[WTOT];
__device__ __half g_wl[WTOT];

// per-layer BN stat buffers (3 BN layers)
__device__ float g_colsum[3 * HID], g_colsq[3 * HID];
__device__ int g_src[NE], g_dst[NE], g_csrc[NE];
__device__ int g_rowptr[NN + 1], g_cnt[NN], g_cursor[NN], g_is64;
__device__ int g_blksum[64], g_blkoff[64];

// ---------------- helpers ----------------
__device__ __forceinline__ unsigned s2u(const void* p) {
    unsigned a;
    asm("{ .reg .u64 t; cvta.to.shared.u64 t, %1; cvt.u32.u64 %0, t; }" : "=r"(a) : "l"(p));
    return a;
}
__device__ __forceinline__ void cp16(unsigned dst, const void* src) {
    asm volatile("cp.async.cg.shared.global [%0], [%1], 16;" :: "r"(dst), "l"(src));
}
__device__ __forceinline__ void split1(float v, __half& hi, __half& lo) {
    hi = __float2half_rn(v);
    lo = __float2half_rn(v - __half2float(hi));
}
// load 4 halves (8B) streaming, convert to float4
__device__ __forceinline__ float4 ldh4cg(const __half* p) {
    uint2 u = __ldcg((const uint2*)p);
    __half2 a = *(__half2*)&u.x;
    __half2 b = *(__half2*)&u.y;
    float2 fa = __half22float2(a);
    float2 fb = __half22float2(b);
    return make_float4(fa.x, fa.y, fb.x, fb.y);
}
__device__ __forceinline__ float4 ldh4(const __half* p) {
    uint2 u = *(const uint2*)p;
    __half2 a = *(__half2*)&u.x;
    __half2 b = *(__half2*)&u.y;
    float2 fa = __half22float2(a);
    float2 fb = __half22float2(b);
    return make_float4(fa.x, fa.y, fb.x, fb.y);
}
__device__ __forceinline__ void mma_f16(float* c,
                                        unsigned a0, unsigned a1, unsigned a2, unsigned a3,
                                        unsigned b0, unsigned b1) {
    asm volatile(
        "mma.sync.aligned.m16n8k16.row.col.f32.f16.f16.f32 "
        "{%0,%1,%2,%3},{%4,%5,%6,%7},{%8,%9},{%0,%1,%2,%3};"
        : "+f"(c[0]), "+f"(c[1]), "+f"(c[2]), "+f"(c[3])
        : "r"(a0), "r"(a1), "r"(a2), "r"(a3), "r"(b0), "r"(b1));
}

// ---------------- prep ----------------
__global__ void prep0_k() {
    int i = blockIdx.x * blockDim.x + threadIdx.x;
    if (i == 0) g_is64 = 1;
    if (i < NN) g_cnt[i] = 0;
    if (i < 3 * HID) { g_colsum[i] = 0.f; g_colsq[i] = 0.f; }
}
__global__ void detect_idx_k(const long long* __restrict__ ei) {
    int stride = gridDim.x * blockDim.x;
    int bad = 0;
    for (int i = blockIdx.x * blockDim.x + threadIdx.x; i < NE; i += stride) {
        long long v = ei[i];
        if (v < 0 || v >= NN) { bad = 1; break; }
    }
    if (__syncthreads_or(bad)) {
        if (threadIdx.x == 0) atomicExch(&g_is64, 0);
    }
}
__global__ void convert_count_k(const void* __restrict__ ei) {
    int e = blockIdx.x * blockDim.x + threadIdx.x;
    if (e >= NE) return;
    int s, d;
    if (g_is64) {
        const long long* p = (const long long*)ei;
        s = (int)p[e]; d = (int)p[e + NE];
    } else {
        const int* p = (const int*)ei;
        s = p[e]; d = p[e + NE];
    }
    s = min(max(s, 0), NN - 1);
    d = min(max(d, 0), NN - 1);
    g_src[e] = s;
    g_dst[e] = d;
    atomicAdd(&g_cnt[d], 1);
}
__global__ void scan1_k() {
    __shared__ int sh[1024];
    int tid = threadIdx.x;
    int i = blockIdx.x * 1024 + tid;
    int v = (i < NN) ? g_cnt[i] : 0;
    sh[tid] = v;
    __syncthreads();
#pragma unroll
    for (int off = 1; off < 1024; off <<= 1) {
        int x = (tid >= off) ? sh[tid - off] : 0;
        __syncthreads();
        sh[tid] += x;
        __syncthreads();
    }
    if (i < NN) g_rowptr[i] = sh[tid] - v;
    if (tid == 1023) g_blksum[blockIdx.x] = sh[1023];
}
__global__ void scan2_k() {
    __shared__ int sh[64];
    int t = threadIdx.x;
    int v = (t < NSB) ? g_blksum[t] : 0;
    sh[t] = v;
    __syncthreads();
#pragma unroll
    for (int off = 1; off < 64; off <<= 1) {
        int x = (t >= off) ? sh[t - off] : 0;
        __syncthreads();
        sh[t] += x;
        __syncthreads();
    }
    if (t < 64) g_blkoff[t] = sh[t] - v;
}
__global__ void scan3_k() {
    int i = blockIdx.x * blockDim.x + threadIdx.x;
    if (i >= NN) return;
    g_rowptr[i] += g_blkoff[i >> 10];
    g_cursor[i] = 0;
    g_invdeg[i] = 1.0f / (float)max(g_cnt[i], 1);
    if (i == 0) g_rowptr[NN] = g_blkoff[NSB - 1] + g_blksum[NSB - 1];
}
__global__ void fill_k() {
    int e = blockIdx.x * blockDim.x + threadIdx.x;
    if (e >= NE) return;
    int d = g_dst[e];
    int slot = g_rowptr[d] + atomicAdd(&g_cursor[d], 1);
    g_csrc[slot] = g_src[e];
}

// ---------------- unified plane split ----------------
#define XTOT (NN * 64)
__global__ void split_all_k(const float* __restrict__ Wl1, const float* __restrict__ Wr1,
                            const float* __restrict__ Wl2, const float* __restrict__ Wr2,
                            const float* __restrict__ Wl3, const float* __restrict__ Wr3,
                            const float* __restrict__ Wl4, const float* __restrict__ Wr4,
                            const float* __restrict__ x) {
    int idx = blockIdx.x * blockDim.x + threadIdx.x;
    if (idx >= WTOT + XTOT) return;
    if (idx >= WTOT) {
        int i = idx - WTOT;
        int n = i >> 6, c = i & 63;
        float v = (c < INF) ? x[(size_t)n * INF + c] : 0.f;
        __half hi, lo;
        split1(v, hi, lo);
        g_xh[i] = hi;
        g_xl[i] = lo;
        return;
    }
    const float* W;
    int off, Kpad, K, N;
    if (idx < OFF_WL2) {
        Kpad = 64; K = INF; N = HID;
        if (idx < OFF_WR1) { W = Wl1; off = OFF_WL1; }
        else               { W = Wr1; off = OFF_WR1; }
    } else if (idx < OFF_WL4) {
        Kpad = 512; K = HID; N = HID;
        if (idx < OFF_WR2)      { W = Wl2; off = OFF_WL2; }
        else if (idx < OFF_WL3) { W = Wr2; off = OFF_WR2; }
        else if (idx < OFF_WR3) { W = Wl3; off = OFF_WL3; }
        else                    { W = Wr3; off = OFF_WR3; }
    } else {
        Kpad = 512; K = HID; N = OUTF;
        if (idx < OFF_WR4) { W = Wl4; off = OFF_WL4; }
        else               { W = Wr4; off = OFF_WR4; }
    }
    int local = idx - off;
    int n = local / Kpad, k = local - n * Kpad;
    float v = (n < N && k < K) ? W[(size_t)k * N + n] : 0.f;
    __half hi, lo;
    split1(v, hi, lo);
    g_wh[idx] = hi;
    g_wl[idx] = lo;
}

// ---------------- layer-1 gather ----------------
__global__ void gather50_k(const float* __restrict__ x) {
    int node = blockIdx.x;
    int t = threadIdx.x;
    float acc = 0.f;
    if (t < INF) {
        int beg = g_rowptr[node], end = g_rowptr[node + 1];
        for (int e = beg; e < end; ++e) acc += x[(size_t)g_csrc[e] * INF + t];
        acc *= g_invdeg[node];
    }
    __half hi, lo;
    split1(acc, hi, lo);
    g_a1h[(size_t)node * 64 + t] = hi;
    g_a1l[(size_t)node * 64 + t] = lo;
}

// ---------------- fused gather + inline-BN apply (fp16 h stream) ----------------
__global__ void __launch_bounds__(256, 8)
gather_bn_k(const float* __restrict__ gamma, const float* __restrict__ beta, int si) {
    int half_ = threadIdx.x >> 7;
    int tid = threadIdx.x & 127;
    int node = blockIdx.x * 2 + half_;
    if (node >= NN) return;
    size_t coff = (size_t)tid * 4;

    float4 cs = *(const float4*)(g_colsum + si * HID + coff);
    float4 cq = *(const float4*)(g_colsq + si * HID + coff);
    float4 ga = *(const float4*)(gamma + coff);
    float4 be = *(const float4*)(beta + coff);
    const float invn = 1.0f / NN;
    float4 sc, sh;
    {
        float m, r;
        m = cs.x * invn; r = rsqrtf(cq.x * invn - m * m + EPSF); sc.x = r * ga.x; sh.x = be.x - m * sc.x;
        m = cs.y * invn; r = rsqrtf(cq.y * invn - m * m + EPSF); sc.y = r * ga.y; sh.y = be.y - m * sc.y;
        m = cs.z * invn; r = rsqrtf(cq.z * invn - m * m + EPSF); sc.z = r * ga.z; sh.z = be.z - m * sc.z;
        m = cs.w * invn; r = rsqrtf(cq.w * invn - m * m + EPSF); sc.w = r * ga.w; sh.w = be.w - m * sc.w;
    }

    // own row -> hb planes
    {
        float4 v = ldh4(g_hh + (size_t)node * HID + coff);
        float r0 = fmaxf(fmaf(v.x, sc.x, sh.x), 0.f);
        float r1 = fmaxf(fmaf(v.y, sc.y, sh.y), 0.f);
        float r2 = fmaxf(fmaf(v.z, sc.z, sh.z), 0.f);
        float r3 = fmaxf(fmaf(v.w, sc.w, sh.w), 0.f);
        __half h0, l0, h1, l1, h2, l2, h3, l3;
        split1(r0, h0, l0); split1(r1, h1, l1); split1(r2, h2, l2); split1(r3, h3, l3);
        size_t o = (size_t)node * HID + coff;
        *(ushort4*)(g_hbh + o) = make_ushort4(__half_as_ushort(h0), __half_as_ushort(h1),
                                              __half_as_ushort(h2), __half_as_ushort(h3));
        *(ushort4*)(g_hbl + o) = make_ushort4(__half_as_ushort(l0), __half_as_ushort(l1),
                                              __half_as_ushort(l2), __half_as_ushort(l3));
    }

    int beg = g_rowptr[node], end = g_rowptr[node + 1];
    float a0 = 0.f, a1 = 0.f, a2 = 0.f, a3 = 0.f;
    int e = beg;
#define GB_ACC(v) \
    a0 += fmaxf(fmaf((v).x, sc.x, sh.x), 0.f); \
    a1 += fmaxf(fmaf((v).y, sc.y, sh.y), 0.f); \
    a2 += fmaxf(fmaf((v).z, sc.z, sh.z), 0.f); \
    a3 += fmaxf(fmaf((v).w, sc.w, sh.w), 0.f)
    for (; e + 7 < end; e += 8) {
        float4 v0 = ldh4cg(g_hh + (size_t)g_csrc[e]     * HID + coff);
        float4 v1 = ldh4cg(g_hh + (size_t)g_csrc[e + 1] * HID + coff);
        float4 v2 = ldh4cg(g_hh + (size_t)g_csrc[e + 2] * HID + coff);
        float4 v3 = ldh4cg(g_hh + (size_t)g_csrc[e + 3] * HID + coff);
        float4 v4 = ldh4cg(g_hh + (size_t)g_csrc[e + 4] * HID + coff);
        float4 v5 = ldh4cg(g_hh + (size_t)g_csrc[e + 5] * HID + coff);
        float4 v6 = ldh4cg(g_hh + (size_t)g_csrc[e + 6] * HID + coff);
        float4 v7 = ldh4cg(g_hh + (size_t)g_csrc[e + 7] * HID + coff);
        GB_ACC(v0); GB_ACC(v1); GB_ACC(v2); GB_ACC(v3);
        GB_ACC(v4); GB_ACC(v5); GB_ACC(v6); GB_ACC(v7);
    }
    for (; e + 3 < end; e += 4) {
        float4 v0 = ldh4cg(g_hh + (size_t)g_csrc[e]     * HID + coff);
        float4 v1 = ldh4cg(g_hh + (size_t)g_csrc[e + 1] * HID + coff);
        float4 v2 = ldh4cg(g_hh + (size_t)g_csrc[e + 2] * HID + coff);
        float4 v3 = ldh4cg(g_hh + (size_t)g_csrc[e + 3] * HID + coff);
        GB_ACC(v0); GB_ACC(v1); GB_ACC(v2); GB_ACC(v3);
    }
    for (; e < end; ++e) {
        float4 v0 = ldh4cg(g_hh + (size_t)g_csrc[e] * HID + coff);
        GB_ACC(v0);
    }
#undef GB_ACC
    float inv = g_invdeg[node];
    a0 *= inv; a1 *= inv; a2 *= inv; a3 *= inv;
    __half h0, l0, h1, l1, h2, l2, h3, l3;
    split1(a0, h0, l0); split1(a1, h1, l1); split1(a2, h2, l2); split1(a3, h3, l3);
    size_t o = (size_t)node * HID + coff;
    *(ushort4*)(g_aggh + o) = make_ushort4(__half_as_ushort(h0), __half_as_ushort(h1),
                                           __half_as_ushort(h2), __half_as_ushort(h3));
    *(ushort4*)(g_aggl + o) = make_ushort4(__half_as_ushort(l0), __half_as_ushort(l1),
                                           __half_as_ushort(l2), __half_as_ushort(l3));
}

// ---------------- templated dual GEMM (NI col-groups/warp; NT split terms) ----------------
#define AW 20
#define ASZ (128 * AW)

template <int NI, int NT>
__global__ void __launch_bounds__(512, 1)
gemm_k(int aSel, int K1, int K2, int woff1, int woff2,
       const float* __restrict__ bias, int N, int cSel, float* __restrict__ cExt,
       int si) {
    constexpr int BN = NI * 32;
    constexpr int BSZ = BN * AW;
    constexpr int NB = (NT == 3) ? 2 : 1;
    constexpr int STGU = 2 * ASZ + NB * BSZ;

    extern __shared__ unsigned sm[];
    unsigned sbase = s2u(sm);
    __shared__ float s_sum[BN], s_sq[BN];

    const __half *A1h, *A1l, *A2h, *A2l;
    if (aSel == 0) { A1h = g_a1h; A1l = g_a1l; A2h = g_xh; A2l = g_xl; }
    else           { A1h = g_aggh; A1l = g_aggl; A2h = g_hbh; A2l = g_hbl; }
    const __half* B1h = g_wh + woff1;
    const __half* B1l = g_wl + woff1;
    const __half* B2h = g_wh + woff2;
    const __half* B2l = g_wl + woff2;
    bool doStat = (si >= 0);

    int tid = threadIdx.x;
    int warp = tid >> 5, lane = tid & 31;
    int wm = warp & 3, wn = warp >> 2;
    int g = lane >> 2, t = lane & 3;
    int row0 = blockIdx.y * 128;
    int col0 = blockIdx.x * BN;

    int S1 = K1 >> 5, S2 = K2 >> 5, S = S1 + S2;

    float acc[2][NI][4];
#pragma unroll
    for (int mi = 0; mi < 2; mi++)
#pragma unroll
        for (int ni = 0; ni < NI; ni++)
#pragma unroll
            for (int r = 0; r < 4; r++) acc[mi][ni][r] = 0.f;

    if (doStat && tid < BN) { s_sum[tid] = 0.f; s_sq[tid] = 0.f; }

    int prow = tid >> 2, pch = tid & 3;

    auto prefetch = [&](int s, int buf) {
        const __half *Ah, *Al, *Bh, *Bl;
        int ka, k0;
        if (s < S1) { Ah = A1h; Al = A1l; Bh = B1h; Bl = B1l; ka = K1; k0 = s * 32; }
        else        { Ah = A2h; Al = A2l; Bh = B2h; Bl = B2l; ka = K2; k0 = (s - S1) * 32; }
        unsigned base = sbase + buf * (STGU * 4);
        {
            unsigned d = base + prow * (AW * 4) + pch * 16;
            size_t aoff = (size_t)(row0 + prow) * ka + k0 + pch * 8;
            cp16(d,           Ah + aoff);
            cp16(d + ASZ * 4, Al + aoff);
        }
#pragma unroll
        for (int l = 0; l < NI / 4; l++) {
            int idx = tid + l * 512;
            int brow = idx >> 2, bch = idx & 3;
            unsigned d = base + 2 * ASZ * 4 + brow * (AW * 4) + bch * 16;
            size_t boff = (size_t)(col0 + brow) * ka + k0 + bch * 8;
            cp16(d, Bh + boff);
            if (NT == 3) cp16(d + BSZ * 4, Bl + boff);
        }
        asm volatile("cp.async.commit_group;" ::: "memory");
    };

    auto compute = [&](int buf) {
        const unsigned* Ah = sm + buf * STGU;
        const unsigned* Al = Ah + ASZ;
        const unsigned* Bh = Ah + 2 * ASZ;
        const unsigned* Bl = Bh + BSZ;
#pragma unroll
        for (int ks = 0; ks < 2; ks++) {
            int kb = ks * 8;
            unsigned ah[2][4], al[2][4];
#pragma unroll
            for (int mi = 0; mi < 2; mi++) {
                int rb = wm * 32 + mi * 16;
                int i0 = (rb + g) * AW + kb + t;
                int i1 = (rb + g + 8) * AW + kb + t;
                ah[mi][0] = Ah[i0];     al[mi][0] = Al[i0];
                ah[mi][1] = Ah[i1];     al[mi][1] = Al[i1];
                ah[mi][2] = Ah[i0 + 4]; al[mi][2] = Al[i0 + 4];
                ah[mi][3] = Ah[i1 + 4]; al[mi][3] = Al[i1 + 4];
            }
#pragma unroll
            for (int ni = 0; ni < NI; ni++) {
                int cb = (wn * (NI * 8) + ni * 8 + g) * AW + kb + t;
                unsigned b0 = Bh[cb];
                unsigned b1 = Bh[cb + 4];
#pragma unroll
                for (int mi = 0; mi < 2; mi++) {
                    float* c = acc[mi][ni];
                    mma_f16(c, ah[mi][0], ah[mi][1], ah[mi][2], ah[mi][3], b0, b1);
                    mma_f16(c, al[mi][0], al[mi][1], al[mi][2], al[mi][3], b0, b1);
                }
                if (NT == 3) {
                    unsigned bl0 = Bl[cb];
                    unsigned bl1 = Bl[cb + 4];
#pragma unroll
                    for (int mi = 0; mi < 2; mi++) {
                        float* c = acc[mi][ni];
                        mma_f16(c, ah[mi][0], ah[mi][1], ah[mi][2], ah[mi][3], bl0, bl1);
                    }
                }
            }
        }
    };

    prefetch(0, 0);
    if (S > 1) prefetch(1, 1);
#pragma unroll 1
    for (int s = 0; s < S; s++) {
        if (s + 1 < S) { asm volatile("cp.async.wait_group 1;" ::: "memory"); }
        else           { asm volatile("cp.async.wait_group 0;" ::: "memory"); }
        __syncthreads();
        if (s + 2 < S) prefetch(s + 2, (s + 2) % 3);
        compute(s % 3);
    }

    if (doStat) __syncthreads();

    float colS[NI][2], colQ[NI][2];
#pragma unroll
    for (int ni = 0; ni < NI; ni++) {
        colS[ni][0] = colS[ni][1] = 0.f;
        colQ[ni][0] = colQ[ni][1] = 0.f;
    }
#pragma unroll
    for (int mi = 0; mi < 2; mi++) {
        int ra = row0 + wm * 32 + mi * 16 + g;
        int rb = ra + 8;
        bool va = ra < NN, vb = rb < NN;
#pragma unroll
        for (int ni = 0; ni < NI; ni++) {
            int col = col0 + wn * (NI * 8) + ni * 8 + t * 2;
            float* c = acc[mi][ni];
            if (col + 1 < N) {
                float b0 = __ldg(&bias[col]);
                float b1 = __ldg(&bias[col + 1]);
                float v0 = c[0] + b0, v1 = c[1] + b1;
                float v2 = c[2] + b0, v3 = c[3] + b1;
                if (cSel == 1) {
                    if (va) *(  __half2*)(g_hh + (size_t)ra * N + col) = __floats2half2_rn(v0, v1);
                    if (vb) *(  __half2*)(g_hh + (size_t)rb * N + col) = __floats2half2_rn(v2, v3);
                } else {
                    if (va) { cExt[(size_t)ra * N + col] = v0; cExt[(size_t)ra * N + col + 1] = v1; }
                    if (vb) { cExt[(size_t)rb * N + col] = v2; cExt[(size_t)rb * N + col + 1] = v3; }
                }
                if (va) { colS[ni][0] += v0; colQ[ni][0] += v0 * v0;
                          colS[ni][1] += v1; colQ[ni][1] += v1 * v1; }
                if (vb) { colS[ni][0] += v2; colQ[ni][0] += v2 * v2;
                          colS[ni][1] += v3; colQ[ni][1] += v3 * v3; }
            } else if (col < N) {
                float b0 = __ldg(&bias[col]);
                float v0 = c[0] + b0, v2 = c[2] + b0;
                if (cSel == 1) {
                    if (va) g_hh[(size_t)ra * N + col] = __float2half_rn(v0);
                    if (vb) g_hh[(size_t)rb * N + col] = __float2half_rn(v2);
                } else {
                    if (va) cExt[(size_t)ra * N + col] = v0;
                    if (vb) cExt[(size_t)rb * N + col] = v2;
                }
                if (va) { colS[ni][0] += v0; colQ[ni][0] += v0 * v0; }
                if (vb) { colS[ni][0] += v2; colQ[ni][0] += v2 * v2; }
            }
        }
    }

    if (doStat) {
#pragma unroll
        for (int ni = 0; ni < NI; ni++)
#pragma unroll
            for (int p = 0; p < 2; p++) {
#pragma unroll
                for (int off = 4; off < 32; off <<= 1) {
                    colS[ni][p] += __shfl_xor_sync(0xFFFFFFFF, colS[ni][p], off);
                    colQ[ni][p] += __shfl_xor_sync(0xFFFFFFFF, colQ[ni][p], off);
                }
            }
        if (g == 0) {
#pragma unroll
            for (int ni = 0; ni < NI; ni++) {
                int ci = wn * (NI * 8) + ni * 8 + t * 2;
                atomicAdd(&s_sum[ci], colS[ni][0]);
                atomicAdd(&s_sq[ci], colQ[ni][0]);
                atomicAdd(&s_sum[ci + 1], colS[ni][1]);
                atomicAdd(&s_sq[ci + 1], colQ[ni][1]);
            }
        }
        __syncthreads();
        if (tid < BN) {
            atomicAdd(&g_colsum[si * HID + col0 + tid], s_sum[tid]);
            atomicAdd(&g_colsq[si * HID + col0 + tid], s_sq[tid]);
        }
    }
}

#define GEMM_SMEM 122880

// ---------------- host ----------------
static inline int cdiv(long long a, int b) { return (int)((a + b - 1) / b); }

extern "C" void kernel_launch(void* const* d_in, const int* in_sizes, int n_in,
                              void* d_out, int out_size) {
    const float* x = (const float*)d_in[0];
    const void* ei = d_in[1];

    const float* Wl[4] = {(const float*)d_in[2], (const float*)d_in[5],
                          (const float*)d_in[8], (const float*)d_in[11]};
    const float* bl[4] = {(const float*)d_in[3], (const float*)d_in[6],
                          (const float*)d_in[9], (const float*)d_in[12]};
    const float* Wr[4] = {(const float*)d_in[4], (const float*)d_in[7],
                          (const float*)d_in[10], (const float*)d_in[13]};
    const float* gam[3] = {(const float*)d_in[14], (const float*)d_in[16], (const float*)d_in[18]};
    const float* bet[3] = {(const float*)d_in[15], (const float*)d_in[17], (const float*)d_in[19]};
    float* out = (float*)d_out;

    cudaFuncSetAttribute(gemm_k<8, 2>, cudaFuncAttributeMaxDynamicSharedMemorySize, GEMM_SMEM);
    cudaFuncSetAttribute(gemm_k<4, 3>, cudaFuncAttributeMaxDynamicSharedMemorySize, GEMM_SMEM);

    // edge indices + CSR
    prep0_k<<<cdiv(NN, 256), 256>>>();
    detect_idx_k<<<128, 1024>>>((const long long*)ei);
    convert_count_k<<<cdiv(NE, 256), 256>>>(ei);
    scan1_k<<<NSB, 1024>>>();
    scan2_k<<<1, 64>>>();
    scan3_k<<<cdiv(NN, 256), 256>>>();
    fill_k<<<cdiv(NE, 256), 256>>>();
    split_all_k<<<cdiv(WTOT + XTOT, 256), 256>>>(Wl[0], Wr[0], Wl[1], Wr[1],
                                                 Wl[2], Wr[2], Wl[3], Wr[3], x);

    dim3 gwide(2, cdiv(NNP, 128));

    // ---- layer 1 (2-term, BN=256; stats -> buf 0) ----
    gather50_k<<<NN, 64>>>(x);
    gemm_k<8, 2><<<gwide, 512, GEMM_SMEM>>>(0, 64, 64, OFF_WL1, OFF_WR1, bl[0], HID, 1, nullptr, 0);

    // ---- layers 2 & 3 (2-term, BN=256) ----
    for (int L = 1; L <= 2; ++L) {
        int wl = (L == 1) ? OFF_WL2 : OFF_WL3;
        int wr = (L == 1) ? OFF_WR2 : OFF_WR3;
        gather_bn_k<<<NN / 2, 256>>>(gam[L - 1], bet[L - 1], L - 1);
        gemm_k<8, 2><<<gwide, 512, GEMM_SMEM>>>(1, 512, 512, wl, wr, bl[L], HID, 1, nullptr, L);
    }

    // ---- layer 4 (3-term, BN=128, writes checked output fp32) ----
    gather_bn_k<<<NN / 2, 256>>>(gam[2], bet[2], 2);
    gemm_k<4, 3><<<dim3(1, cdiv(NNP, 128)), 512, GEMM_SMEM>>>(1, 512, 512, OFF_WL4, OFF_WR4,
                                                              bl[3], OUTF, 0, out, -1);
}

// round 16
// speedup vs baseline: 6.2674x; 1.1226x over previous
#include <cuda_runtime.h>
#include <cuda_fp16.h>

#define NN   50000
#define NNP  50048
#define NE   400000
#define INF  50
#define HID  512
#define OUTF 121
#define EPSF 1e-5f
#define NSB  49

// ---------------- device scratch ----------------
__device__ float g_invdeg[NN];
__device__ __half g_hh[(size_t)NNP * HID];    // inter-layer h (fp16)
__device__ __half g_aggh[(size_t)NNP * HID];  // A operands: single fp16 plane
__device__ __half g_hbh[(size_t)NNP * HID];
__device__ __half g_xh[(size_t)NNP * 64];
__device__ __half g_a1h[(size_t)NNP * 64];

#define OFF_WL1 0
#define OFF_WR1 32768
#define OFF_WL2 65536
#define OFF_WR2 327680
#define OFF_WL3 589824
#define OFF_WR3 851968
#define OFF_WL4 1114112
#define OFF_WR4 1179648
#define WTOT    1245184
__device__ __half g_wh[WTOT];   // weights keep exact hi+lo split
__device__ __half g_wl[WTOT];

__device__ float g_colsum[3 * HID], g_colsq[3 * HID];
__device__ int g_src[NE], g_dst[NE], g_csrc[NE];
__device__ int g_rowptr[NN + 1], g_cnt[NN], g_cursor[NN], g_is64;
__device__ int g_blksum[64], g_blkoff[64];

// ---------------- helpers ----------------
__device__ __forceinline__ unsigned s2u(const void* p) {
    unsigned a;
    asm("{ .reg .u64 t; cvta.to.shared.u64 t, %1; cvt.u32.u64 %0, t; }" : "=r"(a) : "l"(p));
    return a;
}
__device__ __forceinline__ void cp16(unsigned dst, const void* src) {
    asm volatile("cp.async.cg.shared.global [%0], [%1], 16;" :: "r"(dst), "l"(src));
}
__device__ __forceinline__ void split1(float v, __half& hi, __half& lo) {
    hi = __float2half_rn(v);
    lo = __float2half_rn(v - __half2float(hi));
}
__device__ __forceinline__ float4 ldh4cg(const __half* p) {
    uint2 u = __ldcg((const uint2*)p);
    __half2 a = *(__half2*)&u.x;
    __half2 b = *(__half2*)&u.y;
    float2 fa = __half22float2(a);
    float2 fb = __half22float2(b);
    return make_float4(fa.x, fa.y, fb.x, fb.y);
}
__device__ __forceinline__ float4 ldh4(const __half* p) {
    uint2 u = *(const uint2*)p;
    __half2 a = *(__half2*)&u.x;
    __half2 b = *(__half2*)&u.y;
    float2 fa = __half22float2(a);
    float2 fb = __half22float2(b);
    return make_float4(fa.x, fa.y, fb.x, fb.y);
}
__device__ __forceinline__ void mma_f16(float* c,
                                        unsigned a0, unsigned a1, unsigned a2, unsigned a3,
                                        unsigned b0, unsigned b1) {
    asm volatile(
        "mma.sync.aligned.m16n8k16.row.col.f32.f16.f16.f32 "
        "{%0,%1,%2,%3},{%4,%5,%6,%7},{%8,%9},{%0,%1,%2,%3};"
        : "+f"(c[0]), "+f"(c[1]), "+f"(c[2]), "+f"(c[3])
        : "r"(a0), "r"(a1), "r"(a2), "r"(a3), "r"(b0), "r"(b1));
}

// ---------------- prep ----------------
__global__ void prep0_k() {
    int i = blockIdx.x * blockDim.x + threadIdx.x;
    if (i == 0) g_is64 = 1;
    if (i < NN) g_cnt[i] = 0;
    if (i < 3 * HID) { g_colsum[i] = 0.f; g_colsq[i] = 0.f; }
}
__global__ void detect_idx_k(const long long* __restrict__ ei) {
    int stride = gridDim.x * blockDim.x;
    int bad = 0;
    for (int i = blockIdx.x * blockDim.x + threadIdx.x; i < NE; i += stride) {
        long long v = ei[i];
        if (v < 0 || v >= NN) { bad = 1; break; }
    }
    if (__syncthreads_or(bad)) {
        if (threadIdx.x == 0) atomicExch(&g_is64, 0);
    }
}
__global__ void convert_count_k(const void* __restrict__ ei) {
    int e = blockIdx.x * blockDim.x + threadIdx.x;
    if (e >= NE) return;
    int s, d;
    if (g_is64) {
        const long long* p = (const long long*)ei;
        s = (int)p[e]; d = (int)p[e + NE];
    } else {
        const int* p = (const int*)ei;
        s = p[e]; d = p[e + NE];
    }
    s = min(max(s, 0), NN - 1);
    d = min(max(d, 0), NN - 1);
    g_src[e] = s;
    g_dst[e] = d;
    atomicAdd(&g_cnt[d], 1);
}
__global__ void scan1_k() {
    __shared__ int sh[1024];
    int tid = threadIdx.x;
    int i = blockIdx.x * 1024 + tid;
    int v = (i < NN) ? g_cnt[i] : 0;
    sh[tid] = v;
    __syncthreads();
#pragma unroll
    for (int off = 1; off < 1024; off <<= 1) {
        int x = (tid >= off) ? sh[tid - off] : 0;
        __syncthreads();
        sh[tid] += x;
        __syncthreads();
    }
    if (i < NN) g_rowptr[i] = sh[tid] - v;
    if (tid == 1023) g_blksum[blockIdx.x] = sh[1023];
}
__global__ void scan2_k() {
    __shared__ int sh[64];
    int t = threadIdx.x;
    int v = (t < NSB) ? g_blksum[t] : 0;
    sh[t] = v;
    __syncthreads();
#pragma unroll
    for (int off = 1; off < 64; off <<= 1) {
        int x = (t >= off) ? sh[t - off] : 0;
        __syncthreads();
        sh[t] += x;
        __syncthreads();
    }
    if (t < 64) g_blkoff[t] = sh[t] - v;
}
__global__ void scan3_k() {
    int i = blockIdx.x * blockDim.x + threadIdx.x;
    if (i >= NN) return;
    g_rowptr[i] += g_blkoff[i >> 10];
    g_cursor[i] = 0;
    g_invdeg[i] = 1.0f / (float)max(g_cnt[i], 1);
    if (i == 0) g_rowptr[NN] = g_blkoff[NSB - 1] + g_blksum[NSB - 1];
}
__global__ void fill_k() {
    int e = blockIdx.x * blockDim.x + threadIdx.x;
    if (e >= NE) return;
    int d = g_dst[e];
    int slot = g_rowptr[d] + atomicAdd(&g_cursor[d], 1);
    g_csrc[slot] = g_src[e];
}

// ---------------- unified plane split (weights hi+lo; x hi only) ----------------
#define XTOT (NN * 64)
__global__ void split_all_k(const float* __restrict__ Wl1, const float* __restrict__ Wr1,
                            const float* __restrict__ Wl2, const float* __restrict__ Wr2,
                            const float* __restrict__ Wl3, const float* __restrict__ Wr3,
                            const float* __restrict__ Wl4, const float* __restrict__ Wr4,
                            const float* __restrict__ x) {
    int idx = blockIdx.x * blockDim.x + threadIdx.x;
    if (idx >= WTOT + XTOT) return;
    if (idx >= WTOT) {
        int i = idx - WTOT;
        int n = i >> 6, c = i & 63;
        float v = (c < INF) ? x[(size_t)n * INF + c] : 0.f;
        g_xh[i] = __float2half_rn(v);
        return;
    }
    const float* W;
    int off, Kpad, K, N;
    if (idx < OFF_WL2) {
        Kpad = 64; K = INF; N = HID;
        if (idx < OFF_WR1) { W = Wl1; off = OFF_WL1; }
        else               { W = Wr1; off = OFF_WR1; }
    } else if (idx < OFF_WL4) {
        Kpad = 512; K = HID; N = HID;
        if (idx < OFF_WR2)      { W = Wl2; off = OFF_WL2; }
        else if (idx < OFF_WL3) { W = Wr2; off = OFF_WR2; }
        else if (idx < OFF_WR3) { W = Wl3; off = OFF_WL3; }
        else                    { W = Wr3; off = OFF_WR3; }
    } else {
        Kpad = 512; K = HID; N = OUTF;
        if (idx < OFF_WR4) { W = Wl4; off = OFF_WL4; }
        else               { W = Wr4; off = OFF_WR4; }
    }
    int local = idx - off;
    int n = local / Kpad, k = local - n * Kpad;
    float v = (n < N && k < K) ? W[(size_t)k * N + n] : 0.f;
    __half hi, lo;
    split1(v, hi, lo);
    g_wh[idx] = hi;
    g_wl[idx] = lo;
}

// ---------------- layer-1 gather ----------------
__global__ void gather50_k(const float* __restrict__ x) {
    int node = blockIdx.x;
    int t = threadIdx.x;
    float acc = 0.f;
    if (t < INF) {
        int beg = g_rowptr[node], end = g_rowptr[node + 1];
        for (int e = beg; e < end; ++e) acc += x[(size_t)g_csrc[e] * INF + t];
        acc *= g_invdeg[node];
    }
    g_a1h[(size_t)node * 64 + t] = __float2half_rn(acc);
}

// ---------------- fused gather + inline-BN apply (single-plane outputs) ----------------
__global__ void __launch_bounds__(256, 8)
gather_bn_k(const float* __restrict__ gamma, const float* __restrict__ beta, int si) {
    int half_ = threadIdx.x >> 7;
    int tid = threadIdx.x & 127;
    int node = blockIdx.x * 2 + half_;
    if (node >= NN) return;
    size_t coff = (size_t)tid * 4;

    float4 cs = *(const float4*)(g_colsum + si * HID + coff);
    float4 cq = *(const float4*)(g_colsq + si * HID + coff);
    float4 ga = *(const float4*)(gamma + coff);
    float4 be = *(const float4*)(beta + coff);
    const float invn = 1.0f / NN;
    float4 sc, sh;
    {
        float m, r;
        m = cs.x * invn; r = rsqrtf(cq.x * invn - m * m + EPSF); sc.x = r * ga.x; sh.x = be.x - m * sc.x;
        m = cs.y * invn; r = rsqrtf(cq.y * invn - m * m + EPSF); sc.y = r * ga.y; sh.y = be.y - m * sc.y;
        m = cs.z * invn; r = rsqrtf(cq.z * invn - m * m + EPSF); sc.z = r * ga.z; sh.z = be.z - m * sc.z;
        m = cs.w * invn; r = rsqrtf(cq.w * invn - m * m + EPSF); sc.w = r * ga.w; sh.w = be.w - m * sc.w;
    }

    // own row -> hb plane
    {
        float4 v = ldh4(g_hh + (size_t)node * HID + coff);
        __half2 p0 = __floats2half2_rn(fmaxf(fmaf(v.x, sc.x, sh.x), 0.f),
                                       fmaxf(fmaf(v.y, sc.y, sh.y), 0.f));
        __half2 p1 = __floats2half2_rn(fmaxf(fmaf(v.z, sc.z, sh.z), 0.f),
                                       fmaxf(fmaf(v.w, sc.w, sh.w), 0.f));
        size_t o = (size_t)node * HID + coff;
        *(uint2*)(g_hbh + o) = make_uint2(*(unsigned*)&p0, *(unsigned*)&p1);
    }

    int beg = g_rowptr[node], end = g_rowptr[node + 1];
    float a0 = 0.f, a1 = 0.f, a2 = 0.f, a3 = 0.f;
    int e = beg;
#define GB_ACC(v) \
    a0 += fmaxf(fmaf((v).x, sc.x, sh.x), 0.f); \
    a1 += fmaxf(fmaf((v).y, sc.y, sh.y), 0.f); \
    a2 += fmaxf(fmaf((v).z, sc.z, sh.z), 0.f); \
    a3 += fmaxf(fmaf((v).w, sc.w, sh.w), 0.f)
    for (; e + 7 < end; e += 8) {
        float4 v0 = ldh4cg(g_hh + (size_t)g_csrc[e]     * HID + coff);
        float4 v1 = ldh4cg(g_hh + (size_t)g_csrc[e + 1] * HID + coff);
        float4 v2 = ldh4cg(g_hh + (size_t)g_csrc[e + 2] * HID + coff);
        float4 v3 = ldh4cg(g_hh + (size_t)g_csrc[e + 3] * HID + coff);
        float4 v4 = ldh4cg(g_hh + (size_t)g_csrc[e + 4] * HID + coff);
        float4 v5 = ldh4cg(g_hh + (size_t)g_csrc[e + 5] * HID + coff);
        float4 v6 = ldh4cg(g_hh + (size_t)g_csrc[e + 6] * HID + coff);
        float4 v7 = ldh4cg(g_hh + (size_t)g_csrc[e + 7] * HID + coff);
        GB_ACC(v0); GB_ACC(v1); GB_ACC(v2); GB_ACC(v3);
        GB_ACC(v4); GB_ACC(v5); GB_ACC(v6); GB_ACC(v7);
    }
    for (; e + 3 < end; e += 4) {
        float4 v0 = ldh4cg(g_hh + (size_t)g_csrc[e]     * HID + coff);
        float4 v1 = ldh4cg(g_hh + (size_t)g_csrc[e + 1] * HID + coff);
        float4 v2 = ldh4cg(g_hh + (size_t)g_csrc[e + 2] * HID + coff);
        float4 v3 = ldh4cg(g_hh + (size_t)g_csrc[e + 3] * HID + coff);
        GB_ACC(v0); GB_ACC(v1); GB_ACC(v2); GB_ACC(v3);
    }
    for (; e < end; ++e) {
        float4 v0 = ldh4cg(g_hh + (size_t)g_csrc[e] * HID + coff);
        GB_ACC(v0);
    }
#undef GB_ACC
    float inv = g_invdeg[node];
    __half2 p0 = __floats2half2_rn(a0 * inv, a1 * inv);
    __half2 p1 = __floats2half2_rn(a2 * inv, a3 * inv);
    size_t o = (size_t)node * HID + coff;
    *(uint2*)(g_aggh + o) = make_uint2(*(unsigned*)&p0, *(unsigned*)&p1);
}

// ---------------- dual GEMM: A fp16, B hi+lo split; BK=64, 2-stage ----------------
#define AW2 36
#define ASZ2 (128 * AW2)

template <int NI>
__global__ void __launch_bounds__(512, 1)
gemm_k(int aSel, int K1, int K2, int woff1, int woff2,
       const float* __restrict__ bias, int N, int cSel, float* __restrict__ cExt,
       int si) {
    constexpr int BN = NI * 32;
    constexpr int BSZ = BN * AW2;
    constexpr int STGU = ASZ2 + 2 * BSZ;

    extern __shared__ unsigned sm[];
    unsigned sbase = s2u(sm);
    __shared__ float s_sum[BN], s_sq[BN];

    const __half *A1, *A2;
    if (aSel == 0) { A1 = g_a1h; A2 = g_xh; }
    else           { A1 = g_aggh; A2 = g_hbh; }
    const __half* B1h = g_wh + woff1;
    const __half* B1l = g_wl + woff1;
    const __half* B2h = g_wh + woff2;
    const __half* B2l = g_wl + woff2;
    bool doStat = (si >= 0);

    int tid = threadIdx.x;
    int warp = tid >> 5, lane = tid & 31;
    int wm = warp & 3, wn = warp >> 2;
    int g = lane >> 2, t = lane & 3;
    int row0 = blockIdx.y * 128;
    int col0 = blockIdx.x * BN;

    int S1 = K1 >> 6, S2 = K2 >> 6, S = S1 + S2;

    float acc[2][NI][4];
#pragma unroll
    for (int mi = 0; mi < 2; mi++)
#pragma unroll
        for (int ni = 0; ni < NI; ni++)
#pragma unroll
            for (int r = 0; r < 4; r++) acc[mi][ni][r] = 0.f;

    if (doStat && tid < BN) { s_sum[tid] = 0.f; s_sq[tid] = 0.f; }

    auto prefetch = [&](int s, int buf) {
        const __half *Aa, *Bh, *Bl;
        int ka, k0;
        if (s < S1) { Aa = A1; Bh = B1h; Bl = B1l; ka = K1; k0 = s * 64; }
        else        { Aa = A2; Bh = B2h; Bl = B2l; ka = K2; k0 = (s - S1) * 64; }
        unsigned base = sbase + buf * (STGU * 4);
        // A: 128 rows x 8 chunks = 1024 cp16
#pragma unroll
        for (int l = 0; l < 2; l++) {
            int idx = tid + l * 512;
            int row = idx >> 3, ch = idx & 7;
            cp16(base + row * (AW2 * 4) + ch * 16,
                 Aa + (size_t)(row0 + row) * ka + k0 + ch * 8);
        }
        // B hi+lo: BN rows x 8 chunks per plane
#pragma unroll
        for (int l = 0; l < BN / 64; l++) {
            int idx = tid + l * 512;
            int row = idx >> 3, ch = idx & 7;
            unsigned d = base + ASZ2 * 4 + row * (AW2 * 4) + ch * 16;
            size_t boff = (size_t)(col0 + row) * ka + k0 + ch * 8;
            cp16(d, Bh + boff);
            cp16(d + BSZ * 4, Bl + boff);
        }
        asm volatile("cp.async.commit_group;" ::: "memory");
    };

    auto compute = [&](int buf) {
        const unsigned* Ah = sm + buf * STGU;
        const unsigned* Bh = Ah + ASZ2;
        const unsigned* Bl = Bh + BSZ;
#pragma unroll
        for (int ks = 0; ks < 4; ks++) {
            int kb = ks * 8;
            unsigned ah[2][4];
#pragma unroll
            for (int mi = 0; mi < 2; mi++) {
                int rb = wm * 32 + mi * 16;
                int i0 = (rb + g) * AW2 + kb + t;
                int i1 = (rb + g + 8) * AW2 + kb + t;
                ah[mi][0] = Ah[i0];
                ah[mi][1] = Ah[i1];
                ah[mi][2] = Ah[i0 + 4];
                ah[mi][3] = Ah[i1 + 4];
            }
#pragma unroll
            for (int ni = 0; ni < NI; ni++) {
                int cb = (wn * (NI * 8) + ni * 8 + g) * AW2 + kb + t;
                unsigned b0 = Bh[cb], b1 = Bh[cb + 4];
                unsigned c0 = Bl[cb], c1 = Bl[cb + 4];
#pragma unroll
                for (int mi = 0; mi < 2; mi++) {
                    float* c = acc[mi][ni];
                    mma_f16(c, ah[mi][0], ah[mi][1], ah[mi][2], ah[mi][3], b0, b1);
                    mma_f16(c, ah[mi][0], ah[mi][1], ah[mi][2], ah[mi][3], c0, c1);
                }
            }
        }
    };

    // 2-stage pipeline: copy of s+1 overlaps compute of s
    prefetch(0, 0);
#pragma unroll 1
    for (int s = 0; s < S; s++) {
        asm volatile("cp.async.wait_group 0;" ::: "memory");
        __syncthreads();
        if (s + 1 < S) prefetch(s + 1, (s + 1) & 1);
        compute(s & 1);
    }

    if (doStat) __syncthreads();

    float colS[NI][2], colQ[NI][2];
#pragma unroll
    for (int ni = 0; ni < NI; ni++) {
        colS[ni][0] = colS[ni][1] = 0.f;
        colQ[ni][0] = colQ[ni][1] = 0.f;
    }
#pragma unroll
    for (int mi = 0; mi < 2; mi++) {
        int ra = row0 + wm * 32 + mi * 16 + g;
        int rb = ra + 8;
        bool va = ra < NN, vb = rb < NN;
#pragma unroll
        for (int ni = 0; ni < NI; ni++) {
            int col = col0 + wn * (NI * 8) + ni * 8 + t * 2;
            float* c = acc[mi][ni];
            if (col + 1 < N) {
                float b0 = __ldg(&bias[col]);
                float b1 = __ldg(&bias[col + 1]);
                float v0 = c[0] + b0, v1 = c[1] + b1;
                float v2 = c[2] + b0, v3 = c[3] + b1;
                if (cSel == 1) {
                    if (va) *(__half2*)(g_hh + (size_t)ra * N + col) = __floats2half2_rn(v0, v1);
                    if (vb) *(__half2*)(g_hh + (size_t)rb * N + col) = __floats2half2_rn(v2, v3);
                } else {
                    if (va) { cExt[(size_t)ra * N + col] = v0; cExt[(size_t)ra * N + col + 1] = v1; }
                    if (vb) { cExt[(size_t)rb * N + col] = v2; cExt[(size_t)rb * N + col + 1] = v3; }
                }
                if (va) { colS[ni][0] += v0; colQ[ni][0] += v0 * v0;
                          colS[ni][1] += v1; colQ[ni][1] += v1 * v1; }
                if (vb) { colS[ni][0] += v2; colQ[ni][0] += v2 * v2;
                          colS[ni][1] += v3; colQ[ni][1] += v3 * v3; }
            } else if (col < N) {
                float b0 = __ldg(&bias[col]);
                float v0 = c[0] + b0, v2 = c[2] + b0;
                if (cSel == 1) {
                    if (va) g_hh[(size_t)ra * N + col] = __float2half_rn(v0);
                    if (vb) g_hh[(size_t)rb * N + col] = __float2half_rn(v2);
                } else {
                    if (va) cExt[(size_t)ra * N + col] = v0;
                    if (vb) cExt[(size_t)rb * N + col] = v2;
                }
                if (va) { colS[ni][0] += v0; colQ[ni][0] += v0 * v0; }
                if (vb) { colS[ni][0] += v2; colQ[ni][0] += v2 * v2; }
            }
        }
    }

    if (doStat) {
#pragma unroll
        for (int ni = 0; ni < NI; ni++)
#pragma unroll
            for (int p = 0; p < 2; p++) {
#pragma unroll
                for (int off = 4; off < 32; off <<= 1) {
                    colS[ni][p] += __shfl_xor_sync(0xFFFFFFFF, colS[ni][p], off);
                    colQ[ni][p] += __shfl_xor_sync(0xFFFFFFFF, colQ[ni][p], off);
                }
            }
        if (g == 0) {
#pragma unroll
            for (int ni = 0; ni < NI; ni++) {
                int ci = wn * (NI * 8) + ni * 8 + t * 2;
                atomicAdd(&s_sum[ci], colS[ni][0]);
                atomicAdd(&s_sq[ci], colQ[ni][0]);
                atomicAdd(&s_sum[ci + 1], colS[ni][1]);
                atomicAdd(&s_sq[ci + 1], colQ[ni][1]);
            }
        }
        __syncthreads();
        if (tid < BN) {
            atomicAdd(&g_colsum[si * HID + col0 + tid], s_sum[tid]);
            atomicAdd(&g_colsq[si * HID + col0 + tid], s_sq[tid]);
        }
    }
}

#define GEMM_SMEM8 ((ASZ2 + 2 * 256 * AW2) * 4 * 2)   // 184320 B
#define GEMM_SMEM4 ((ASZ2 + 2 * 128 * AW2) * 4 * 2)   // 110592 B

// ---------------- host ----------------
static inline int cdiv(long long a, int b) { return (int)((a + b - 1) / b); }

extern "C" void kernel_launch(void* const* d_in, const int* in_sizes, int n_in,
                              void* d_out, int out_size) {
    const float* x = (const float*)d_in[0];
    const void* ei = d_in[1];

    const float* Wl[4] = {(const float*)d_in[2], (const float*)d_in[5],
                          (const float*)d_in[8], (const float*)d_in[11]};
    const float* bl[4] = {(const float*)d_in[3], (const float*)d_in[6],
                          (const float*)d_in[9], (const float*)d_in[12]};
    const float* Wr[4] = {(const float*)d_in[4], (const float*)d_in[7],
                          (const float*)d_in[10], (const float*)d_in[13]};
    const float* gam[3] = {(const float*)d_in[14], (const float*)d_in[16], (const float*)d_in[18]};
    const float* bet[3] = {(const float*)d_in[15], (const float*)d_in[17], (const float*)d_in[19]};
    float* out = (float*)d_out;

    cudaFuncSetAttribute(gemm_k<8>, cudaFuncAttributeMaxDynamicSharedMemorySize, GEMM_SMEM8);
    cudaFuncSetAttribute(gemm_k<4>, cudaFuncAttributeMaxDynamicSharedMemorySize, GEMM_SMEM4);

    // edge indices + CSR
    prep0_k<<<cdiv(NN, 256), 256>>>();
    detect_idx_k<<<128, 1024>>>((const long long*)ei);
    convert_count_k<<<cdiv(NE, 256), 256>>>(ei);
    scan1_k<<<NSB, 1024>>>();
    scan2_k<<<1, 64>>>();
    scan3_k<<<cdiv(NN, 256), 256>>>();
    fill_k<<<cdiv(NE, 256), 256>>>();
    split_all_k<<<cdiv(WTOT + XTOT, 256), 256>>>(Wl[0], Wr[0], Wl[1], Wr[1],
                                                 Wl[2], Wr[2], Wl[3], Wr[3], x);

    dim3 gwide(2, cdiv(NNP, 128));

    // ---- layer 1 ----
    gather50_k<<<NN, 64>>>(x);
    gemm_k<8><<<gwide, 512, GEMM_SMEM8>>>(0, 64, 64, OFF_WL1, OFF_WR1, bl[0], HID, 1, nullptr, 0);

    // ---- layers 2 & 3 ----
    for (int L = 1; L <= 2; ++L) {
        int wl = (L == 1) ? OFF_WL2 : OFF_WL3;
        int wr = (L == 1) ? OFF_WR2 : OFF_WR3;
        gather_bn_k<<<NN / 2, 256>>>(gam[L - 1], bet[L - 1], L - 1);
        gemm_k<8><<<gwide, 512, GEMM_SMEM8>>>(1, 512, 512, wl, wr, bl[L], HID, 1, nullptr, L);
    }

    // ---- layer 4 -> d_out (fp32) ----
    gather_bn_k<<<NN / 2, 256>>>(gam[2], bet[2], 2);
    gemm_k<4><<<dim3(1, cdiv(NNP, 128)), 512, GEMM_SMEM4>>>(1, 512, 512, OFF_WL4, OFF_WR4,
                                                            bl[3], OUTF, 0, out, -1);
}